// round 1
// baseline (speedup 1.0000x reference)
#include <cuda_runtime.h>
#include <math.h>

#define BATCH 16
#define CH    768
#define NPIX  4096
#define NH    12
#define HD    64
#define ATT_SCALE 0.125f   // HD^-0.5

// ---------------- scratch (device globals; no runtime allocation) ----------------
__device__ float g_G[BATCH * CH * CH];     // Gram matrices X X^T
__device__ float g_T[BATCH * CH * CH];     // T = Wq * G
__device__ float g_P[BATCH * CH * CH];     // P = A_bd * Wv
__device__ float g_M[BATCH * CH * CH];     // M = Wo * P
__device__ float g_A[BATCH * NH * HD * HD];// softmax attention blocks
__device__ float g_s[BATCH * CH];          // row sums of X
__device__ float g_qs[BATCH * CH];         // Wq * s
__device__ float g_ks[BATCH * CH];         // Wk * s
__device__ float g_abv[BATCH * CH];        // A_bd * bv
__device__ float g_c[BATCH * CH];          // Wo * abv + bo

// ---------------- row sums s[b,c] = sum_n X[b,c,n] ----------------
__global__ void rowsum_kernel(const float* __restrict__ x) {
    int c = blockIdx.x, b = blockIdx.y;
    const float* row = x + ((long)b * CH + c) * NPIX;
    float s = 0.f;
    for (int n = threadIdx.x * 4; n < NPIX; n += 256 * 4) {
        float4 v = *(const float4*)(row + n);
        s += v.x + v.y + v.z + v.w;
    }
    __shared__ float red[256];
    red[threadIdx.x] = s;
    __syncthreads();
    for (int off = 128; off > 0; off >>= 1) {
        if (threadIdx.x < off) red[threadIdx.x] += red[threadIdx.x + off];
        __syncthreads();
    }
    if (threadIdx.x == 0) g_s[b * CH + c] = red[0];
}

// ---------------- generic 128x128x8 SGEMM, 256 threads, 8x8 per thread ----------------
// C[b] = A[b] * op(B[b]) (+ bias per row).  A is [M,K] row-major.
// TRANSB: B is [N,K] row-major (contract over columns of both) else [K,N].
template<bool TRANSB, bool HASBIAS>
__global__ void __launch_bounds__(256, 2) gemm128_kernel(
    const float* __restrict__ Ag, const float* __restrict__ Bg,
    float* __restrict__ Cg, const float* __restrict__ biasg,
    int M_, int N_, int K_,
    long sA, long sB, long sC, long sBias)
{
    __shared__ float As[8][128];
    __shared__ float Bs[8][128];
    int b = blockIdx.z;
    const float* A = Ag + (long)b * sA;
    const float* B = Bg + (long)b * sB;
    float*       C = Cg + (long)b * sC;
    int m0 = blockIdx.y * 128, n0 = blockIdx.x * 128;
    int tid = threadIdx.x;
    int tx = tid & 15, ty = tid >> 4;

    int arow = tid >> 1;
    int acol = (tid & 1) * 4;
    const float* Aptr = A + (long)(m0 + arow) * K_ + acol;

    const float* Bptr;
    int brow, bcol;
    if (TRANSB) {
        brow = tid >> 1; bcol = (tid & 1) * 4;
        Bptr = B + (long)(n0 + brow) * K_ + bcol;
    } else {
        brow = tid >> 5; bcol = (tid & 31) * 4;
        Bptr = B + (long)brow * N_ + n0 + bcol;
    }

    float acc[8][8];
    #pragma unroll
    for (int i = 0; i < 8; i++)
        #pragma unroll
        for (int j = 0; j < 8; j++) acc[i][j] = 0.f;

    for (int k0 = 0; k0 < K_; k0 += 8) {
        float4 av = *(const float4*)(Aptr + k0);
        As[acol + 0][arow] = av.x; As[acol + 1][arow] = av.y;
        As[acol + 2][arow] = av.z; As[acol + 3][arow] = av.w;
        if (TRANSB) {
            float4 bv = *(const float4*)(Bptr + k0);
            Bs[bcol + 0][brow] = bv.x; Bs[bcol + 1][brow] = bv.y;
            Bs[bcol + 2][brow] = bv.z; Bs[bcol + 3][brow] = bv.w;
        } else {
            float4 bv = *(const float4*)(Bptr + (long)k0 * N_);
            *(float4*)&Bs[brow][bcol] = bv;
        }
        __syncthreads();
        #pragma unroll
        for (int kk = 0; kk < 8; kk++) {
            float ra[8], rb[8];
            *(float4*)&ra[0] = *(const float4*)&As[kk][ty * 8];
            *(float4*)&ra[4] = *(const float4*)&As[kk][ty * 8 + 4];
            *(float4*)&rb[0] = *(const float4*)&Bs[kk][tx * 8];
            *(float4*)&rb[4] = *(const float4*)&Bs[kk][tx * 8 + 4];
            #pragma unroll
            for (int i = 0; i < 8; i++)
                #pragma unroll
                for (int j = 0; j < 8; j++)
                    acc[i][j] += ra[i] * rb[j];
        }
        __syncthreads();
    }

    #pragma unroll
    for (int i = 0; i < 8; i++) {
        int gm = m0 + ty * 8 + i;
        float bias = 0.f;
        if (HASBIAS) bias = biasg[b * sBias + gm];
        float* crow = C + (long)gm * N_ + n0 + tx * 8;
        float4 v0 = make_float4(acc[i][0] + bias, acc[i][1] + bias,
                                acc[i][2] + bias, acc[i][3] + bias);
        float4 v1 = make_float4(acc[i][4] + bias, acc[i][5] + bias,
                                acc[i][6] + bias, acc[i][7] + bias);
        *(float4*)crow = v0;
        *(float4*)(crow + 4) = v1;
    }
}

// ---------------- qs = Wq*s, ks = Wk*s (per batch) ----------------
__global__ void qsks_kernel(const float* __restrict__ wq, const float* __restrict__ wk) {
    int b = blockIdx.x;
    __shared__ float sv[CH];
    for (int i = threadIdx.x; i < CH; i += 256) sv[i] = g_s[b * CH + i];
    __syncthreads();
    for (int o = threadIdx.x; o < CH; o += 256) {
        const float* wr = wq + (long)o * CH;
        const float* kr = wk + (long)o * CH;
        float aq = 0.f, ak = 0.f;
        for (int c = 0; c < CH; c++) { aq += wr[c] * sv[c]; ak += kr[c] * sv[c]; }
        g_qs[b * CH + o] = aq;
        g_ks[b * CH + o] = ak;
    }
}

// ---------------- energy blocks + softmax + abv;  E_h = T_h * Wk_h^T + bias terms ----------------
__global__ void __launch_bounds__(256) attn_kernel(
    const float* __restrict__ wk, const float* __restrict__ bq,
    const float* __restrict__ bk, const float* __restrict__ bv)
{
    int h = blockIdx.x, b = blockIdx.y;
    __shared__ float Ts[16][64];
    __shared__ float Ks[16][64];
    __shared__ float Es[64][65];
    __shared__ float qv[64], kvv[64], bqv[64], bkv[64], bvv[64];
    int tid = threadIdx.x;
    if (tid < 64) {
        qv[tid]  = g_qs[b * CH + h * HD + tid];
        kvv[tid] = g_ks[b * CH + h * HD + tid];
        bqv[tid] = bq[h * HD + tid];
        bkv[tid] = bk[h * HD + tid];
        bvv[tid] = bv[h * HD + tid];
    }
    const float* Tb = g_T + ((long)b * CH + h * HD) * CH;
    const float* Kb = wk + (long)(h * HD) * CH;
    int lrow = tid >> 2;
    int lcol = (tid & 3) * 4;
    int tx = tid & 15, ty = tid >> 4;
    float acc[4][4];
    #pragma unroll
    for (int i = 0; i < 4; i++)
        #pragma unroll
        for (int j = 0; j < 4; j++) acc[i][j] = 0.f;

    for (int a0 = 0; a0 < CH; a0 += 16) {
        float4 tv = *(const float4*)(Tb + (long)lrow * CH + a0 + lcol);
        Ts[lcol + 0][lrow] = tv.x; Ts[lcol + 1][lrow] = tv.y;
        Ts[lcol + 2][lrow] = tv.z; Ts[lcol + 3][lrow] = tv.w;
        float4 kv4 = *(const float4*)(Kb + (long)lrow * CH + a0 + lcol);
        Ks[lcol + 0][lrow] = kv4.x; Ks[lcol + 1][lrow] = kv4.y;
        Ks[lcol + 2][lrow] = kv4.z; Ks[lcol + 3][lrow] = kv4.w;
        __syncthreads();
        #pragma unroll
        for (int kk = 0; kk < 16; kk++) {
            float ra[4], rb[4];
            *(float4*)&ra[0] = *(const float4*)&Ts[kk][ty * 4];
            *(float4*)&rb[0] = *(const float4*)&Ks[kk][tx * 4];
            #pragma unroll
            for (int i = 0; i < 4; i++)
                #pragma unroll
                for (int j = 0; j < 4; j++)
                    acc[i][j] += ra[i] * rb[j];
        }
        __syncthreads();
    }
    #pragma unroll
    for (int i = 0; i < 4; i++) {
        int gi = ty * 4 + i;
        #pragma unroll
        for (int j = 0; j < 4; j++) {
            int gj = tx * 4 + j;
            float e = acc[i][j] + qv[gi] * bkv[gj] + bqv[gi] * kvv[gj]
                      + 4096.f * bqv[gi] * bkv[gj];
            Es[gi][gj] = e * ATT_SCALE;
        }
    }
    __syncthreads();
    if (tid < 64) {
        int i = tid;
        float m = -1e30f;
        for (int j = 0; j < 64; j++) m = fmaxf(m, Es[i][j]);
        float sum = 0.f;
        for (int j = 0; j < 64; j++) {
            float ex = expf(Es[i][j] - m);
            Es[i][j] = ex;
            sum += ex;
        }
        float inv = 1.f / sum;
        float ab = 0.f;
        float* Arow = g_A + (((long)b * NH + h) * HD + i) * HD;
        for (int j = 0; j < 64; j++) {
            float a = Es[i][j] * inv;
            Arow[j] = a;
            ab += a * bvv[j];
        }
        g_abv[b * CH + h * HD + i] = ab;
    }
}

// ---------------- P = A_bd * Wv  (per head: [64x64] @ [64x768]) ----------------
__global__ void __launch_bounds__(256) pk_kernel(const float* __restrict__ wv) {
    int h = blockIdx.x, b = blockIdx.y;
    __shared__ float Ash[64][64];   // Ash[j][i] = A[i][j]
    __shared__ float Bv[64][64];
    int tid = threadIdx.x;
    const float* Ab = g_A + ((long)b * NH + h) * HD * HD;
    for (int r = tid; r < 64 * 16; r += 256) {
        int i = r >> 4, q = (r & 15) * 4;
        float4 v = *(const float4*)(Ab + i * 64 + q);
        Ash[q + 0][i] = v.x; Ash[q + 1][i] = v.y;
        Ash[q + 2][i] = v.z; Ash[q + 3][i] = v.w;
    }
    int tx = tid & 15, ty = tid >> 4;
    for (int cc = 0; cc < CH; cc += 64) {
        __syncthreads();
        for (int r = tid; r < 64 * 16; r += 256) {
            int j = r >> 4, q = (r & 15) * 4;
            *(float4*)&Bv[j][q] = *(const float4*)(wv + (long)(h * HD + j) * CH + cc + q);
        }
        __syncthreads();
        float acc[4][4];
        #pragma unroll
        for (int i = 0; i < 4; i++)
            #pragma unroll
            for (int j = 0; j < 4; j++) acc[i][j] = 0.f;
        #pragma unroll 8
        for (int j = 0; j < 64; j++) {
            float ra[4], rb[4];
            *(float4*)&ra[0] = *(const float4*)&Ash[j][ty * 4];
            *(float4*)&rb[0] = *(const float4*)&Bv[j][tx * 4];
            #pragma unroll
            for (int i = 0; i < 4; i++)
                #pragma unroll
                for (int u = 0; u < 4; u++)
                    acc[i][u] += ra[i] * rb[u];
        }
        #pragma unroll
        for (int i = 0; i < 4; i++) {
            float* Pp = g_P + ((long)b * CH + h * HD + ty * 4 + i) * CH + cc + tx * 4;
            *(float4*)Pp = make_float4(acc[i][0], acc[i][1], acc[i][2], acc[i][3]);
        }
    }
}

// ---------------- c[b] = Wo * abv[b] + bo ----------------
__global__ void cvec_kernel(const float* __restrict__ wo, const float* __restrict__ bo) {
    int b = blockIdx.x;
    __shared__ float sv[CH];
    for (int i = threadIdx.x; i < CH; i += 256) sv[i] = g_abv[b * CH + i];
    __syncthreads();
    for (int o = threadIdx.x; o < CH; o += 256) {
        const float* wr = wo + (long)o * CH;
        float sum = bo[o];
        for (int c = 0; c < CH; c++) sum += wr[c] * sv[c];
        g_c[b * CH + o] = sum;
    }
}

// ---------------- launch ----------------
extern "C" void kernel_launch(void* const* d_in, const int* in_sizes, int n_in,
                              void* d_out, int out_size) {
    const float* x  = (const float*)d_in[0];
    const float* wq = (const float*)d_in[1];
    const float* bq = (const float*)d_in[2];
    const float* wk = (const float*)d_in[3];
    const float* bk = (const float*)d_in[4];
    const float* wv = (const float*)d_in[5];
    const float* bv = (const float*)d_in[6];
    const float* wo = (const float*)d_in[7];
    const float* bo = (const float*)d_in[8];
    float* y = (float*)d_out;

    float *pG, *pT, *pP, *pM, *pc;
    cudaGetSymbolAddress((void**)&pG, g_G);
    cudaGetSymbolAddress((void**)&pT, g_T);
    cudaGetSymbolAddress((void**)&pP, g_P);
    cudaGetSymbolAddress((void**)&pM, g_M);
    cudaGetSymbolAddress((void**)&pc, g_c);

    // 1. row sums
    rowsum_kernel<<<dim3(CH, BATCH), 256>>>(x);

    // 2. Gram: G[b] = X[b] X[b]^T   (NT, K = 4096)
    gemm128_kernel<true, false><<<dim3(6, 6, BATCH), 256>>>(
        x, x, pG, nullptr, CH, CH, NPIX,
        (long)CH * NPIX, (long)CH * NPIX, (long)CH * CH, 0);

    // 3. qs/ks
    qsks_kernel<<<BATCH, 256>>>(wq, wk);

    // 4. T[b] = Wq * G[b]   (NN, K = 768)
    gemm128_kernel<false, false><<<dim3(6, 6, BATCH), 256>>>(
        wq, pG, pT, nullptr, CH, CH, CH,
        0, (long)CH * CH, (long)CH * CH, 0);

    // 5. energy blocks + softmax + abv
    attn_kernel<<<dim3(NH, BATCH), 256>>>(wk, bq, bk, bv);

    // 6. P[b] = A_bd * Wv
    pk_kernel<<<dim3(NH, BATCH), 256>>>(wv);

    // 7. c[b] = Wo * abv + bo
    cvec_kernel<<<BATCH, 256>>>(wo, bo);

    // 8. M[b] = Wo * P[b]   (NN, K = 768)
    gemm128_kernel<false, false><<<dim3(6, 6, BATCH), 256>>>(
        wo, pP, pM, nullptr, CH, CH, CH,
        0, (long)CH * CH, (long)CH * CH, 0);

    // 9. y[b] = M[b] * X[b] + c[b]   (NN, K = 768, row bias)
    gemm128_kernel<false, true><<<dim3(32, 6, BATCH), 256>>>(
        pM, x, y, pc, CH, NPIX, CH,
        (long)CH * CH, (long)CH * NPIX, (long)CH * NPIX, CH);
}

// round 5
// speedup vs baseline: 1.9622x; 1.9622x over previous
#include <cuda_runtime.h>
#include <cuda_bf16.h>
#include <math.h>
#include <stdint.h>

#define BATCH 16
#define CH    768
#define NPIX  4096
#define NH    12
#define HD    64
#define ATT_SCALE 0.125f   // HD^-0.5

typedef __nv_bfloat16 bf16;

// ---------------- scratch (device globals; no runtime allocation) ----------------
__device__ float g_T[BATCH * CH * CH];      // T = Wq * G (fp32, feeds attn)
__device__ float g_A[BATCH * NH * HD * HD]; // softmax attention blocks
__device__ float g_s[BATCH * CH];           // row sums of X
__device__ float g_qs[BATCH * CH];          // Wq * s
__device__ float g_ks[BATCH * CH];          // Wk * s
__device__ float g_abv[BATCH * CH];         // A_bd * bv
__device__ float g_c[BATCH * CH];           // Wo * abv + bo

// bf16 hi/lo splits
__device__ __align__(16) bf16 g_Xh [BATCH * CH * NPIX]; // [b][c][n]
__device__ __align__(16) bf16 g_Xl [BATCH * CH * NPIX];
__device__ __align__(16) bf16 g_Xth[BATCH * NPIX * CH]; // [b][n][c]
__device__ __align__(16) bf16 g_Xtl[BATCH * NPIX * CH];
__device__ __align__(16) bf16 g_Gh [BATCH * CH * CH];   // Gram (symmetric)
__device__ __align__(16) bf16 g_Gl [BATCH * CH * CH];
__device__ __align__(16) bf16 g_Pth[BATCH * CH * CH];   // (A_bd * Wv)^T : [c][r]
__device__ __align__(16) bf16 g_Ptl[BATCH * CH * CH];
__device__ __align__(16) bf16 g_Mh [BATCH * CH * CH];   // M = Wo * P
__device__ __align__(16) bf16 g_Ml [BATCH * CH * CH];
__device__ __align__(16) bf16 g_Wqh[CH * CH];
__device__ __align__(16) bf16 g_Wql[CH * CH];
__device__ __align__(16) bf16 g_Woh[CH * CH];
__device__ __align__(16) bf16 g_Wol[CH * CH];

// ---------------- asm helpers (sm_80-compatible only) ----------------
__device__ __forceinline__ uint32_t smem_u32(const void* p) {
    uint32_t a;
    asm("{ .reg .u64 t; cvta.to.shared.u64 t, %1; cvt.u32.u64 %0, t; }" : "=r"(a) : "l"(p));
    return a;
}
__device__ __forceinline__ void ldsm4(uint32_t* r, uint32_t a) {
    asm volatile("ldmatrix.sync.aligned.m8n8.x4.shared.b16 {%0,%1,%2,%3}, [%4];"
                 : "=r"(r[0]), "=r"(r[1]), "=r"(r[2]), "=r"(r[3]) : "r"(a));
}
__device__ __forceinline__ void mma_bf16(float* c, const uint32_t* a, const uint32_t* b) {
    asm volatile(
        "mma.sync.aligned.m16n8k16.row.col.f32.bf16.bf16.f32 "
        "{%0,%1,%2,%3}, {%4,%5,%6,%7}, {%8,%9}, {%0,%1,%2,%3};"
        : "+f"(c[0]), "+f"(c[1]), "+f"(c[2]), "+f"(c[3])
        : "r"(a[0]), "r"(a[1]), "r"(a[2]), "r"(a[3]), "r"(b[0]), "r"(b[1]));
}
#define CP_A16(dst, src) asm volatile( \
    "cp.async.cg.shared.global [%0], [%1], 16;" :: "r"(dst), "l"(src))
#define CP_COMMIT() asm volatile("cp.async.commit_group;" ::: "memory")
#define CP_WAIT0()  asm volatile("cp.async.wait_group 0;" ::: "memory")
#define CP_WAIT1()  asm volatile("cp.async.wait_group 1;" ::: "memory")

// ---------------- smem geometry for mma_gemm ----------------
// per stage: AH | AL | BH | BL, each 128 rows x 40 halves (80 B pitch) = 10240 B
#define ROWPITCH 80
#define ARR_BYTES 10240
#define STAGE_BYTES (4 * ARR_BYTES)          // 40960
#define MMA_SMEM (2 * STAGE_BYTES)           // 81920

// =================================================================
// 3-term bf16 GEMM via mma.sync:  C(128x128 tile) = Ah*Bh^T + Ah*Bl^T + Al*Bh^T
// A: [M x K] row-major (K-major), B: [N x K] row-major (K-major).
// EPI: 0 = fp32 out, 2 = bf16 hi/lo out, 3 = fp32 out + per-row bias
// =================================================================
template<int EPI>
__global__ void __launch_bounds__(256) mma_gemm(
    const bf16* __restrict__ Ahg, const bf16* __restrict__ Alg,
    const bf16* __restrict__ Bhg, const bf16* __restrict__ Blg,
    float* __restrict__ Cf, bf16* __restrict__ Chh, bf16* __restrict__ Cll,
    const float* __restrict__ biasg,
    int Kdim, int ldc, long sA, long sB, long sC)
{
    extern __shared__ char smem[];
    uint32_t sbase = smem_u32(smem);
    int tid = threadIdx.x;
    int lane = tid & 31, wid = tid >> 5;
    int b = blockIdx.z;
    int m0 = blockIdx.y * 128, n0 = blockIdx.x * 128;
    int m_warp = (wid & 3) * 32, n_warp = (wid >> 2) * 64;

    const bf16* pAh = Ahg + b * sA + (long)m0 * Kdim;
    const bf16* pAl = Alg + b * sA + (long)m0 * Kdim;
    const bf16* pBh = Bhg + b * sB + (long)n0 * Kdim;
    const bf16* pBl = Blg + b * sB + (long)n0 * Kdim;

    // per-lane ldmatrix byte offsets
    uint32_t a_off = (uint32_t)((m_warp + (lane & 15)) * ROWPITCH + (lane >> 4) * 16);
    uint32_t b_off = (uint32_t)((n_warp + (lane & 7) + ((lane >> 4) & 1) * 8) * ROWPITCH
                                + ((lane >> 3) & 1) * 16);

    float acc[2][8][4];
    #pragma unroll
    for (int mt = 0; mt < 2; mt++)
        #pragma unroll
        for (int nt = 0; nt < 8; nt++)
            #pragma unroll
            for (int q = 0; q < 4; q++) acc[mt][nt][q] = 0.f;

    int nch = Kdim >> 5;   // K chunks of 32

    // ---- loader: one K-chunk (32 halves) of all 4 arrays into stage st ----
    auto load_stage = [&](int stage, int k0) {
        uint32_t st = sbase + stage * STAGE_BYTES;
        #pragma unroll
        for (int it = 0; it < 2; it++) {
            int q = tid + it * 256;          // q in [0,512): r = q>>2, chunk = q&3
            int r = q >> 2, c = q & 3;
            uint32_t off = r * ROWPITCH + c * 16;
            long gofs = ((long)r * Kdim + k0 + c * 8);
            CP_A16(st + 0 * ARR_BYTES + off, (const char*)(pAh + gofs));
            CP_A16(st + 1 * ARR_BYTES + off, (const char*)(pAl + gofs));
            CP_A16(st + 2 * ARR_BYTES + off, (const char*)(pBh + gofs));
            CP_A16(st + 3 * ARR_BYTES + off, (const char*)(pBl + gofs));
        }
        CP_COMMIT();
    };

    load_stage(0, 0);

    for (int ic = 0; ic < nch; ic++) {
        int p = ic & 1;
        if (ic + 1 < nch) { load_stage(p ^ 1, (ic + 1) * 32); CP_WAIT1(); }
        else              { CP_WAIT0(); }
        __syncthreads();

        uint32_t st = sbase + p * STAGE_BYTES;
        #pragma unroll
        for (int kk = 0; kk < 2; kk++) {
            uint32_t ah[2][4], al[2][4];
            ldsm4(ah[0], st + 0 * ARR_BYTES + a_off + kk * 32);
            ldsm4(ah[1], st + 0 * ARR_BYTES + a_off + 16 * ROWPITCH + kk * 32);
            ldsm4(al[0], st + 1 * ARR_BYTES + a_off + kk * 32);
            ldsm4(al[1], st + 1 * ARR_BYTES + a_off + 16 * ROWPITCH + kk * 32);
            #pragma unroll
            for (int ntp = 0; ntp < 4; ntp++) {
                uint32_t bh[4], bl[4];
                ldsm4(bh, st + 2 * ARR_BYTES + b_off + ntp * 16 * ROWPITCH + kk * 32);
                ldsm4(bl, st + 3 * ARR_BYTES + b_off + ntp * 16 * ROWPITCH + kk * 32);
                #pragma unroll
                for (int mt = 0; mt < 2; mt++) {
                    mma_bf16(acc[mt][2 * ntp],     ah[mt], bh);
                    mma_bf16(acc[mt][2 * ntp],     ah[mt], bl);
                    mma_bf16(acc[mt][2 * ntp],     al[mt], bh);
                    mma_bf16(acc[mt][2 * ntp + 1], ah[mt], bh + 2);
                    mma_bf16(acc[mt][2 * ntp + 1], ah[mt], bl + 2);
                    mma_bf16(acc[mt][2 * ntp + 1], al[mt], bh + 2);
                }
            }
        }
        __syncthreads();
    }

    // ---- epilogue ----
    #pragma unroll
    for (int mt = 0; mt < 2; mt++) {
        #pragma unroll
        for (int hh = 0; hh < 2; hh++) {
            int rg = m0 + m_warp + mt * 16 + (lane >> 2) + hh * 8;
            float bias = (EPI == 3) ? biasg[b * CH + rg] : 0.f;
            long rowoff = b * sC + (long)rg * ldc;
            #pragma unroll
            for (int nt = 0; nt < 8; nt++) {
                int cg = n0 + n_warp + nt * 8 + (lane & 3) * 2;
                float v0 = acc[mt][nt][hh * 2 + 0];
                float v1 = acc[mt][nt][hh * 2 + 1];
                if (EPI == 2) {
                    bf16 h0 = __float2bfloat16(v0);
                    bf16 h1 = __float2bfloat16(v1);
                    __nv_bfloat162 hv, lv;
                    hv.x = h0; hv.y = h1;
                    lv.x = __float2bfloat16(v0 - __bfloat162float(h0));
                    lv.y = __float2bfloat16(v1 - __bfloat162float(h1));
                    *(__nv_bfloat162*)(Chh + rowoff + cg) = hv;
                    *(__nv_bfloat162*)(Cll + rowoff + cg) = lv;
                } else {
                    *(float2*)(Cf + rowoff + cg) = make_float2(v0 + bias, v1 + bias);
                }
            }
        }
    }
}

// =================================================================
// x -> (Xh, Xl) same layout + (Xth, Xtl) transposed, via 32x32 smem tiles
// =================================================================
__global__ void splitx_kernel(const float* __restrict__ x) {
    __shared__ bf16 sh[32][33];
    __shared__ bf16 sl[32][33];
    int b = blockIdx.z;
    int n0 = blockIdx.x * 32, c0 = blockIdx.y * 32;
    int tx = threadIdx.x, ty = threadIdx.y;
    const float* xb = x + (long)b * CH * NPIX;
    #pragma unroll
    for (int k = 0; k < 4; k++) {
        int c = c0 + ty + k * 8;
        float v = xb[(long)c * NPIX + n0 + tx];
        bf16 h = __float2bfloat16(v);
        bf16 l = __float2bfloat16(v - __bfloat162float(h));
        long idx = ((long)b * CH + c) * NPIX + n0 + tx;
        g_Xh[idx] = h;
        g_Xl[idx] = l;
        sh[ty + k * 8][tx] = h;
        sl[ty + k * 8][tx] = l;
    }
    __syncthreads();
    #pragma unroll
    for (int k = 0; k < 4; k++) {
        int n = n0 + ty + k * 8;
        long idx = ((long)b * NPIX + n) * CH + c0 + tx;
        g_Xth[idx] = sh[tx][ty + k * 8];
        g_Xtl[idx] = sl[tx][ty + k * 8];
    }
}

// ---------------- elementwise split fp32 -> bf16 h/l ----------------
__global__ void splitw_kernel(const float* __restrict__ src,
                              bf16* __restrict__ oh, bf16* __restrict__ ol) {
    long i = ((long)blockIdx.x * 256 + threadIdx.x) * 4;
    float4 v = *(const float4*)(src + i);
    bf16 h0 = __float2bfloat16(v.x), h1 = __float2bfloat16(v.y);
    bf16 h2 = __float2bfloat16(v.z), h3 = __float2bfloat16(v.w);
    oh[i + 0] = h0; ol[i + 0] = __float2bfloat16(v.x - __bfloat162float(h0));
    oh[i + 1] = h1; ol[i + 1] = __float2bfloat16(v.y - __bfloat162float(h1));
    oh[i + 2] = h2; ol[i + 2] = __float2bfloat16(v.z - __bfloat162float(h2));
    oh[i + 3] = h3; ol[i + 3] = __float2bfloat16(v.w - __bfloat162float(h3));
}

// ---------------- row sums s[b,c] = sum_n X[b,c,n] ----------------
__global__ void rowsum_kernel(const float* __restrict__ x) {
    int c = blockIdx.x, b = blockIdx.y;
    const float* row = x + ((long)b * CH + c) * NPIX;
    float s = 0.f;
    for (int n = threadIdx.x * 4; n < NPIX; n += 256 * 4) {
        float4 v = *(const float4*)(row + n);
        s += v.x + v.y + v.z + v.w;
    }
    __shared__ float red[256];
    red[threadIdx.x] = s;
    __syncthreads();
    for (int off = 128; off > 0; off >>= 1) {
        if (threadIdx.x < off) red[threadIdx.x] += red[threadIdx.x + off];
        __syncthreads();
    }
    if (threadIdx.x == 0) g_s[b * CH + c] = red[0];
}

// ---------------- qs = Wq*s, ks = Wk*s (per batch) ----------------
__global__ void qsks_kernel(const float* __restrict__ wq, const float* __restrict__ wk) {
    int b = blockIdx.x;
    __shared__ float sv[CH];
    for (int i = threadIdx.x; i < CH; i += 256) sv[i] = g_s[b * CH + i];
    __syncthreads();
    for (int o = threadIdx.x; o < CH; o += 256) {
        const float* wr = wq + (long)o * CH;
        const float* kr = wk + (long)o * CH;
        float aq = 0.f, ak = 0.f;
        for (int c = 0; c < CH; c++) { aq += wr[c] * sv[c]; ak += kr[c] * sv[c]; }
        g_qs[b * CH + o] = aq;
        g_ks[b * CH + o] = ak;
    }
}

// ---------------- energy blocks + softmax + abv ----------------
__global__ void __launch_bounds__(256) attn_kernel(
    const float* __restrict__ wk, const float* __restrict__ bq,
    const float* __restrict__ bk, const float* __restrict__ bv)
{
    int h = blockIdx.x, b = blockIdx.y;
    __shared__ float Ts[16][64];
    __shared__ float Ks[16][64];
    __shared__ float Es[64][65];
    __shared__ float qv[64], kvv[64], bqv[64], bkv[64], bvv[64];
    int tid = threadIdx.x;
    if (tid < 64) {
        qv[tid]  = g_qs[b * CH + h * HD + tid];
        kvv[tid] = g_ks[b * CH + h * HD + tid];
        bqv[tid] = bq[h * HD + tid];
        bkv[tid] = bk[h * HD + tid];
        bvv[tid] = bv[h * HD + tid];
    }
    const float* Tb = g_T + ((long)b * CH + h * HD) * CH;
    const float* Kb = wk + (long)(h * HD) * CH;
    int lrow = tid >> 2;
    int lcol = (tid & 3) * 4;
    int tx = tid & 15, ty = tid >> 4;
    float acc[4][4];
    #pragma unroll
    for (int i = 0; i < 4; i++)
        #pragma unroll
        for (int j = 0; j < 4; j++) acc[i][j] = 0.f;

    for (int a0 = 0; a0 < CH; a0 += 16) {
        float4 tv = *(const float4*)(Tb + (long)lrow * CH + a0 + lcol);
        Ts[lcol + 0][lrow] = tv.x; Ts[lcol + 1][lrow] = tv.y;
        Ts[lcol + 2][lrow] = tv.z; Ts[lcol + 3][lrow] = tv.w;
        float4 kv4 = *(const float4*)(Kb + (long)lrow * CH + a0 + lcol);
        Ks[lcol + 0][lrow] = kv4.x; Ks[lcol + 1][lrow] = kv4.y;
        Ks[lcol + 2][lrow] = kv4.z; Ks[lcol + 3][lrow] = kv4.w;
        __syncthreads();
        #pragma unroll
        for (int kk = 0; kk < 16; kk++) {
            float ra[4], rb[4];
            *(float4*)&ra[0] = *(const float4*)&Ts[kk][ty * 4];
            *(float4*)&rb[0] = *(const float4*)&Ks[kk][tx * 4];
            #pragma unroll
            for (int i = 0; i < 4; i++)
                #pragma unroll
                for (int j = 0; j < 4; j++)
                    acc[i][j] += ra[i] * rb[j];
        }
        __syncthreads();
    }
    #pragma unroll
    for (int i = 0; i < 4; i++) {
        int gi = ty * 4 + i;
        #pragma unroll
        for (int j = 0; j < 4; j++) {
            int gj = tx * 4 + j;
            float e = acc[i][j] + qv[gi] * bkv[gj] + bqv[gi] * kvv[gj]
                      + 4096.f * bqv[gi] * bkv[gj];
            Es[gi][gj] = e * ATT_SCALE;
        }
    }
    __syncthreads();
    if (tid < 64) {
        int i = tid;
        float m = -1e30f;
        for (int j = 0; j < 64; j++) m = fmaxf(m, Es[i][j]);
        float sum = 0.f;
        for (int j = 0; j < 64; j++) {
            float ex = expf(Es[i][j] - m);
            Es[i][j] = ex;
            sum += ex;
        }
        float inv = 1.f / sum;
        float ab = 0.f;
        float* Arow = g_A + (((long)b * NH + h) * HD + i) * HD;
        for (int j = 0; j < 64; j++) {
            float a = Es[i][j] * inv;
            Arow[j] = a;
            ab += a * bvv[j];
        }
        g_abv[b * CH + h * HD + i] = ab;
    }
}

// ---------------- Pt = (A_bd * Wv)^T, written as bf16 hi/lo [c][r] ----------------
__global__ void __launch_bounds__(256) pk_kernel(const float* __restrict__ wv) {
    int h = blockIdx.x, b = blockIdx.y;
    __shared__ float Ash[64][64];   // Ash[j][i] = A[i][j]
    __shared__ float Bv[64][64];
    int tid = threadIdx.x;
    const float* Ab = g_A + ((long)b * NH + h) * HD * HD;
    for (int r = tid; r < 64 * 16; r += 256) {
        int i = r >> 4, q = (r & 15) * 4;
        float4 v = *(const float4*)(Ab + i * 64 + q);
        Ash[q + 0][i] = v.x; Ash[q + 1][i] = v.y;
        Ash[q + 2][i] = v.z; Ash[q + 3][i] = v.w;
    }
    int tx = tid & 15, ty = tid >> 4;
    for (int cc = 0; cc < CH; cc += 64) {
        __syncthreads();
        for (int r = tid; r < 64 * 16; r += 256) {
            int j = r >> 4, q = (r & 15) * 4;
            *(float4*)&Bv[j][q] = *(const float4*)(wv + (long)(h * HD + j) * CH + cc + q);
        }
        __syncthreads();
        float acc[4][4];
        #pragma unroll
        for (int i = 0; i < 4; i++)
            #pragma unroll
            for (int j = 0; j < 4; j++) acc[i][j] = 0.f;
        #pragma unroll 8
        for (int j = 0; j < 64; j++) {
            float ra[4], rb[4];
            *(float4*)&ra[0] = *(const float4*)&Ash[j][ty * 4];
            *(float4*)&rb[0] = *(const float4*)&Bv[j][tx * 4];
            #pragma unroll
            for (int i = 0; i < 4; i++)
                #pragma unroll
                for (int u = 0; u < 4; u++)
                    acc[i][u] += ra[i] * rb[u];
        }
        // transposed bf16 hi/lo store: Pt[c][r], 4 consecutive r per thread per u
        #pragma unroll
        for (int u = 0; u < 4; u++) {
            int c = cc + tx * 4 + u;
            long base = ((long)b * CH + c) * CH + h * HD + ty * 4;
            float v0 = acc[0][u], v1 = acc[1][u], v2 = acc[2][u], v3 = acc[3][u];
            bf16 h0 = __float2bfloat16(v0), h1 = __float2bfloat16(v1);
            bf16 h2 = __float2bfloat16(v2), h3 = __float2bfloat16(v3);
            __nv_bfloat162 a0, a1, b0, b1;
            a0.x = h0; a0.y = h1; a1.x = h2; a1.y = h3;
            b0.x = __float2bfloat16(v0 - __bfloat162float(h0));
            b0.y = __float2bfloat16(v1 - __bfloat162float(h1));
            b1.x = __float2bfloat16(v2 - __bfloat162float(h2));
            b1.y = __float2bfloat16(v3 - __bfloat162float(h3));
            *(__nv_bfloat162*)(g_Pth + base)     = a0;
            *(__nv_bfloat162*)(g_Pth + base + 2) = a1;
            *(__nv_bfloat162*)(g_Ptl + base)     = b0;
            *(__nv_bfloat162*)(g_Ptl + base + 2) = b1;
        }
    }
}

// ---------------- c[b] = Wo * abv[b] + bo ----------------
__global__ void cvec_kernel(const float* __restrict__ wo, const float* __restrict__ bo) {
    int b = blockIdx.x;
    __shared__ float sv[CH];
    for (int i = threadIdx.x; i < CH; i += 256) sv[i] = g_abv[b * CH + i];
    __syncthreads();
    for (int o = threadIdx.x; o < CH; o += 256) {
        const float* wr = wo + (long)o * CH;
        float sum = bo[o];
        for (int c = 0; c < CH; c++) sum += wr[c] * sv[c];
        g_c[b * CH + o] = sum;
    }
}

// ---------------- launch ----------------
extern "C" void kernel_launch(void* const* d_in, const int* in_sizes, int n_in,
                              void* d_out, int out_size) {
    const float* x  = (const float*)d_in[0];
    const float* wq = (const float*)d_in[1];
    const float* bq = (const float*)d_in[2];
    const float* wk = (const float*)d_in[3];
    const float* bk = (const float*)d_in[4];
    const float* wv = (const float*)d_in[5];
    const float* bv = (const float*)d_in[6];
    const float* wo = (const float*)d_in[7];
    const float* bo = (const float*)d_in[8];
    float* y = (float*)d_out;

    float *pT, *pc;
    bf16 *pXh, *pXl, *pXth, *pXtl, *pGh, *pGl, *pPth, *pPtl, *pMh, *pMl;
    bf16 *pWqh, *pWql, *pWoh, *pWol;
    cudaGetSymbolAddress((void**)&pT,  g_T);
    cudaGetSymbolAddress((void**)&pc,  g_c);
    cudaGetSymbolAddress((void**)&pXh, g_Xh);
    cudaGetSymbolAddress((void**)&pXl, g_Xl);
    cudaGetSymbolAddress((void**)&pXth, g_Xth);
    cudaGetSymbolAddress((void**)&pXtl, g_Xtl);
    cudaGetSymbolAddress((void**)&pGh, g_Gh);
    cudaGetSymbolAddress((void**)&pGl, g_Gl);
    cudaGetSymbolAddress((void**)&pPth, g_Pth);
    cudaGetSymbolAddress((void**)&pPtl, g_Ptl);
    cudaGetSymbolAddress((void**)&pMh, g_Mh);
    cudaGetSymbolAddress((void**)&pMl, g_Ml);
    cudaGetSymbolAddress((void**)&pWqh, g_Wqh);
    cudaGetSymbolAddress((void**)&pWql, g_Wql);
    cudaGetSymbolAddress((void**)&pWoh, g_Woh);
    cudaGetSymbolAddress((void**)&pWol, g_Wol);

    cudaFuncSetAttribute(mma_gemm<0>, cudaFuncAttributeMaxDynamicSharedMemorySize, MMA_SMEM);
    cudaFuncSetAttribute(mma_gemm<2>, cudaFuncAttributeMaxDynamicSharedMemorySize, MMA_SMEM);
    cudaFuncSetAttribute(mma_gemm<3>, cudaFuncAttributeMaxDynamicSharedMemorySize, MMA_SMEM);

    // 1. split x -> bf16 hi/lo (natural + transposed)
    splitx_kernel<<<dim3(NPIX / 32, CH / 32, BATCH), dim3(32, 8)>>>(x);

    // 2. row sums + weight splits
    rowsum_kernel<<<dim3(CH, BATCH), 256>>>(x);
    splitw_kernel<<<(CH * CH) / 1024, 256>>>(wq, pWqh, pWql);
    splitw_kernel<<<(CH * CH) / 1024, 256>>>(wo, pWoh, pWol);

    // 3. Gram: G[b] = X X^T (3-term bf16), out bf16 h/l.  K = 4096
    mma_gemm<2><<<dim3(6, 6, BATCH), 256, MMA_SMEM>>>(
        pXh, pXl, pXh, pXl, nullptr, pGh, pGl, nullptr,
        NPIX, CH, (long)CH * NPIX, (long)CH * NPIX, (long)CH * CH);

    // 4. qs/ks
    qsks_kernel<<<BATCH, 256>>>(wq, wk);

    // 5. T[b] = Wq * G[b]  (G symmetric -> row-major == K-major).  K = 768
    mma_gemm<0><<<dim3(6, 6, BATCH), 256, MMA_SMEM>>>(
        pWqh, pWql, pGh, pGl, pT, nullptr, nullptr, nullptr,
        CH, CH, 0L, (long)CH * CH, (long)CH * CH);

    // 6. energy blocks + softmax + abv
    attn_kernel<<<dim3(NH, BATCH), 256>>>(wk, bq, bk, bv);

    // 7. Pt[b] = (A_bd * Wv)^T  -> bf16 h/l
    pk_kernel<<<dim3(NH, BATCH), 256>>>(wv);

    // 8. c[b] = Wo * abv + bo
    cvec_kernel<<<BATCH, 256>>>(wo, bo);

    // 9. M[b] = Wo * P[b]  (B operand = Pt, [c][r] K-major).  K = 768
    mma_gemm<2><<<dim3(6, 6, BATCH), 256, MMA_SMEM>>>(
        pWoh, pWol, pPth, pPtl, nullptr, pMh, pMl, nullptr,
        CH, CH, 0L, (long)CH * CH, (long)CH * CH);

    // 10. y[b] = M[b] * X[b] + c[b]  (B operand = Xt, [n][c] K-major).  K = 768
    mma_gemm<3><<<dim3(NPIX / 128, 6, BATCH), 256, MMA_SMEM>>>(
        pMh, pMl, pXth, pXtl, y, nullptr, nullptr, pc,
        CH, NPIX, (long)CH * CH, (long)NPIX * CH, (long)CH * NPIX);
}

// round 6
// speedup vs baseline: 2.1798x; 1.1109x over previous
#include <cuda_runtime.h>
#include <cuda_bf16.h>
#include <math.h>
#include <stdint.h>

#define BATCH 16
#define CH    768
#define NPIX  4096
#define NH    12
#define HD    64
#define ATT_SCALE 0.125f   // HD^-0.5

typedef __nv_bfloat16 bf16;

// ---------------- scratch (device globals; no runtime allocation) ----------------
__device__ float g_T[BATCH * CH * CH];      // T = Wq * G (fp32, feeds attn)
__device__ float g_M[BATCH * CH * CH];      // M = Wo * P (fp32, quantized after)
__device__ float g_A[BATCH * NH * HD * HD]; // softmax attention blocks
__device__ float g_s[BATCH * CH];           // row sums of X
__device__ float g_qs[BATCH * CH];          // Wq * s
__device__ float g_ks[BATCH * CH];          // Wk * s
__device__ float g_abv[BATCH * CH];         // A_bd * bv
__device__ float g_c[BATCH * CH];           // Wo * abv + bo
__device__ float g_sXt[BATCH * NPIX];       // column max scales of X (per n)
__device__ float g_sM[BATCH * CH];          // row max scales of M

// bf16 hi/lo splits (Gram + mid GEMM operands)
__device__ __align__(16) bf16 g_Xh [BATCH * CH * NPIX]; // [b][c][n]
__device__ __align__(16) bf16 g_Xl [BATCH * CH * NPIX];
__device__ __align__(16) bf16 g_Gh [BATCH * CH * CH];   // Gram (symmetric)
__device__ __align__(16) bf16 g_Gl [BATCH * CH * CH];
__device__ __align__(16) bf16 g_Pth[BATCH * CH * CH];   // (A_bd * Wv)^T : [c][r]
__device__ __align__(16) bf16 g_Ptl[BATCH * CH * CH];
__device__ __align__(16) bf16 g_Wqh[CH * CH];
__device__ __align__(16) bf16 g_Wql[CH * CH];
__device__ __align__(16) bf16 g_Woh[CH * CH];
__device__ __align__(16) bf16 g_Wol[CH * CH];

// int8 2-limb (final GEMM operands)
__device__ __align__(16) int8_t g_Xt0[BATCH * NPIX * CH]; // [b][n][c]
__device__ __align__(16) int8_t g_Xt1[BATCH * NPIX * CH];
__device__ __align__(16) int8_t g_M0 [BATCH * CH * CH];
__device__ __align__(16) int8_t g_M1 [BATCH * CH * CH];

// ---------------- asm helpers (sm_80-compatible only) ----------------
__device__ __forceinline__ uint32_t smem_u32(const void* p) {
    uint32_t a;
    asm("{ .reg .u64 t; cvta.to.shared.u64 t, %1; cvt.u32.u64 %0, t; }" : "=r"(a) : "l"(p));
    return a;
}
__device__ __forceinline__ void ldsm4(uint32_t* r, uint32_t a) {
    asm volatile("ldmatrix.sync.aligned.m8n8.x4.shared.b16 {%0,%1,%2,%3}, [%4];"
                 : "=r"(r[0]), "=r"(r[1]), "=r"(r[2]), "=r"(r[3]) : "r"(a));
}
__device__ __forceinline__ void mma_bf16(float* c, const uint32_t* a, const uint32_t* b) {
    asm volatile(
        "mma.sync.aligned.m16n8k16.row.col.f32.bf16.bf16.f32 "
        "{%0,%1,%2,%3}, {%4,%5,%6,%7}, {%8,%9}, {%0,%1,%2,%3};"
        : "+f"(c[0]), "+f"(c[1]), "+f"(c[2]), "+f"(c[3])
        : "r"(a[0]), "r"(a[1]), "r"(a[2]), "r"(a[3]), "r"(b[0]), "r"(b[1]));
}
__device__ __forceinline__ void mma_s8(int* c, const uint32_t* a, const uint32_t* b) {
    asm volatile(
        "mma.sync.aligned.m16n8k32.row.col.s32.s8.s8.s32 "
        "{%0,%1,%2,%3}, {%4,%5,%6,%7}, {%8,%9}, {%0,%1,%2,%3};"
        : "+r"(c[0]), "+r"(c[1]), "+r"(c[2]), "+r"(c[3])
        : "r"(a[0]), "r"(a[1]), "r"(a[2]), "r"(a[3]), "r"(b[0]), "r"(b[1]));
}
#define CP_A16(dst, src) asm volatile( \
    "cp.async.cg.shared.global [%0], [%1], 16;" :: "r"(dst), "l"(src))
#define CP_COMMIT() asm volatile("cp.async.commit_group;" ::: "memory")
#define CP_WAIT0()  asm volatile("cp.async.wait_group 0;" ::: "memory")
#define CP_WAIT1()  asm volatile("cp.async.wait_group 1;" ::: "memory")

// ---------------- smem geometry (identical bytes for bf16 & i8 pipelines) ----------------
// per stage: 4 arrays x (128 rows x 80 B pitch, 64 B payload) = 40960 B
#define ROWPITCH 80
#define ARR_BYTES 10240
#define STAGE_BYTES (4 * ARR_BYTES)
#define MMA_SMEM (2 * STAGE_BYTES)          // 81920

// =================================================================
// 3-term bf16 GEMM via mma.sync:  C(128x128) = Ah*Bh^T + Ah*Bl^T + Al*Bh^T
// A: [M x K] K-major, B: [N x K] K-major.
// EPI: 0 = fp32 out, 2 = bf16 hi/lo out.  MIRROR: lower-triangle grid + transpose write.
// =================================================================
template<int EPI, bool MIRROR>
__global__ void __launch_bounds__(256) mma_gemm(
    const bf16* __restrict__ Ahg, const bf16* __restrict__ Alg,
    const bf16* __restrict__ Bhg, const bf16* __restrict__ Blg,
    float* __restrict__ Cf, bf16* __restrict__ Chh, bf16* __restrict__ Cll,
    int Kdim, int ldc, long sA, long sB, long sC)
{
    extern __shared__ char smem[];
    uint32_t sbase = smem_u32(smem);
    int tid = threadIdx.x;
    int lane = tid & 31, wid = tid >> 5;
    int b = blockIdx.z;
    int m0, n0;
    if (MIRROR) {
        int t = blockIdx.x, bi = 0;
        while ((bi + 1) * (bi + 2) / 2 <= t) bi++;
        int bj = t - bi * (bi + 1) / 2;
        m0 = bi * 128; n0 = bj * 128;
    } else {
        m0 = blockIdx.y * 128; n0 = blockIdx.x * 128;
    }
    int m_warp = (wid & 3) * 32, n_warp = (wid >> 2) * 64;

    const bf16* pAh = Ahg + b * sA + (long)m0 * Kdim;
    const bf16* pAl = Alg + b * sA + (long)m0 * Kdim;
    const bf16* pBh = Bhg + b * sB + (long)n0 * Kdim;
    const bf16* pBl = Blg + b * sB + (long)n0 * Kdim;

    uint32_t a_off = (uint32_t)((m_warp + (lane & 15)) * ROWPITCH + (lane >> 4) * 16);
    uint32_t b_off = (uint32_t)((n_warp + (lane & 7) + ((lane >> 4) & 1) * 8) * ROWPITCH
                                + ((lane >> 3) & 1) * 16);

    float acc[2][8][4];
    #pragma unroll
    for (int mt = 0; mt < 2; mt++)
        #pragma unroll
        for (int nt = 0; nt < 8; nt++)
            #pragma unroll
            for (int q = 0; q < 4; q++) acc[mt][nt][q] = 0.f;

    int nch = Kdim >> 5;   // K chunks of 32 bf16 (64 B)

    auto load_stage = [&](int stage, int k0) {
        uint32_t st = sbase + stage * STAGE_BYTES;
        #pragma unroll
        for (int it = 0; it < 2; it++) {
            int q = tid + it * 256;
            int r = q >> 2, c = q & 3;
            uint32_t off = r * ROWPITCH + c * 16;
            long gofs = ((long)r * Kdim + k0 + c * 8);
            CP_A16(st + 0 * ARR_BYTES + off, (const char*)(pAh + gofs));
            CP_A16(st + 1 * ARR_BYTES + off, (const char*)(pAl + gofs));
            CP_A16(st + 2 * ARR_BYTES + off, (const char*)(pBh + gofs));
            CP_A16(st + 3 * ARR_BYTES + off, (const char*)(pBl + gofs));
        }
        CP_COMMIT();
    };

    load_stage(0, 0);

    for (int ic = 0; ic < nch; ic++) {
        int p = ic & 1;
        if (ic + 1 < nch) { load_stage(p ^ 1, (ic + 1) * 32); CP_WAIT1(); }
        else              { CP_WAIT0(); }
        __syncthreads();

        uint32_t st = sbase + p * STAGE_BYTES;
        #pragma unroll
        for (int kk = 0; kk < 2; kk++) {
            uint32_t ah[2][4], al[2][4];
            ldsm4(ah[0], st + 0 * ARR_BYTES + a_off + kk * 32);
            ldsm4(ah[1], st + 0 * ARR_BYTES + a_off + 16 * ROWPITCH + kk * 32);
            ldsm4(al[0], st + 1 * ARR_BYTES + a_off + kk * 32);
            ldsm4(al[1], st + 1 * ARR_BYTES + a_off + 16 * ROWPITCH + kk * 32);
            #pragma unroll
            for (int ntp = 0; ntp < 4; ntp++) {
                uint32_t bh[4], bl[4];
                ldsm4(bh, st + 2 * ARR_BYTES + b_off + ntp * 16 * ROWPITCH + kk * 32);
                ldsm4(bl, st + 3 * ARR_BYTES + b_off + ntp * 16 * ROWPITCH + kk * 32);
                #pragma unroll
                for (int mt = 0; mt < 2; mt++) {
                    mma_bf16(acc[mt][2 * ntp],     ah[mt], bh);
                    mma_bf16(acc[mt][2 * ntp],     ah[mt], bl);
                    mma_bf16(acc[mt][2 * ntp],     al[mt], bh);
                    mma_bf16(acc[mt][2 * ntp + 1], ah[mt], bh + 2);
                    mma_bf16(acc[mt][2 * ntp + 1], ah[mt], bl + 2);
                    mma_bf16(acc[mt][2 * ntp + 1], al[mt], bh + 2);
                }
            }
        }
        __syncthreads();
    }

    bool do_mirror = MIRROR && (m0 != n0);

    #pragma unroll
    for (int mt = 0; mt < 2; mt++) {
        #pragma unroll
        for (int hh = 0; hh < 2; hh++) {
            int rg = m0 + m_warp + mt * 16 + (lane >> 2) + hh * 8;
            long rowoff = b * sC + (long)rg * ldc;
            #pragma unroll
            for (int nt = 0; nt < 8; nt++) {
                int cg = n0 + n_warp + nt * 8 + (lane & 3) * 2;
                float v0 = acc[mt][nt][hh * 2 + 0];
                float v1 = acc[mt][nt][hh * 2 + 1];
                if (EPI == 2) {
                    bf16 h0 = __float2bfloat16(v0);
                    bf16 h1 = __float2bfloat16(v1);
                    bf16 l0 = __float2bfloat16(v0 - __bfloat162float(h0));
                    bf16 l1 = __float2bfloat16(v1 - __bfloat162float(h1));
                    __nv_bfloat162 hv, lv;
                    hv.x = h0; hv.y = h1; lv.x = l0; lv.y = l1;
                    *(__nv_bfloat162*)(Chh + rowoff + cg) = hv;
                    *(__nv_bfloat162*)(Cll + rowoff + cg) = lv;
                    if (do_mirror) {
                        long tb = b * sC;
                        Chh[tb + (long)cg * ldc + rg]       = h0;
                        Chh[tb + (long)(cg + 1) * ldc + rg] = h1;
                        Cll[tb + (long)cg * ldc + rg]       = l0;
                        Cll[tb + (long)(cg + 1) * ldc + rg] = l1;
                    }
                } else {
                    *(float2*)(Cf + rowoff + cg) = make_float2(v0, v1);
                }
            }
        }
    }
}

// =================================================================
// int8 2-limb GEMM via mma.sync IMMA:  y = sA*sB*(A0B0 + (A0B1+A1B0)/128) + bias
// A: [M x K] K-major int8 limbs; B: [N x K] K-major int8 limbs.  fp32 out.
// =================================================================
__global__ void __launch_bounds__(256, 1) mma_gemm_i8(
    const int8_t* __restrict__ A0g, const int8_t* __restrict__ A1g,
    const int8_t* __restrict__ B0g, const int8_t* __restrict__ B1g,
    const float* __restrict__ sAg, const float* __restrict__ sBg,
    float* __restrict__ Cf, const float* __restrict__ biasg,
    int Kdim, int ldc, long sA, long sB, long sC)
{
    extern __shared__ char smem[];
    __shared__ float snv[128];
    uint32_t sbase = smem_u32(smem);
    int tid = threadIdx.x;
    int lane = tid & 31, wid = tid >> 5;
    int b = blockIdx.z;
    int m0 = blockIdx.y * 128, n0 = blockIdx.x * 128;
    int m_warp = (wid & 3) * 32, n_warp = (wid >> 2) * 64;

    const int8_t* pA0 = A0g + b * sA + (long)m0 * Kdim;
    const int8_t* pA1 = A1g + b * sA + (long)m0 * Kdim;
    const int8_t* pB0 = B0g + b * sB + (long)n0 * Kdim;
    const int8_t* pB1 = B1g + b * sB + (long)n0 * Kdim;

    if (tid < 128) snv[tid] = sBg[b * NPIX + n0 + tid];

    uint32_t a_off = (uint32_t)((m_warp + (lane & 15)) * ROWPITCH + (lane >> 4) * 16);
    uint32_t b_off = (uint32_t)((n_warp + (lane & 7) + ((lane >> 4) & 1) * 8) * ROWPITCH
                                + ((lane >> 3) & 1) * 16);

    int acc0[2][8][4], acc1[2][8][4];
    #pragma unroll
    for (int mt = 0; mt < 2; mt++)
        #pragma unroll
        for (int nt = 0; nt < 8; nt++)
            #pragma unroll
            for (int q = 0; q < 4; q++) { acc0[mt][nt][q] = 0; acc1[mt][nt][q] = 0; }

    int nch = Kdim >> 6;   // K chunks of 64 int8 (64 B)

    auto load_stage = [&](int stage, int k0) {
        uint32_t st = sbase + stage * STAGE_BYTES;
        #pragma unroll
        for (int it = 0; it < 2; it++) {
            int q = tid + it * 256;
            int r = q >> 2, c = q & 3;
            uint32_t off = r * ROWPITCH + c * 16;
            long gofs = ((long)r * Kdim + k0 + c * 16);
            CP_A16(st + 0 * ARR_BYTES + off, (const char*)(pA0 + gofs));
            CP_A16(st + 1 * ARR_BYTES + off, (const char*)(pA1 + gofs));
            CP_A16(st + 2 * ARR_BYTES + off, (const char*)(pB0 + gofs));
            CP_A16(st + 3 * ARR_BYTES + off, (const char*)(pB1 + gofs));
        }
        CP_COMMIT();
    };

    load_stage(0, 0);

    for (int ic = 0; ic < nch; ic++) {
        int p = ic & 1;
        if (ic + 1 < nch) { load_stage(p ^ 1, (ic + 1) * 64); CP_WAIT1(); }
        else              { CP_WAIT0(); }
        __syncthreads();

        uint32_t st = sbase + p * STAGE_BYTES;
        #pragma unroll
        for (int kk = 0; kk < 2; kk++) {   // two k32 steps per 64-B chunk
            uint32_t a0[2][4], a1[2][4];
            ldsm4(a0[0], st + 0 * ARR_BYTES + a_off + kk * 32);
            ldsm4(a0[1], st + 0 * ARR_BYTES + a_off + 16 * ROWPITCH + kk * 32);
            ldsm4(a1[0], st + 1 * ARR_BYTES + a_off + kk * 32);
            ldsm4(a1[1], st + 1 * ARR_BYTES + a_off + 16 * ROWPITCH + kk * 32);
            #pragma unroll
            for (int ntp = 0; ntp < 4; ntp++) {
                uint32_t b0[4], b1[4];
                ldsm4(b0, st + 2 * ARR_BYTES + b_off + ntp * 16 * ROWPITCH + kk * 32);
                ldsm4(b1, st + 3 * ARR_BYTES + b_off + ntp * 16 * ROWPITCH + kk * 32);
                #pragma unroll
                for (int mt = 0; mt < 2; mt++) {
                    mma_s8(acc0[mt][2 * ntp],     a0[mt], b0);
                    mma_s8(acc1[mt][2 * ntp],     a0[mt], b1);
                    mma_s8(acc1[mt][2 * ntp],     a1[mt], b0);
                    mma_s8(acc0[mt][2 * ntp + 1], a0[mt], b0 + 2);
                    mma_s8(acc1[mt][2 * ntp + 1], a0[mt], b1 + 2);
                    mma_s8(acc1[mt][2 * ntp + 1], a1[mt], b0 + 2);
                }
            }
        }
        __syncthreads();
    }

    #pragma unroll
    for (int mt = 0; mt < 2; mt++) {
        #pragma unroll
        for (int hh = 0; hh < 2; hh++) {
            int rg = m0 + m_warp + mt * 16 + (lane >> 2) + hh * 8;
            float sm = sAg[b * CH + rg];
            float bias = biasg[b * CH + rg];
            long rowoff = b * sC + (long)rg * ldc;
            #pragma unroll
            for (int nt = 0; nt < 8; nt++) {
                int cg = n0 + n_warp + nt * 8 + (lane & 3) * 2;
                int ci = cg - n0;
                float v0 = sm * snv[ci]     * ((float)acc0[mt][nt][hh * 2 + 0]
                           + (float)acc1[mt][nt][hh * 2 + 0] * 0.0078125f) + bias;
                float v1 = sm * snv[ci + 1] * ((float)acc0[mt][nt][hh * 2 + 1]
                           + (float)acc1[mt][nt][hh * 2 + 1] * 0.0078125f) + bias;
                *(float2*)(Cf + rowoff + cg) = make_float2(v0, v1);
            }
        }
    }
}

// ---------------- column max scales: s_Xt[b][n] = max_c |x[b][c][n]| / 127 ----------------
__global__ void colmax_kernel(const float* __restrict__ x) {
    int b = blockIdx.y;
    int n = blockIdx.x * 256 + threadIdx.x;
    const float* p = x + (long)b * CH * NPIX + n;
    float m0 = 0.f, m1 = 0.f, m2 = 0.f, m3 = 0.f;
    #pragma unroll 4
    for (int r = 0; r < CH; r += 4) {
        m0 = fmaxf(m0, fabsf(p[(long)(r + 0) * NPIX]));
        m1 = fmaxf(m1, fabsf(p[(long)(r + 1) * NPIX]));
        m2 = fmaxf(m2, fabsf(p[(long)(r + 2) * NPIX]));
        m3 = fmaxf(m3, fabsf(p[(long)(r + 3) * NPIX]));
    }
    float m = fmaxf(fmaxf(m0, m1), fmaxf(m2, m3));
    g_sXt[b * NPIX + n] = fmaxf(m, 1e-20f) * (1.f / 127.f);
}

// ---------------- x -> bf16 h/l (natural) + int8 2-limb (transposed) ----------------
__global__ void splitx_kernel(const float* __restrict__ x) {
    __shared__ float xt[32][33];
    int b = blockIdx.z;
    int n0 = blockIdx.x * 32, c0 = blockIdx.y * 32;
    int tx = threadIdx.x, ty = threadIdx.y;
    const float* xb = x + (long)b * CH * NPIX;
    #pragma unroll
    for (int k = 0; k < 4; k++) {
        int c = c0 + ty + k * 8;
        float v = xb[(long)c * NPIX + n0 + tx];
        xt[ty + k * 8][tx] = v;
        bf16 h = __float2bfloat16(v);
        bf16 l = __float2bfloat16(v - __bfloat162float(h));
        long idx = ((long)b * CH + c) * NPIX + n0 + tx;
        g_Xh[idx] = h;
        g_Xl[idx] = l;
    }
    __syncthreads();
    int tid = ty * 32 + tx;
    int nl = tid >> 3;
    int cl = (tid & 7) * 4;
    int n = n0 + nl;
    float inv = 1.f / g_sXt[b * NPIX + n];
    char q0[4], q1[4];
    #pragma unroll
    for (int j = 0; j < 4; j++) {
        float q = xt[cl + j][nl] * inv;
        q = fminf(fmaxf(q, -127.f), 127.f);
        float a0 = rintf(q);
        float a1 = rintf((q - a0) * 128.f);
        q0[j] = (char)a0;
        q1[j] = (char)a1;
    }
    long tidx = ((long)b * NPIX + n) * CH + c0 + cl;
    *(char4*)(g_Xt0 + tidx) = make_char4(q0[0], q0[1], q0[2], q0[3]);
    *(char4*)(g_Xt1 + tidx) = make_char4(q1[0], q1[1], q1[2], q1[3]);
}

// ---------------- M fp32 -> int8 2-limb + row scales ----------------
__global__ void quantm_kernel() {
    int r = blockIdx.x, b = blockIdx.y;
    const float* row = g_M + ((long)b * CH + r) * CH;
    __shared__ float red[256];
    int tid = threadIdx.x;
    float m = 0.f;
    for (int i = tid; i < CH; i += 256) m = fmaxf(m, fabsf(row[i]));
    red[tid] = m;
    __syncthreads();
    for (int off = 128; off > 0; off >>= 1) {
        if (tid < off) red[tid] = fmaxf(red[tid], red[tid + off]);
        __syncthreads();
    }
    float s = fmaxf(red[0], 1e-20f) * (1.f / 127.f);
    if (tid == 0) g_sM[b * CH + r] = s;
    float inv = 1.f / s;
    long base = ((long)b * CH + r) * CH;
    for (int i = tid; i < CH; i += 256) {
        float q = row[i] * inv;
        q = fminf(fmaxf(q, -127.f), 127.f);
        float a0 = rintf(q);
        float a1 = rintf((q - a0) * 128.f);
        g_M0[base + i] = (int8_t)a0;
        g_M1[base + i] = (int8_t)a1;
    }
}

// ---------------- elementwise split fp32 -> bf16 h/l (weights) ----------------
__global__ void splitw_kernel(const float* __restrict__ src,
                              bf16* __restrict__ oh, bf16* __restrict__ ol) {
    long i = ((long)blockIdx.x * 256 + threadIdx.x) * 4;
    float4 v = *(const float4*)(src + i);
    bf16 h0 = __float2bfloat16(v.x), h1 = __float2bfloat16(v.y);
    bf16 h2 = __float2bfloat16(v.z), h3 = __float2bfloat16(v.w);
    oh[i + 0] = h0; ol[i + 0] = __float2bfloat16(v.x - __bfloat162float(h0));
    oh[i + 1] = h1; ol[i + 1] = __float2bfloat16(v.y - __bfloat162float(h1));
    oh[i + 2] = h2; ol[i + 2] = __float2bfloat16(v.z - __bfloat162float(h2));
    oh[i + 3] = h3; ol[i + 3] = __float2bfloat16(v.w - __bfloat162float(h3));
}

// ---------------- row sums s[b,c] = sum_n X[b,c,n] ----------------
__global__ void rowsum_kernel(const float* __restrict__ x) {
    int c = blockIdx.x, b = blockIdx.y;
    const float* row = x + ((long)b * CH + c) * NPIX;
    float s = 0.f;
    for (int n = threadIdx.x * 4; n < NPIX; n += 256 * 4) {
        float4 v = *(const float4*)(row + n);
        s += v.x + v.y + v.z + v.w;
    }
    __shared__ float red[256];
    red[threadIdx.x] = s;
    __syncthreads();
    for (int off = 128; off > 0; off >>= 1) {
        if (threadIdx.x < off) red[threadIdx.x] += red[threadIdx.x + off];
        __syncthreads();
    }
    if (threadIdx.x == 0) g_s[b * CH + c] = red[0];
}

// ---------------- qs = Wq*s, ks = Wk*s (per batch) ----------------
__global__ void qsks_kernel(const float* __restrict__ wq, const float* __restrict__ wk) {
    int b = blockIdx.x;
    __shared__ float sv[CH];
    for (int i = threadIdx.x; i < CH; i += 256) sv[i] = g_s[b * CH + i];
    __syncthreads();
    for (int o = threadIdx.x; o < CH; o += 256) {
        const float* wr = wq + (long)o * CH;
        const float* kr = wk + (long)o * CH;
        float aq = 0.f, ak = 0.f;
        for (int c = 0; c < CH; c++) { aq += wr[c] * sv[c]; ak += kr[c] * sv[c]; }
        g_qs[b * CH + o] = aq;
        g_ks[b * CH + o] = ak;
    }
}

// ---------------- energy blocks + softmax + abv ----------------
__global__ void __launch_bounds__(256) attn_kernel(
    const float* __restrict__ wk, const float* __restrict__ bq,
    const float* __restrict__ bk, const float* __restrict__ bv)
{
    int h = blockIdx.x, b = blockIdx.y;
    __shared__ float Ts[16][64];
    __shared__ float Ks[16][64];
    __shared__ float Es[64][65];
    __shared__ float qv[64], kvv[64], bqv[64], bkv[64], bvv[64];
    int tid = threadIdx.x;
    if (tid < 64) {
        qv[tid]  = g_qs[b * CH + h * HD + tid];
        kvv[tid] = g_ks[b * CH + h * HD + tid];
        bqv[tid] = bq[h * HD + tid];
        bkv[tid] = bk[h * HD + tid];
        bvv[tid] = bv[h * HD + tid];
    }
    const float* Tb = g_T + ((long)b * CH + h * HD) * CH;
    const float* Kb = wk + (long)(h * HD) * CH;
    int lrow = tid >> 2;
    int lcol = (tid & 3) * 4;
    int tx = tid & 15, ty = tid >> 4;
    float acc[4][4];
    #pragma unroll
    for (int i = 0; i < 4; i++)
        #pragma unroll
        for (int j = 0; j < 4; j++) acc[i][j] = 0.f;

    for (int a0 = 0; a0 < CH; a0 += 16) {
        float4 tv = *(const float4*)(Tb + (long)lrow * CH + a0 + lcol);
        Ts[lcol + 0][lrow] = tv.x; Ts[lcol + 1][lrow] = tv.y;
        Ts[lcol + 2][lrow] = tv.z; Ts[lcol + 3][lrow] = tv.w;
        float4 kv4 = *(const float4*)(Kb + (long)lrow * CH + a0 + lcol);
        Ks[lcol + 0][lrow] = kv4.x; Ks[lcol + 1][lrow] = kv4.y;
        Ks[lcol + 2][lrow] = kv4.z; Ks[lcol + 3][lrow] = kv4.w;
        __syncthreads();
        #pragma unroll
        for (int kk = 0; kk < 16; kk++) {
            float ra[4], rb[4];
            *(float4*)&ra[0] = *(const float4*)&Ts[kk][ty * 4];
            *(float4*)&rb[0] = *(const float4*)&Ks[kk][tx * 4];
            #pragma unroll
            for (int i = 0; i < 4; i++)
                #pragma unroll
                for (int j = 0; j < 4; j++)
                    acc[i][j] += ra[i] * rb[j];
        }
        __syncthreads();
    }
    #pragma unroll
    for (int i = 0; i < 4; i++) {
        int gi = ty * 4 + i;
        #pragma unroll
        for (int j = 0; j < 4; j++) {
            int gj = tx * 4 + j;
            float e = acc[i][j] + qv[gi] * bkv[gj] + bqv[gi] * kvv[gj]
                      + 4096.f * bqv[gi] * bkv[gj];
            Es[gi][gj] = e * ATT_SCALE;
        }
    }
    __syncthreads();
    if (tid < 64) {
        int i = tid;
        float m = -1e30f;
        for (int j = 0; j < 64; j++) m = fmaxf(m, Es[i][j]);
        float sum = 0.f;
        for (int j = 0; j < 64; j++) {
            float ex = expf(Es[i][j] - m);
            Es[i][j] = ex;
            sum += ex;
        }
        float inv = 1.f / sum;
        float ab = 0.f;
        float* Arow = g_A + (((long)b * NH + h) * HD + i) * HD;
        for (int j = 0; j < 64; j++) {
            float a = Es[i][j] * inv;
            Arow[j] = a;
            ab += a * bvv[j];
        }
        g_abv[b * CH + h * HD + i] = ab;
    }
}

// ---------------- Pt = (A_bd * Wv)^T, written as bf16 hi/lo [c][r] ----------------
__global__ void __launch_bounds__(256) pk_kernel(const float* __restrict__ wv) {
    int h = blockIdx.x, b = blockIdx.y;
    __shared__ float Ash[64][64];
    __shared__ float Bv[64][64];
    int tid = threadIdx.x;
    const float* Ab = g_A + ((long)b * NH + h) * HD * HD;
    for (int r = tid; r < 64 * 16; r += 256) {
        int i = r >> 4, q = (r & 15) * 4;
        float4 v = *(const float4*)(Ab + i * 64 + q);
        Ash[q + 0][i] = v.x; Ash[q + 1][i] = v.y;
        Ash[q + 2][i] = v.z; Ash[q + 3][i] = v.w;
    }
    int tx = tid & 15, ty = tid >> 4;
    for (int cc = 0; cc < CH; cc += 64) {
        __syncthreads();
        for (int r = tid; r < 64 * 16; r += 256) {
            int j = r >> 4, q = (r & 15) * 4;
            *(float4*)&Bv[j][q] = *(const float4*)(wv + (long)(h * HD + j) * CH + cc + q);
        }
        __syncthreads();
        float acc[4][4];
        #pragma unroll
        for (int i = 0; i < 4; i++)
            #pragma unroll
            for (int j = 0; j < 4; j++) acc[i][j] = 0.f;
        #pragma unroll 8
        for (int j = 0; j < 64; j++) {
            float ra[4], rb[4];
            *(float4*)&ra[0] = *(const float4*)&Ash[j][ty * 4];
            *(float4*)&rb[0] = *(const float4*)&Bv[j][tx * 4];
            #pragma unroll
            for (int i = 0; i < 4; i++)
                #pragma unroll
                for (int u = 0; u < 4; u++)
                    acc[i][u] += ra[i] * rb[u];
        }
        #pragma unroll
        for (int u = 0; u < 4; u++) {
            int c = cc + tx * 4 + u;
            long base = ((long)b * CH + c) * CH + h * HD + ty * 4;
            float v0 = acc[0][u], v1 = acc[1][u], v2 = acc[2][u], v3 = acc[3][u];
            bf16 h0 = __float2bfloat16(v0), h1 = __float2bfloat16(v1);
            bf16 h2 = __float2bfloat16(v2), h3 = __float2bfloat16(v3);
            __nv_bfloat162 a0, a1, b0, b1;
            a0.x = h0; a0.y = h1; a1.x = h2; a1.y = h3;
            b0.x = __float2bfloat16(v0 - __bfloat162float(h0));
            b0.y = __float2bfloat16(v1 - __bfloat162float(h1));
            b1.x = __float2bfloat16(v2 - __bfloat162float(h2));
            b1.y = __float2bfloat16(v3 - __bfloat162float(h3));
            *(__nv_bfloat162*)(g_Pth + base)     = a0;
            *(__nv_bfloat162*)(g_Pth + base + 2) = a1;
            *(__nv_bfloat162*)(g_Ptl + base)     = b0;
            *(__nv_bfloat162*)(g_Ptl + base + 2) = b1;
        }
    }
}

// ---------------- c[b] = Wo * abv[b] + bo ----------------
__global__ void cvec_kernel(const float* __restrict__ wo, const float* __restrict__ bo) {
    int b = blockIdx.x;
    __shared__ float sv[CH];
    for (int i = threadIdx.x; i < CH; i += 256) sv[i] = g_abv[b * CH + i];
    __syncthreads();
    for (int o = threadIdx.x; o < CH; o += 256) {
        const float* wr = wo + (long)o * CH;
        float sum = bo[o];
        for (int c = 0; c < CH; c++) sum += wr[c] * sv[c];
        g_c[b * CH + o] = sum;
    }
}

// ---------------- launch ----------------
extern "C" void kernel_launch(void* const* d_in, const int* in_sizes, int n_in,
                              void* d_out, int out_size) {
    const float* x  = (const float*)d_in[0];
    const float* wq = (const float*)d_in[1];
    const float* bq = (const float*)d_in[2];
    const float* wk = (const float*)d_in[3];
    const float* bk = (const float*)d_in[4];
    const float* wv = (const float*)d_in[5];
    const float* bv = (const float*)d_in[6];
    const float* wo = (const float*)d_in[7];
    const float* bo = (const float*)d_in[8];
    float* y = (float*)d_out;

    float *pT, *pM, *pc, *psM, *psXt;
    bf16 *pXh, *pXl, *pGh, *pGl, *pPth, *pPtl;
    bf16 *pWqh, *pWql, *pWoh, *pWol;
    int8_t *pXt0, *pXt1, *pM0, *pM1;
    cudaGetSymbolAddress((void**)&pT,  g_T);
    cudaGetSymbolAddress((void**)&pM,  g_M);
    cudaGetSymbolAddress((void**)&pc,  g_c);
    cudaGetSymbolAddress((void**)&psM, g_sM);
    cudaGetSymbolAddress((void**)&psXt, g_sXt);
    cudaGetSymbolAddress((void**)&pXh, g_Xh);
    cudaGetSymbolAddress((void**)&pXl, g_Xl);
    cudaGetSymbolAddress((void**)&pGh, g_Gh);
    cudaGetSymbolAddress((void**)&pGl, g_Gl);
    cudaGetSymbolAddress((void**)&pPth, g_Pth);
    cudaGetSymbolAddress((void**)&pPtl, g_Ptl);
    cudaGetSymbolAddress((void**)&pWqh, g_Wqh);
    cudaGetSymbolAddress((void**)&pWql, g_Wql);
    cudaGetSymbolAddress((void**)&pWoh, g_Woh);
    cudaGetSymbolAddress((void**)&pWol, g_Wol);
    cudaGetSymbolAddress((void**)&pXt0, g_Xt0);
    cudaGetSymbolAddress((void**)&pXt1, g_Xt1);
    cudaGetSymbolAddress((void**)&pM0, g_M0);
    cudaGetSymbolAddress((void**)&pM1, g_M1);

    cudaFuncSetAttribute((const void*)mma_gemm<2, true>,
                         cudaFuncAttributeMaxDynamicSharedMemorySize, MMA_SMEM);
    cudaFuncSetAttribute((const void*)mma_gemm<0, false>,
                         cudaFuncAttributeMaxDynamicSharedMemorySize, MMA_SMEM);
    cudaFuncSetAttribute((const void*)mma_gemm_i8,
                         cudaFuncAttributeMaxDynamicSharedMemorySize, MMA_SMEM);

    // 1. column max scales, then split x (bf16 natural + int8 transposed)
    colmax_kernel<<<dim3(NPIX / 256, BATCH), 256>>>(x);
    splitx_kernel<<<dim3(NPIX / 32, CH / 32, BATCH), dim3(32, 8)>>>(x);

    // 2. row sums + weight splits
    rowsum_kernel<<<dim3(CH, BATCH), 256>>>(x);
    splitw_kernel<<<(CH * CH) / 1024, 256>>>(wq, pWqh, pWql);
    splitw_kernel<<<(CH * CH) / 1024, 256>>>(wo, pWoh, pWol);

    // 3. Gram (symmetric): 21 lower-triangle tiles, mirrored.  K = 4096
    mma_gemm<2, true><<<dim3(21, 1, BATCH), 256, MMA_SMEM>>>(
        pXh, pXl, pXh, pXl, nullptr, pGh, pGl,
        NPIX, CH, (long)CH * NPIX, (long)CH * NPIX, (long)CH * CH);

    // 4. qs/ks
    qsks_kernel<<<BATCH, 256>>>(wq, wk);

    // 5. T[b] = Wq * G[b]  (G symmetric -> row-major == K-major).  K = 768
    mma_gemm<0, false><<<dim3(6, 6, BATCH), 256, MMA_SMEM>>>(
        pWqh, pWql, pGh, pGl, pT, nullptr, nullptr,
        CH, CH, 0L, (long)CH * CH, (long)CH * CH);

    // 6. energy blocks + softmax + abv
    attn_kernel<<<dim3(NH, BATCH), 256>>>(wk, bq, bk, bv);

    // 7. Pt[b] = (A_bd * Wv)^T  -> bf16 h/l
    pk_kernel<<<dim3(NH, BATCH), 256>>>(wv);

    // 8. c[b] = Wo * abv + bo
    cvec_kernel<<<BATCH, 256>>>(wo, bo);

    // 9. M[b] = Wo * P[b]  (fp32 out).  K = 768
    mma_gemm<0, false><<<dim3(6, 6, BATCH), 256, MMA_SMEM>>>(
        pWoh, pWol, pPth, pPtl, pM, nullptr, nullptr,
        CH, CH, 0L, (long)CH * CH, (long)CH * CH);

    // 10. quantize M -> int8 2-limb
    quantm_kernel<<<dim3(CH, BATCH), 256>>>();

    // 11. y[b] = M[b] * X[b] + c[b]   (int8 2-limb IMMA).  K = 768
    mma_gemm_i8<<<dim3(NPIX / 128, 6, BATCH), 256, MMA_SMEM>>>(
        pM0, pM1, pXt0, pXt1, psM, psXt, y, pc,
        CH, NPIX, (long)CH * CH, (long)NPIX * CH, (long)CH * NPIX);
}

// round 7
// speedup vs baseline: 2.1975x; 1.0081x over previous
#include <cuda_runtime.h>
#include <cuda_bf16.h>
#include <math.h>
#include <stdint.h>

#define BATCH 16
#define CH    768
#define NPIX  4096
#define NH    12
#define HD    64
#define ATT_SCALE 0.125f   // HD^-0.5

typedef __nv_bfloat16 bf16;

// ---------------- scratch (device globals; no runtime allocation) ----------------
__device__ float g_T [BATCH * CH * CH];       // T = Wq * G
__device__ float g_M [BATCH * CH * CH];       // M = Wo * P (fp32, quantized after)
__device__ float g_Pt[BATCH * CH * CH];       // (A_bd * Wv)^T fp32 [c][r]
__device__ float g_GP[2L * BATCH * CH * CH];  // Gram split-K partials
__device__ float g_A[BATCH * NH * HD * HD];
__device__ float g_s[BATCH * CH];
__device__ float g_qs[BATCH * CH];
__device__ float g_ks[BATCH * CH];
__device__ float g_abv[BATCH * CH];
__device__ float g_c[BATCH * CH];
__device__ float g_sXt[BATCH * NPIX];
__device__ float g_sM [BATCH * CH];
__device__ float g_sPt[BATCH * CH];
__device__ float g_sWo[CH];

__device__ __align__(16) bf16 g_Xh [BATCH * CH * NPIX];
__device__ __align__(16) bf16 g_Xl [BATCH * CH * NPIX];
__device__ __align__(16) bf16 g_Gh [BATCH * CH * CH];
__device__ __align__(16) bf16 g_Gl [BATCH * CH * CH];
__device__ __align__(16) bf16 g_Wqh[CH * CH];
__device__ __align__(16) bf16 g_Wql[CH * CH];

__device__ __align__(16) int8_t g_Xt0[BATCH * NPIX * CH];
__device__ __align__(16) int8_t g_Xt1[BATCH * NPIX * CH];
__device__ __align__(16) int8_t g_M0 [BATCH * CH * CH];
__device__ __align__(16) int8_t g_M1 [BATCH * CH * CH];
__device__ __align__(16) int8_t g_Pt0[BATCH * CH * CH];
__device__ __align__(16) int8_t g_Pt1[BATCH * CH * CH];
__device__ __align__(16) int8_t g_Wo0[CH * CH];
__device__ __align__(16) int8_t g_Wo1[CH * CH];

// ---------------- asm helpers (sm_80-compatible only) ----------------
__device__ __forceinline__ uint32_t smem_u32(const void* p) {
    uint32_t a;
    asm("{ .reg .u64 t; cvta.to.shared.u64 t, %1; cvt.u32.u64 %0, t; }" : "=r"(a) : "l"(p));
    return a;
}
__device__ __forceinline__ void ldsm4(uint32_t* r, uint32_t a) {
    asm volatile("ldmatrix.sync.aligned.m8n8.x4.shared.b16 {%0,%1,%2,%3}, [%4];"
                 : "=r"(r[0]), "=r"(r[1]), "=r"(r[2]), "=r"(r[3]) : "r"(a));
}
__device__ __forceinline__ void mma_bf16(float* c, const uint32_t* a, const uint32_t* b) {
    asm volatile(
        "mma.sync.aligned.m16n8k16.row.col.f32.bf16.bf16.f32 "
        "{%0,%1,%2,%3}, {%4,%5,%6,%7}, {%8,%9}, {%0,%1,%2,%3};"
        : "+f"(c[0]), "+f"(c[1]), "+f"(c[2]), "+f"(c[3])
        : "r"(a[0]), "r"(a[1]), "r"(a[2]), "r"(a[3]), "r"(b[0]), "r"(b[1]));
}
__device__ __forceinline__ void mma_s8(int* c, const uint32_t* a, const uint32_t* b) {
    asm volatile(
        "mma.sync.aligned.m16n8k32.row.col.s32.s8.s8.s32 "
        "{%0,%1,%2,%3}, {%4,%5,%6,%7}, {%8,%9}, {%0,%1,%2,%3};"
        : "+r"(c[0]), "+r"(c[1]), "+r"(c[2]), "+r"(c[3])
        : "r"(a[0]), "r"(a[1]), "r"(a[2]), "r"(a[3]), "r"(b[0]), "r"(b[1]));
}
#define CP_A16(dst, src) asm volatile( \
    "cp.async.cg.shared.global [%0], [%1], 16;" :: "r"(dst), "l"(src))
#define CP_COMMIT() asm volatile("cp.async.commit_group;" ::: "memory")
#define CP_WAIT0()  asm volatile("cp.async.wait_group 0;" ::: "memory")
#define CP_WAIT1()  asm volatile("cp.async.wait_group 1;" ::: "memory")
#define CP_WAIT2()  asm volatile("cp.async.wait_group 2;" ::: "memory")

// ---------------- smem geometry (3-stage pipeline) ----------------
#define ROWPITCH 80
#define ARR_BYTES 10240
#define STAGE_BYTES (4 * ARR_BYTES)          // 40960
#define MMA_SMEM (3 * STAGE_BYTES)           // 122880

// =================================================================
// 3-term bf16 GEMM:  C(128x128) = Ah*Bh^T + Ah*Bl^T + Al*Bh^T  (fp32 out)
// MIRROR: lower-triangle tile decode + split-K partial output.
// =================================================================
template<bool MIRROR>
__global__ void __launch_bounds__(256) mma_gemm(
    const bf16* __restrict__ Ahg, const bf16* __restrict__ Alg,
    const bf16* __restrict__ Bhg, const bf16* __restrict__ Blg,
    float* __restrict__ Cf,
    int Kdim, int Ksub, int ldc, long sA, long sB, long sC)
{
    extern __shared__ char smem[];
    uint32_t sbase = smem_u32(smem);
    int tid = threadIdx.x;
    int lane = tid & 31, wid = tid >> 5;
    int b = blockIdx.z;
    int m0, n0, kbase = 0;
    long outb;
    if (MIRROR) {
        int t = blockIdx.x, bi = 0;
        while ((bi + 1) * (bi + 2) / 2 <= t) bi++;
        int bj = t - bi * (bi + 1) / 2;
        m0 = bi * 128; n0 = bj * 128;
        kbase = blockIdx.y * Ksub;
        outb = ((long)blockIdx.y * BATCH + b) * sC;
    } else {
        m0 = blockIdx.y * 128; n0 = blockIdx.x * 128;
        outb = (long)b * sC;
    }
    int m_warp = (wid & 3) * 32, n_warp = (wid >> 2) * 64;

    const bf16* pAh = Ahg + b * sA + (long)m0 * Kdim + kbase;
    const bf16* pAl = Alg + b * sA + (long)m0 * Kdim + kbase;
    const bf16* pBh = Bhg + b * sB + (long)n0 * Kdim + kbase;
    const bf16* pBl = Blg + b * sB + (long)n0 * Kdim + kbase;

    uint32_t a_off = (uint32_t)((m_warp + (lane & 15)) * ROWPITCH + (lane >> 4) * 16);
    uint32_t b_off = (uint32_t)((n_warp + (lane & 7) + ((lane >> 4) & 1) * 8) * ROWPITCH
                                + ((lane >> 3) & 1) * 16);

    float acc[2][8][4];
    #pragma unroll
    for (int mt = 0; mt < 2; mt++)
        #pragma unroll
        for (int nt = 0; nt < 8; nt++)
            #pragma unroll
            for (int q = 0; q < 4; q++) acc[mt][nt][q] = 0.f;

    int nch = Ksub >> 5;

    auto load_stage = [&](int stage, int k0) {
        uint32_t st = sbase + stage * STAGE_BYTES;
        #pragma unroll
        for (int it = 0; it < 2; it++) {
            int q = tid + it * 256;
            int r = q >> 2, c = q & 3;
            uint32_t off = r * ROWPITCH + c * 16;
            long gofs = ((long)r * Kdim + k0 + c * 8);
            CP_A16(st + 0 * ARR_BYTES + off, (const char*)(pAh + gofs));
            CP_A16(st + 1 * ARR_BYTES + off, (const char*)(pAl + gofs));
            CP_A16(st + 2 * ARR_BYTES + off, (const char*)(pBh + gofs));
            CP_A16(st + 3 * ARR_BYTES + off, (const char*)(pBl + gofs));
        }
        CP_COMMIT();
    };

    load_stage(0, 0);
    load_stage(1, 32);

    for (int ic = 0; ic < nch; ic++) {
        if (ic + 2 < nch) { load_stage((ic + 2) % 3, (ic + 2) * 32); CP_WAIT2(); }
        else if (ic + 1 < nch) { CP_WAIT1(); }
        else { CP_WAIT0(); }
        __syncthreads();

        uint32_t st = sbase + (ic % 3) * STAGE_BYTES;
        #pragma unroll
        for (int kk = 0; kk < 2; kk++) {
            uint32_t ah[2][4], al[2][4];
            ldsm4(ah[0], st + 0 * ARR_BYTES + a_off + kk * 32);
            ldsm4(ah[1], st + 0 * ARR_BYTES + a_off + 16 * ROWPITCH + kk * 32);
            ldsm4(al[0], st + 1 * ARR_BYTES + a_off + kk * 32);
            ldsm4(al[1], st + 1 * ARR_BYTES + a_off + 16 * ROWPITCH + kk * 32);
            #pragma unroll
            for (int ntp = 0; ntp < 4; ntp++) {
                uint32_t bh[4], bl[4];
                ldsm4(bh, st + 2 * ARR_BYTES + b_off + ntp * 16 * ROWPITCH + kk * 32);
                ldsm4(bl, st + 3 * ARR_BYTES + b_off + ntp * 16 * ROWPITCH + kk * 32);
                #pragma unroll
                for (int mt = 0; mt < 2; mt++) {
                    mma_bf16(acc[mt][2 * ntp],     ah[mt], bh);
                    mma_bf16(acc[mt][2 * ntp],     ah[mt], bl);
                    mma_bf16(acc[mt][2 * ntp],     al[mt], bh);
                    mma_bf16(acc[mt][2 * ntp + 1], ah[mt], bh + 2);
                    mma_bf16(acc[mt][2 * ntp + 1], ah[mt], bl + 2);
                    mma_bf16(acc[mt][2 * ntp + 1], al[mt], bh + 2);
                }
            }
        }
        __syncthreads();
    }

    #pragma unroll
    for (int mt = 0; mt < 2; mt++) {
        #pragma unroll
        for (int hh = 0; hh < 2; hh++) {
            int rg = m0 + m_warp + mt * 16 + (lane >> 2) + hh * 8;
            long rowoff = outb + (long)rg * ldc;
            #pragma unroll
            for (int nt = 0; nt < 8; nt++) {
                int cg = n0 + n_warp + nt * 8 + (lane & 3) * 2;
                *(float2*)(Cf + rowoff + cg) =
                    make_float2(acc[mt][nt][hh * 2 + 0], acc[mt][nt][hh * 2 + 1]);
            }
        }
    }
}

// ---------------- Gram reduce: sum split-K partials, bf16 h/l split + mirror ----------------
__global__ void gram_reduce() {
    int t = blockIdx.x, b = blockIdx.y;
    int bi = 0;
    while ((bi + 1) * (bi + 2) / 2 <= t) bi++;
    int bj = t - bi * (bi + 1) / 2;
    long mb = (long)b * CH * CH;
    const float* P0 = g_GP + mb;
    const float* P1 = g_GP + (long)BATCH * CH * CH + mb;
    bool mir = (bi != bj);
    for (int e = threadIdx.x; e < 16384; e += 256) {
        int r = bi * 128 + (e >> 7);
        int c = bj * 128 + (e & 127);
        long o = (long)r * CH + c;
        float v = P0[o] + P1[o];
        bf16 h = __float2bfloat16(v);
        bf16 l = __float2bfloat16(v - __bfloat162float(h));
        g_Gh[mb + o] = h;
        g_Gl[mb + o] = l;
        if (mir) {
            long ot = (long)c * CH + r;
            g_Gh[mb + ot] = h;
            g_Gl[mb + ot] = l;
        }
    }
}

// =================================================================
// int8 2-limb GEMM:  C = sA[r]*sB[c]*(A0B0 + (A0B1+A1B0)/128) (+bias[r])
// =================================================================
__global__ void __launch_bounds__(256) mma_gemm_i8(
    const int8_t* __restrict__ A0g, const int8_t* __restrict__ A1g,
    const int8_t* __restrict__ B0g, const int8_t* __restrict__ B1g,
    const float* __restrict__ sAg, long sAs,
    const float* __restrict__ sBg, long sBs,
    float* __restrict__ Cf, const float* __restrict__ biasg,
    int Kdim, int ldc, long sA, long sB, long sC)
{
    extern __shared__ char smem[];
    __shared__ float snv[128];
    uint32_t sbase = smem_u32(smem);
    int tid = threadIdx.x;
    int lane = tid & 31, wid = tid >> 5;
    int b = blockIdx.z;
    int m0 = blockIdx.y * 128, n0 = blockIdx.x * 128;
    int m_warp = (wid & 3) * 32, n_warp = (wid >> 2) * 64;

    const int8_t* pA0 = A0g + b * sA + (long)m0 * Kdim;
    const int8_t* pA1 = A1g + b * sA + (long)m0 * Kdim;
    const int8_t* pB0 = B0g + b * sB + (long)n0 * Kdim;
    const int8_t* pB1 = B1g + b * sB + (long)n0 * Kdim;

    if (tid < 128) snv[tid] = sBg[b * sBs + n0 + tid];

    uint32_t a_off = (uint32_t)((m_warp + (lane & 15)) * ROWPITCH + (lane >> 4) * 16);
    uint32_t b_off = (uint32_t)((n_warp + (lane & 7) + ((lane >> 4) & 1) * 8) * ROWPITCH
                                + ((lane >> 3) & 1) * 16);

    int acc0[2][8][4], acc1[2][8][4];
    #pragma unroll
    for (int mt = 0; mt < 2; mt++)
        #pragma unroll
        for (int nt = 0; nt < 8; nt++)
            #pragma unroll
            for (int q = 0; q < 4; q++) { acc0[mt][nt][q] = 0; acc1[mt][nt][q] = 0; }

    int nch = Kdim >> 6;

    auto load_stage = [&](int stage, int k0) {
        uint32_t st = sbase + stage * STAGE_BYTES;
        #pragma unroll
        for (int it = 0; it < 2; it++) {
            int q = tid + it * 256;
            int r = q >> 2, c = q & 3;
            uint32_t off = r * ROWPITCH + c * 16;
            long gofs = ((long)r * Kdim + k0 + c * 16);
            CP_A16(st + 0 * ARR_BYTES + off, (const char*)(pA0 + gofs));
            CP_A16(st + 1 * ARR_BYTES + off, (const char*)(pA1 + gofs));
            CP_A16(st + 2 * ARR_BYTES + off, (const char*)(pB0 + gofs));
            CP_A16(st + 3 * ARR_BYTES + off, (const char*)(pB1 + gofs));
        }
        CP_COMMIT();
    };

    load_stage(0, 0);
    load_stage(1, 64);

    for (int ic = 0; ic < nch; ic++) {
        if (ic + 2 < nch) { load_stage((ic + 2) % 3, (ic + 2) * 64); CP_WAIT2(); }
        else if (ic + 1 < nch) { CP_WAIT1(); }
        else { CP_WAIT0(); }
        __syncthreads();

        uint32_t st = sbase + (ic % 3) * STAGE_BYTES;
        #pragma unroll
        for (int kk = 0; kk < 2; kk++) {
            uint32_t a0[2][4], a1[2][4];
            ldsm4(a0[0], st + 0 * ARR_BYTES + a_off + kk * 32);
            ldsm4(a0[1], st + 0 * ARR_BYTES + a_off + 16 * ROWPITCH + kk * 32);
            ldsm4(a1[0], st + 1 * ARR_BYTES + a_off + kk * 32);
            ldsm4(a1[1], st + 1 * ARR_BYTES + a_off + 16 * ROWPITCH + kk * 32);
            #pragma unroll
            for (int ntp = 0; ntp < 4; ntp++) {
                uint32_t b0[4], b1[4];
                ldsm4(b0, st + 2 * ARR_BYTES + b_off + ntp * 16 * ROWPITCH + kk * 32);
                ldsm4(b1, st + 3 * ARR_BYTES + b_off + ntp * 16 * ROWPITCH + kk * 32);
                #pragma unroll
                for (int mt = 0; mt < 2; mt++) {
                    mma_s8(acc0[mt][2 * ntp],     a0[mt], b0);
                    mma_s8(acc1[mt][2 * ntp],     a0[mt], b1);
                    mma_s8(acc1[mt][2 * ntp],     a1[mt], b0);
                    mma_s8(acc0[mt][2 * ntp + 1], a0[mt], b0 + 2);
                    mma_s8(acc1[mt][2 * ntp + 1], a0[mt], b1 + 2);
                    mma_s8(acc1[mt][2 * ntp + 1], a1[mt], b0 + 2);
                }
            }
        }
        __syncthreads();
    }

    #pragma unroll
    for (int mt = 0; mt < 2; mt++) {
        #pragma unroll
        for (int hh = 0; hh < 2; hh++) {
            int rg = m0 + m_warp + mt * 16 + (lane >> 2) + hh * 8;
            float sm = sAg[b * sAs + rg];
            float bias = biasg ? biasg[b * CH + rg] : 0.f;
            long rowoff = b * sC + (long)rg * ldc;
            #pragma unroll
            for (int nt = 0; nt < 8; nt++) {
                int cg = n0 + n_warp + nt * 8 + (lane & 3) * 2;
                int ci = cg - n0;
                float v0 = sm * snv[ci]     * ((float)acc0[mt][nt][hh * 2 + 0]
                           + (float)acc1[mt][nt][hh * 2 + 0] * 0.0078125f) + bias;
                float v1 = sm * snv[ci + 1] * ((float)acc0[mt][nt][hh * 2 + 1]
                           + (float)acc1[mt][nt][hh * 2 + 1] * 0.0078125f) + bias;
                *(float2*)(Cf + rowoff + cg) = make_float2(v0, v1);
            }
        }
    }
}

// ---------------- generic per-row int8 2-limb quantizer (row length CH) ----------------
__global__ void quant_rows(const float* __restrict__ src,
                           int8_t* __restrict__ o0, int8_t* __restrict__ o1,
                           float* __restrict__ sout) {
    long row = (long)blockIdx.y * gridDim.x + blockIdx.x;
    const float* p = src + row * CH;
    __shared__ float red[256];
    int tid = threadIdx.x;
    float m = 0.f;
    for (int i = tid; i < CH; i += 256) m = fmaxf(m, fabsf(p[i]));
    red[tid] = m;
    __syncthreads();
    for (int off = 128; off > 0; off >>= 1) {
        if (tid < off) red[tid] = fmaxf(red[tid], red[tid + off]);
        __syncthreads();
    }
    float s = fmaxf(red[0], 1e-20f) * (1.f / 127.f);
    if (tid == 0) sout[row] = s;
    float inv = 1.f / s;
    for (int i = tid; i < CH; i += 256) {
        float q = p[i] * inv;
        q = fminf(fmaxf(q, -127.f), 127.f);
        float a0 = rintf(q);
        float a1 = rintf((q - a0) * 128.f);
        o0[row * CH + i] = (int8_t)a0;
        o1[row * CH + i] = (int8_t)a1;
    }
}

// ---------------- column max scales ----------------
__global__ void colmax_kernel(const float* __restrict__ x) {
    int b = blockIdx.y;
    int n = blockIdx.x * 256 + threadIdx.x;
    const float* p = x + (long)b * CH * NPIX + n;
    float m0 = 0.f, m1 = 0.f, m2 = 0.f, m3 = 0.f;
    #pragma unroll 4
    for (int r = 0; r < CH; r += 4) {
        m0 = fmaxf(m0, fabsf(p[(long)(r + 0) * NPIX]));
        m1 = fmaxf(m1, fabsf(p[(long)(r + 1) * NPIX]));
        m2 = fmaxf(m2, fabsf(p[(long)(r + 2) * NPIX]));
        m3 = fmaxf(m3, fabsf(p[(long)(r + 3) * NPIX]));
    }
    float m = fmaxf(fmaxf(m0, m1), fmaxf(m2, m3));
    g_sXt[b * NPIX + n] = fmaxf(m, 1e-20f) * (1.f / 127.f);
}

// ---------------- x -> bf16 h/l (natural) + int8 2-limb (transposed) ----------------
__global__ void splitx_kernel(const float* __restrict__ x) {
    __shared__ float xt[32][33];
    int b = blockIdx.z;
    int n0 = blockIdx.x * 32, c0 = blockIdx.y * 32;
    int tx = threadIdx.x, ty = threadIdx.y;
    const float* xb = x + (long)b * CH * NPIX;
    #pragma unroll
    for (int k = 0; k < 4; k++) {
        int c = c0 + ty + k * 8;
        float v = xb[(long)c * NPIX + n0 + tx];
        xt[ty + k * 8][tx] = v;
        bf16 h = __float2bfloat16(v);
        bf16 l = __float2bfloat16(v - __bfloat162float(h));
        long idx = ((long)b * CH + c) * NPIX + n0 + tx;
        g_Xh[idx] = h;
        g_Xl[idx] = l;
    }
    __syncthreads();
    int tid = ty * 32 + tx;
    int nl = tid >> 3;
    int cl = (tid & 7) * 4;
    int n = n0 + nl;
    float inv = 1.f / g_sXt[b * NPIX + n];
    char q0[4], q1[4];
    #pragma unroll
    for (int j = 0; j < 4; j++) {
        float q = xt[cl + j][nl] * inv;
        q = fminf(fmaxf(q, -127.f), 127.f);
        float a0 = rintf(q);
        float a1 = rintf((q - a0) * 128.f);
        q0[j] = (char)a0;
        q1[j] = (char)a1;
    }
    long tidx = ((long)b * NPIX + n) * CH + c0 + cl;
    *(char4*)(g_Xt0 + tidx) = make_char4(q0[0], q0[1], q0[2], q0[3]);
    *(char4*)(g_Xt1 + tidx) = make_char4(q1[0], q1[1], q1[2], q1[3]);
}

// ---------------- elementwise split fp32 -> bf16 h/l (wq) ----------------
__global__ void splitw_kernel(const float* __restrict__ src,
                              bf16* __restrict__ oh, bf16* __restrict__ ol) {
    long i = ((long)blockIdx.x * 256 + threadIdx.x) * 4;
    float4 v = *(const float4*)(src + i);
    bf16 h0 = __float2bfloat16(v.x), h1 = __float2bfloat16(v.y);
    bf16 h2 = __float2bfloat16(v.z), h3 = __float2bfloat16(v.w);
    oh[i + 0] = h0; ol[i + 0] = __float2bfloat16(v.x - __bfloat162float(h0));
    oh[i + 1] = h1; ol[i + 1] = __float2bfloat16(v.y - __bfloat162float(h1));
    oh[i + 2] = h2; ol[i + 2] = __float2bfloat16(v.z - __bfloat162float(h2));
    oh[i + 3] = h3; ol[i + 3] = __float2bfloat16(v.w - __bfloat162float(h3));
}

// ---------------- row sums ----------------
__global__ void rowsum_kernel(const float* __restrict__ x) {
    int c = blockIdx.x, b = blockIdx.y;
    const float* row = x + ((long)b * CH + c) * NPIX;
    float s = 0.f;
    for (int n = threadIdx.x * 4; n < NPIX; n += 256 * 4) {
        float4 v = *(const float4*)(row + n);
        s += v.x + v.y + v.z + v.w;
    }
    __shared__ float red[256];
    red[threadIdx.x] = s;
    __syncthreads();
    for (int off = 128; off > 0; off >>= 1) {
        if (threadIdx.x < off) red[threadIdx.x] += red[threadIdx.x + off];
        __syncthreads();
    }
    if (threadIdx.x == 0) g_s[b * CH + c] = red[0];
}

// ---------------- qs = Wq*s, ks = Wk*s ----------------
__global__ void qsks_kernel(const float* __restrict__ wq, const float* __restrict__ wk) {
    int b = blockIdx.x;
    __shared__ float sv[CH];
    for (int i = threadIdx.x; i < CH; i += 256) sv[i] = g_s[b * CH + i];
    __syncthreads();
    for (int o = threadIdx.x; o < CH; o += 256) {
        const float* wr = wq + (long)o * CH;
        const float* kr = wk + (long)o * CH;
        float aq = 0.f, ak = 0.f;
        for (int c = 0; c < CH; c++) { aq += wr[c] * sv[c]; ak += kr[c] * sv[c]; }
        g_qs[b * CH + o] = aq;
        g_ks[b * CH + o] = ak;
    }
}

// ---------------- energy blocks + softmax + abv ----------------
__global__ void __launch_bounds__(256) attn_kernel(
    const float* __restrict__ wk, const float* __restrict__ bq,
    const float* __restrict__ bk, const float* __restrict__ bv)
{
    int h = blockIdx.x, b = blockIdx.y;
    __shared__ float Ts[16][64];
    __shared__ float Ks[16][64];
    __shared__ float Es[64][65];
    __shared__ float qv[64], kvv[64], bqv[64], bkv[64], bvv[64];
    int tid = threadIdx.x;
    if (tid < 64) {
        qv[tid]  = g_qs[b * CH + h * HD + tid];
        kvv[tid] = g_ks[b * CH + h * HD + tid];
        bqv[tid] = bq[h * HD + tid];
        bkv[tid] = bk[h * HD + tid];
        bvv[tid] = bv[h * HD + tid];
    }
    const float* Tb = g_T + ((long)b * CH + h * HD) * CH;
    const float* Kb = wk + (long)(h * HD) * CH;
    int lrow = tid >> 2;
    int lcol = (tid & 3) * 4;
    int tx = tid & 15, ty = tid >> 4;
    float acc[4][4];
    #pragma unroll
    for (int i = 0; i < 4; i++)
        #pragma unroll
        for (int j = 0; j < 4; j++) acc[i][j] = 0.f;

    for (int a0 = 0; a0 < CH; a0 += 16) {
        float4 tv = *(const float4*)(Tb + (long)lrow * CH + a0 + lcol);
        Ts[lcol + 0][lrow] = tv.x; Ts[lcol + 1][lrow] = tv.y;
        Ts[lcol + 2][lrow] = tv.z; Ts[lcol + 3][lrow] = tv.w;
        float4 kv4 = *(const float4*)(Kb + (long)lrow * CH + a0 + lcol);
        Ks[lcol + 0][lrow] = kv4.x; Ks[lcol + 1][lrow] = kv4.y;
        Ks[lcol + 2][lrow] = kv4.z; Ks[lcol + 3][lrow] = kv4.w;
        __syncthreads();
        #pragma unroll
        for (int kk = 0; kk < 16; kk++) {
            float ra[4], rb[4];
            *(float4*)&ra[0] = *(const float4*)&Ts[kk][ty * 4];
            *(float4*)&rb[0] = *(const float4*)&Ks[kk][tx * 4];
            #pragma unroll
            for (int i = 0; i < 4; i++)
                #pragma unroll
                for (int j = 0; j < 4; j++)
                    acc[i][j] += ra[i] * rb[j];
        }
        __syncthreads();
    }
    #pragma unroll
    for (int i = 0; i < 4; i++) {
        int gi = ty * 4 + i;
        #pragma unroll
        for (int j = 0; j < 4; j++) {
            int gj = tx * 4 + j;
            float e = acc[i][j] + qv[gi] * bkv[gj] + bqv[gi] * kvv[gj]
                      + 4096.f * bqv[gi] * bkv[gj];
            Es[gi][gj] = e * ATT_SCALE;
        }
    }
    __syncthreads();
    if (tid < 64) {
        int i = tid;
        float m = -1e30f;
        for (int j = 0; j < 64; j++) m = fmaxf(m, Es[i][j]);
        float sum = 0.f;
        for (int j = 0; j < 64; j++) {
            float ex = expf(Es[i][j] - m);
            Es[i][j] = ex;
            sum += ex;
        }
        float inv = 1.f / sum;
        float ab = 0.f;
        float* Arow = g_A + (((long)b * NH + h) * HD + i) * HD;
        for (int j = 0; j < 64; j++) {
            float a = Es[i][j] * inv;
            Arow[j] = a;
            ab += a * bvv[j];
        }
        g_abv[b * CH + h * HD + i] = ab;
    }
}

// ---------------- Pt = (A_bd * Wv)^T, fp32 [c][r] ----------------
__global__ void __launch_bounds__(256) pk_kernel(const float* __restrict__ wv) {
    int h = blockIdx.x, b = blockIdx.y;
    __shared__ float Ash[64][64];
    __shared__ float Bv[64][64];
    int tid = threadIdx.x;
    const float* Ab = g_A + ((long)b * NH + h) * HD * HD;
    for (int r = tid; r < 64 * 16; r += 256) {
        int i = r >> 4, q = (r & 15) * 4;
        float4 v = *(const float4*)(Ab + i * 64 + q);
        Ash[q + 0][i] = v.x; Ash[q + 1][i] = v.y;
        Ash[q + 2][i] = v.z; Ash[q + 3][i] = v.w;
    }
    int tx = tid & 15, ty = tid >> 4;
    for (int cc = 0; cc < CH; cc += 64) {
        __syncthreads();
        for (int r = tid; r < 64 * 16; r += 256) {
            int j = r >> 4, q = (r & 15) * 4;
            *(float4*)&Bv[j][q] = *(const float4*)(wv + (long)(h * HD + j) * CH + cc + q);
        }
        __syncthreads();
        float acc[4][4];
        #pragma unroll
        for (int i = 0; i < 4; i++)
            #pragma unroll
            for (int j = 0; j < 4; j++) acc[i][j] = 0.f;
        #pragma unroll 8
        for (int j = 0; j < 64; j++) {
            float ra[4], rb[4];
            *(float4*)&ra[0] = *(const float4*)&Ash[j][ty * 4];
            *(float4*)&rb[0] = *(const float4*)&Bv[j][tx * 4];
            #pragma unroll
            for (int i = 0; i < 4; i++)
                #pragma unroll
                for (int u = 0; u < 4; u++)
                    acc[i][u] += ra[i] * rb[u];
        }
        #pragma unroll
        for (int u = 0; u < 4; u++) {
            int c = cc + tx * 4 + u;
            long base = ((long)b * CH + c) * CH + h * HD + ty * 4;
            *(float4*)(g_Pt + base) = make_float4(acc[0][u], acc[1][u], acc[2][u], acc[3][u]);
        }
    }
}

// ---------------- c[b] = Wo * abv[b] + bo ----------------
__global__ void cvec_kernel(const float* __restrict__ wo, const float* __restrict__ bo) {
    int b = blockIdx.x;
    __shared__ float sv[CH];
    for (int i = threadIdx.x; i < CH; i += 256) sv[i] = g_abv[b * CH + i];
    __syncthreads();
    for (int o = threadIdx.x; o < CH; o += 256) {
        const float* wr = wo + (long)o * CH;
        float sum = bo[o];
        for (int c = 0; c < CH; c++) sum += wr[c] * sv[c];
        g_c[b * CH + o] = sum;
    }
}

// ---------------- launch ----------------
extern "C" void kernel_launch(void* const* d_in, const int* in_sizes, int n_in,
                              void* d_out, int out_size) {
    const float* x  = (const float*)d_in[0];
    const float* wq = (const float*)d_in[1];
    const float* bq = (const float*)d_in[2];
    const float* wk = (const float*)d_in[3];
    const float* bk = (const float*)d_in[4];
    const float* wv = (const float*)d_in[5];
    const float* bv = (const float*)d_in[6];
    const float* wo = (const float*)d_in[7];
    const float* bo = (const float*)d_in[8];
    float* y = (float*)d_out;

    float *pT, *pM, *pPt, *pGP, *pc, *psM, *psXt, *psPt, *psWo;
    bf16 *pXh, *pXl, *pGh, *pGl, *pWqh, *pWql;
    int8_t *pXt0, *pXt1, *pM0, *pM1, *pPt0, *pPt1, *pWo0, *pWo1;
    cudaGetSymbolAddress((void**)&pT,  g_T);
    cudaGetSymbolAddress((void**)&pM,  g_M);
    cudaGetSymbolAddress((void**)&pPt, g_Pt);
    cudaGetSymbolAddress((void**)&pGP, g_GP);
    cudaGetSymbolAddress((void**)&pc,  g_c);
    cudaGetSymbolAddress((void**)&psM, g_sM);
    cudaGetSymbolAddress((void**)&psXt, g_sXt);
    cudaGetSymbolAddress((void**)&psPt, g_sPt);
    cudaGetSymbolAddress((void**)&psWo, g_sWo);
    cudaGetSymbolAddress((void**)&pXh, g_Xh);
    cudaGetSymbolAddress((void**)&pXl, g_Xl);
    cudaGetSymbolAddress((void**)&pGh, g_Gh);
    cudaGetSymbolAddress((void**)&pGl, g_Gl);
    cudaGetSymbolAddress((void**)&pWqh, g_Wqh);
    cudaGetSymbolAddress((void**)&pWql, g_Wql);
    cudaGetSymbolAddress((void**)&pXt0, g_Xt0);
    cudaGetSymbolAddress((void**)&pXt1, g_Xt1);
    cudaGetSymbolAddress((void**)&pM0, g_M0);
    cudaGetSymbolAddress((void**)&pM1, g_M1);
    cudaGetSymbolAddress((void**)&pPt0, g_Pt0);
    cudaGetSymbolAddress((void**)&pPt1, g_Pt1);
    cudaGetSymbolAddress((void**)&pWo0, g_Wo0);
    cudaGetSymbolAddress((void**)&pWo1, g_Wo1);

    cudaFuncSetAttribute((const void*)mma_gemm<true>,
                         cudaFuncAttributeMaxDynamicSharedMemorySize, MMA_SMEM);
    cudaFuncSetAttribute((const void*)mma_gemm<false>,
                         cudaFuncAttributeMaxDynamicSharedMemorySize, MMA_SMEM);
    cudaFuncSetAttribute((const void*)mma_gemm_i8,
                         cudaFuncAttributeMaxDynamicSharedMemorySize, MMA_SMEM);

    // 1. scales + splits of x
    colmax_kernel<<<dim3(NPIX / 256, BATCH), 256>>>(x);
    splitx_kernel<<<dim3(NPIX / 32, CH / 32, BATCH), dim3(32, 8)>>>(x);

    // 2. row sums + weight preps
    rowsum_kernel<<<dim3(CH, BATCH), 256>>>(x);
    splitw_kernel<<<(CH * CH) / 1024, 256>>>(wq, pWqh, pWql);
    quant_rows<<<dim3(CH, 1), 256>>>(wo, pWo0, pWo1, psWo);

    // 3. Gram partials: 21 triangle tiles x split-K 2.  K = 4096
    mma_gemm<true><<<dim3(21, 2, BATCH), 256, MMA_SMEM>>>(
        pXh, pXl, pXh, pXl, pGP,
        NPIX, NPIX / 2, CH, (long)CH * NPIX, (long)CH * NPIX, (long)CH * CH);

    // 4. reduce partials -> Gh/Gl (with mirror)
    gram_reduce<<<dim3(21, BATCH), 256>>>();

    // 5. qs/ks
    qsks_kernel<<<BATCH, 256>>>(wq, wk);

    // 6. T[b] = Wq * G[b]  (bf16 3-term).  K = 768
    mma_gemm<false><<<dim3(6, 6, BATCH), 256, MMA_SMEM>>>(
        pWqh, pWql, pGh, pGl, pT,
        CH, CH, CH, 0L, (long)CH * CH, (long)CH * CH);

    // 7. attention
    attn_kernel<<<dim3(NH, BATCH), 256>>>(wk, bq, bk, bv);

    // 8. Pt fp32, then quantize rows (per c)
    pk_kernel<<<dim3(NH, BATCH), 256>>>(wv);
    quant_rows<<<dim3(CH, BATCH), 256>>>(pPt, pPt0, pPt1, psPt);

    // 9. c[b] = Wo * abv + bo
    cvec_kernel<<<BATCH, 256>>>(wo, bo);

    // 10. M[b] = Wo * P[b]  (int8 2-limb).  K = 768
    mma_gemm_i8<<<dim3(6, 6, BATCH), 256, MMA_SMEM>>>(
        pWo0, pWo1, pPt0, pPt1, psWo, 0L, psPt, (long)CH,
        pM, nullptr, CH, CH, 0L, (long)CH * CH, (long)CH * CH);

    // 11. quantize M rows
    quant_rows<<<dim3(CH, BATCH), 256>>>(pM, pM0, pM1, psM);

    // 12. y[b] = M[b] * X[b] + c[b]  (int8 2-limb).  K = 768
    mma_gemm_i8<<<dim3(NPIX / 128, 6, BATCH), 256, MMA_SMEM>>>(
        pM0, pM1, pXt0, pXt1, psM, (long)CH, psXt, (long)NPIX,
        y, pc, CH, NPIX, (long)CH * CH, (long)NPIX * CH, (long)CH * NPIX);
}

// round 8
// speedup vs baseline: 2.3349x; 1.0625x over previous
#include <cuda_runtime.h>
#include <cuda_fp16.h>
#include <math.h>
#include <stdint.h>

#define BATCH 16
#define CH    768
#define NPIX  4096
#define NH    12
#define HD    64
#define ATT_SCALE 0.125f   // HD^-0.5

typedef __half fp16;

// ---------------- scratch (device globals; no runtime allocation) ----------------
__device__ float g_T [BATCH * CH * CH];       // T = Wq * G
__device__ float g_GP[2L * BATCH * CH * CH];  // Gram split-K partials
__device__ float g_A[BATCH * NH * HD * HD];
__device__ float g_s[BATCH * CH];
__device__ float g_qs[BATCH * CH];
__device__ float g_ks[BATCH * CH];
__device__ float g_abv[BATCH * CH];
__device__ float g_c[BATCH * CH];

__device__ __align__(16) fp16 g_Xh [BATCH * CH * NPIX];  // fp16 hi of X [b][c][n]
__device__ __align__(16) fp16 g_Xl [BATCH * CH * NPIX];  // fp16 lo
__device__ __align__(16) fp16 g_Xt [BATCH * NPIX * CH];  // fp16(X) transposed [b][n][c]
__device__ __align__(16) fp16 g_Gh [BATCH * CH * CH];
__device__ __align__(16) fp16 g_Gl [BATCH * CH * CH];
__device__ __align__(16) fp16 g_Pth[BATCH * CH * CH];    // (A_bd*Wv)^T hi [c][r]
__device__ __align__(16) fp16 g_Ptl[BATCH * CH * CH];
__device__ __align__(16) fp16 g_Mh [BATCH * CH * CH];    // fp16(M) single
__device__ __align__(16) fp16 g_Wqh[CH * CH];
__device__ __align__(16) fp16 g_Wql[CH * CH];
__device__ __align__(16) fp16 g_Woh[CH * CH];
__device__ __align__(16) fp16 g_Wol[CH * CH];

// ---------------- asm helpers (sm_80-compatible only) ----------------
__device__ __forceinline__ uint32_t smem_u32(const void* p) {
    uint32_t a;
    asm("{ .reg .u64 t; cvta.to.shared.u64 t, %1; cvt.u32.u64 %0, t; }" : "=r"(a) : "l"(p));
    return a;
}
__device__ __forceinline__ void ldsm4(uint32_t* r, uint32_t a) {
    asm volatile("ldmatrix.sync.aligned.m8n8.x4.shared.b16 {%0,%1,%2,%3}, [%4];"
                 : "=r"(r[0]), "=r"(r[1]), "=r"(r[2]), "=r"(r[3]) : "r"(a));
}
__device__ __forceinline__ void mma_f16(float* c, const uint32_t* a, const uint32_t* b) {
    asm volatile(
        "mma.sync.aligned.m16n8k16.row.col.f32.f16.f16.f32 "
        "{%0,%1,%2,%3}, {%4,%5,%6,%7}, {%8,%9}, {%0,%1,%2,%3};"
        : "+f"(c[0]), "+f"(c[1]), "+f"(c[2]), "+f"(c[3])
        : "r"(a[0]), "r"(a[1]), "r"(a[2]), "r"(a[3]), "r"(b[0]), "r"(b[1]));
}
#define CP_A16(dst, src) asm volatile( \
    "cp.async.cg.shared.global [%0], [%1], 16;" :: "r"(dst), "l"(src))
#define CP_COMMIT() asm volatile("cp.async.commit_group;" ::: "memory")
#define CP_WAIT0()  asm volatile("cp.async.wait_group 0;" ::: "memory")
#define CP_WAIT1()  asm volatile("cp.async.wait_group 1;" ::: "memory")
#define CP_WAIT2()  asm volatile("cp.async.wait_group 2;" ::: "memory")

// ---------------- smem geometry ----------------
#define ROWPITCH 80
#define ARR_BYTES 10240
#define STAGE_BYTES (4 * ARR_BYTES)          // 3-term: AH AL BH BL
#define MMA_SMEM (3 * STAGE_BYTES)           // 122880
#define H1_STAGE (2 * ARR_BYTES)             // 1-term: A B
#define H1_SMEM (3 * H1_STAGE)               // 61440

// =================================================================
// 3-term fp16 GEMM:  C(128x128) = Ah*Bh^T + Ah*Bl^T + Al*Bh^T
// EPI: 0 = fp32 out, 1 = fp16 single out.
// MIRROR: lower-triangle tile decode + split-K partial output.
// =================================================================
template<int EPI, bool MIRROR>
__global__ void __launch_bounds__(256) mma_gemm(
    const fp16* __restrict__ Ahg, const fp16* __restrict__ Alg,
    const fp16* __restrict__ Bhg, const fp16* __restrict__ Blg,
    float* __restrict__ Cf, fp16* __restrict__ Ch,
    int Kdim, int Ksub, int ldc, long sA, long sB, long sC)
{
    extern __shared__ char smem[];
    uint32_t sbase = smem_u32(smem);
    int tid = threadIdx.x;
    int lane = tid & 31, wid = tid >> 5;
    int b = blockIdx.z;
    int m0, n0, kbase = 0;
    long outb;
    if (MIRROR) {
        int t = blockIdx.x, bi = 0;
        while ((bi + 1) * (bi + 2) / 2 <= t) bi++;
        int bj = t - bi * (bi + 1) / 2;
        m0 = bi * 128; n0 = bj * 128;
        kbase = blockIdx.y * Ksub;
        outb = ((long)blockIdx.y * BATCH + b) * sC;
    } else {
        m0 = blockIdx.y * 128; n0 = blockIdx.x * 128;
        outb = (long)b * sC;
    }
    int m_warp = (wid & 3) * 32, n_warp = (wid >> 2) * 64;

    const fp16* pAh = Ahg + b * sA + (long)m0 * Kdim + kbase;
    const fp16* pAl = Alg + b * sA + (long)m0 * Kdim + kbase;
    const fp16* pBh = Bhg + b * sB + (long)n0 * Kdim + kbase;
    const fp16* pBl = Blg + b * sB + (long)n0 * Kdim + kbase;

    uint32_t a_off = (uint32_t)((m_warp + (lane & 15)) * ROWPITCH + (lane >> 4) * 16);
    uint32_t b_off = (uint32_t)((n_warp + (lane & 7) + ((lane >> 4) & 1) * 8) * ROWPITCH
                                + ((lane >> 3) & 1) * 16);

    float acc[2][8][4];
    #pragma unroll
    for (int mt = 0; mt < 2; mt++)
        #pragma unroll
        for (int nt = 0; nt < 8; nt++)
            #pragma unroll
            for (int q = 0; q < 4; q++) acc[mt][nt][q] = 0.f;

    int nch = Ksub >> 5;

    auto load_stage = [&](int stage, int k0) {
        uint32_t st = sbase + stage * STAGE_BYTES;
        #pragma unroll
        for (int it = 0; it < 2; it++) {
            int q = tid + it * 256;
            int r = q >> 2, c = q & 3;
            uint32_t off = r * ROWPITCH + c * 16;
            long gofs = ((long)r * Kdim + k0 + c * 8);
            CP_A16(st + 0 * ARR_BYTES + off, (const char*)(pAh + gofs));
            CP_A16(st + 1 * ARR_BYTES + off, (const char*)(pAl + gofs));
            CP_A16(st + 2 * ARR_BYTES + off, (const char*)(pBh + gofs));
            CP_A16(st + 3 * ARR_BYTES + off, (const char*)(pBl + gofs));
        }
        CP_COMMIT();
    };

    load_stage(0, 0);
    load_stage(1, 32);

    for (int ic = 0; ic < nch; ic++) {
        if (ic + 2 < nch) { load_stage((ic + 2) % 3, (ic + 2) * 32); CP_WAIT2(); }
        else if (ic + 1 < nch) { CP_WAIT1(); }
        else { CP_WAIT0(); }
        __syncthreads();

        uint32_t st = sbase + (ic % 3) * STAGE_BYTES;
        #pragma unroll
        for (int kk = 0; kk < 2; kk++) {
            uint32_t ah[2][4], al[2][4];
            ldsm4(ah[0], st + 0 * ARR_BYTES + a_off + kk * 32);
            ldsm4(ah[1], st + 0 * ARR_BYTES + a_off + 16 * ROWPITCH + kk * 32);
            ldsm4(al[0], st + 1 * ARR_BYTES + a_off + kk * 32);
            ldsm4(al[1], st + 1 * ARR_BYTES + a_off + 16 * ROWPITCH + kk * 32);
            #pragma unroll
            for (int ntp = 0; ntp < 4; ntp++) {
                uint32_t bh[4], bl[4];
                ldsm4(bh, st + 2 * ARR_BYTES + b_off + ntp * 16 * ROWPITCH + kk * 32);
                ldsm4(bl, st + 3 * ARR_BYTES + b_off + ntp * 16 * ROWPITCH + kk * 32);
                #pragma unroll
                for (int mt = 0; mt < 2; mt++) {
                    mma_f16(acc[mt][2 * ntp],     ah[mt], bh);
                    mma_f16(acc[mt][2 * ntp],     ah[mt], bl);
                    mma_f16(acc[mt][2 * ntp],     al[mt], bh);
                    mma_f16(acc[mt][2 * ntp + 1], ah[mt], bh + 2);
                    mma_f16(acc[mt][2 * ntp + 1], ah[mt], bl + 2);
                    mma_f16(acc[mt][2 * ntp + 1], al[mt], bh + 2);
                }
            }
        }
        __syncthreads();
    }

    #pragma unroll
    for (int mt = 0; mt < 2; mt++) {
        #pragma unroll
        for (int hh = 0; hh < 2; hh++) {
            int rg = m0 + m_warp + mt * 16 + (lane >> 2) + hh * 8;
            long rowoff = outb + (long)rg * ldc;
            #pragma unroll
            for (int nt = 0; nt < 8; nt++) {
                int cg = n0 + n_warp + nt * 8 + (lane & 3) * 2;
                float v0 = acc[mt][nt][hh * 2 + 0];
                float v1 = acc[mt][nt][hh * 2 + 1];
                if (EPI == 1) {
                    __half2 hv;
                    hv.x = __float2half(v0);
                    hv.y = __float2half(v1);
                    *(__half2*)(Ch + rowoff + cg) = hv;
                } else {
                    *(float2*)(Cf + rowoff + cg) = make_float2(v0, v1);
                }
            }
        }
    }
}

// ---------------- Gram reduce: sum split-K partials -> fp16 h/l + mirror ----------------
__global__ void gram_reduce() {
    int t = blockIdx.x, b = blockIdx.y;
    int bi = 0;
    while ((bi + 1) * (bi + 2) / 2 <= t) bi++;
    int bj = t - bi * (bi + 1) / 2;
    long mb = (long)b * CH * CH;
    const float* P0 = g_GP + mb;
    const float* P1 = g_GP + (long)BATCH * CH * CH + mb;
    bool mir = (bi != bj);
    for (int e = threadIdx.x; e < 16384; e += 256) {
        int r = bi * 128 + (e >> 7);
        int c = bj * 128 + (e & 127);
        long o = (long)r * CH + c;
        float v = P0[o] + P1[o];
        fp16 h = __float2half(v);
        fp16 l = __float2half(v - __half2float(h));
        g_Gh[mb + o] = h;
        g_Gl[mb + o] = l;
        if (mir) {
            long ot = (long)c * CH + r;
            g_Gh[mb + ot] = h;
            g_Gl[mb + ot] = l;
        }
    }
}

// =================================================================
// 1-term fp16 GEMM (final):  C = A * B^T + bias[r]
// A [M x K], B [N x K], both fp16 K-major. 2 CTAs/SM.
// =================================================================
__global__ void __launch_bounds__(256, 2) mma_gemm_h1(
    const fp16* __restrict__ Ag, const fp16* __restrict__ Bg,
    float* __restrict__ Cf, const float* __restrict__ biasg,
    int Kdim, int ldc, long sA, long sB, long sC)
{
    extern __shared__ char smem[];
    uint32_t sbase = smem_u32(smem);
    int tid = threadIdx.x;
    int lane = tid & 31, wid = tid >> 5;
    int b = blockIdx.z;
    int m0 = blockIdx.y * 128, n0 = blockIdx.x * 128;
    int m_warp = (wid & 3) * 32, n_warp = (wid >> 2) * 64;

    const fp16* pA = Ag + b * sA + (long)m0 * Kdim;
    const fp16* pB = Bg + b * sB + (long)n0 * Kdim;

    uint32_t a_off = (uint32_t)((m_warp + (lane & 15)) * ROWPITCH + (lane >> 4) * 16);
    uint32_t b_off = (uint32_t)((n_warp + (lane & 7) + ((lane >> 4) & 1) * 8) * ROWPITCH
                                + ((lane >> 3) & 1) * 16);

    float acc[2][8][4];
    #pragma unroll
    for (int mt = 0; mt < 2; mt++)
        #pragma unroll
        for (int nt = 0; nt < 8; nt++)
            #pragma unroll
            for (int q = 0; q < 4; q++) acc[mt][nt][q] = 0.f;

    int nch = Kdim >> 5;

    auto load_stage = [&](int stage, int k0) {
        uint32_t st = sbase + stage * H1_STAGE;
        #pragma unroll
        for (int it = 0; it < 4; it++) {
            int q = tid + it * 256;           // 0..1023
            int r = q >> 2, c = q & 3;        // r 0..255
            int arr = r >> 7, rr = r & 127;
            uint32_t dst = st + arr * ARR_BYTES + rr * ROWPITCH + c * 16;
            const fp16* src = (arr ? pB : pA) + (long)rr * Kdim + k0 + c * 8;
            CP_A16(dst, (const char*)src);
        }
        CP_COMMIT();
    };

    load_stage(0, 0);
    load_stage(1, 32);

    for (int ic = 0; ic < nch; ic++) {
        if (ic + 2 < nch) { load_stage((ic + 2) % 3, (ic + 2) * 32); CP_WAIT2(); }
        else if (ic + 1 < nch) { CP_WAIT1(); }
        else { CP_WAIT0(); }
        __syncthreads();

        uint32_t st = sbase + (ic % 3) * H1_STAGE;
        #pragma unroll
        for (int kk = 0; kk < 2; kk++) {
            uint32_t a[2][4];
            ldsm4(a[0], st + a_off + kk * 32);
            ldsm4(a[1], st + a_off + 16 * ROWPITCH + kk * 32);
            #pragma unroll
            for (int ntp = 0; ntp < 4; ntp++) {
                uint32_t bf[4];
                ldsm4(bf, st + ARR_BYTES + b_off + ntp * 16 * ROWPITCH + kk * 32);
                #pragma unroll
                for (int mt = 0; mt < 2; mt++) {
                    mma_f16(acc[mt][2 * ntp],     a[mt], bf);
                    mma_f16(acc[mt][2 * ntp + 1], a[mt], bf + 2);
                }
            }
        }
        __syncthreads();
    }

    #pragma unroll
    for (int mt = 0; mt < 2; mt++) {
        #pragma unroll
        for (int hh = 0; hh < 2; hh++) {
            int rg = m0 + m_warp + mt * 16 + (lane >> 2) + hh * 8;
            float bias = biasg[b * CH + rg];
            long rowoff = b * sC + (long)rg * ldc;
            #pragma unroll
            for (int nt = 0; nt < 8; nt++) {
                int cg = n0 + n_warp + nt * 8 + (lane & 3) * 2;
                *(float2*)(Cf + rowoff + cg) =
                    make_float2(acc[mt][nt][hh * 2 + 0] + bias,
                                acc[mt][nt][hh * 2 + 1] + bias);
            }
        }
    }
}

// ---------------- x -> fp16 h/l (natural) + fp16 single (transposed) ----------------
__global__ void splitx_kernel(const float* __restrict__ x) {
    __shared__ float xt[32][33];
    int b = blockIdx.z;
    int n0 = blockIdx.x * 32, c0 = blockIdx.y * 32;
    int tx = threadIdx.x, ty = threadIdx.y;
    const float* xb = x + (long)b * CH * NPIX;
    #pragma unroll
    for (int k = 0; k < 4; k++) {
        int c = c0 + ty + k * 8;
        float v = xb[(long)c * NPIX + n0 + tx];
        xt[ty + k * 8][tx] = v;
        fp16 h = __float2half(v);
        fp16 l = __float2half(v - __half2float(h));
        long idx = ((long)b * CH + c) * NPIX + n0 + tx;
        g_Xh[idx] = h;
        g_Xl[idx] = l;
    }
    __syncthreads();
    #pragma unroll
    for (int k = 0; k < 4; k++) {
        int n = n0 + ty + k * 8;
        long idx = ((long)b * NPIX + n) * CH + c0 + tx;
        g_Xt[idx] = __float2half(xt[tx][ty + k * 8]);
    }
}

// ---------------- elementwise split fp32 -> fp16 h/l ----------------
__global__ void splitw_kernel(const float* __restrict__ src,
                              fp16* __restrict__ oh, fp16* __restrict__ ol) {
    long i = ((long)blockIdx.x * 256 + threadIdx.x) * 4;
    float4 v = *(const float4*)(src + i);
    fp16 h0 = __float2half(v.x), h1 = __float2half(v.y);
    fp16 h2 = __float2half(v.z), h3 = __float2half(v.w);
    oh[i + 0] = h0; ol[i + 0] = __float2half(v.x - __half2float(h0));
    oh[i + 1] = h1; ol[i + 1] = __float2half(v.y - __half2float(h1));
    oh[i + 2] = h2; ol[i + 2] = __float2half(v.z - __half2float(h2));
    oh[i + 3] = h3; ol[i + 3] = __float2half(v.w - __half2float(h3));
}

// ---------------- row sums ----------------
__global__ void rowsum_kernel(const float* __restrict__ x) {
    int c = blockIdx.x, b = blockIdx.y;
    const float* row = x + ((long)b * CH + c) * NPIX;
    float s = 0.f;
    for (int n = threadIdx.x * 4; n < NPIX; n += 256 * 4) {
        float4 v = *(const float4*)(row + n);
        s += v.x + v.y + v.z + v.w;
    }
    __shared__ float red[256];
    red[threadIdx.x] = s;
    __syncthreads();
    for (int off = 128; off > 0; off >>= 1) {
        if (threadIdx.x < off) red[threadIdx.x] += red[threadIdx.x + off];
        __syncthreads();
    }
    if (threadIdx.x == 0) g_s[b * CH + c] = red[0];
}

// ---------------- qs = Wq*s, ks = Wk*s ----------------
__global__ void qsks_kernel(const float* __restrict__ wq, const float* __restrict__ wk) {
    int b = blockIdx.x;
    __shared__ float sv[CH];
    for (int i = threadIdx.x; i < CH; i += 256) sv[i] = g_s[b * CH + i];
    __syncthreads();
    for (int o = threadIdx.x; o < CH; o += 256) {
        const float* wr = wq + (long)o * CH;
        const float* kr = wk + (long)o * CH;
        float aq = 0.f, ak = 0.f;
        for (int c = 0; c < CH; c++) { aq += wr[c] * sv[c]; ak += kr[c] * sv[c]; }
        g_qs[b * CH + o] = aq;
        g_ks[b * CH + o] = ak;
    }
}

// ---------------- energy blocks + softmax + abv ----------------
__global__ void __launch_bounds__(256) attn_kernel(
    const float* __restrict__ wk, const float* __restrict__ bq,
    const float* __restrict__ bk, const float* __restrict__ bv)
{
    int h = blockIdx.x, b = blockIdx.y;
    __shared__ float Ts[16][64];
    __shared__ float Ks[16][64];
    __shared__ float Es[64][65];
    __shared__ float qv[64], kvv[64], bqv[64], bkv[64], bvv[64];
    int tid = threadIdx.x;
    if (tid < 64) {
        qv[tid]  = g_qs[b * CH + h * HD + tid];
        kvv[tid] = g_ks[b * CH + h * HD + tid];
        bqv[tid] = bq[h * HD + tid];
        bkv[tid] = bk[h * HD + tid];
        bvv[tid] = bv[h * HD + tid];
    }
    const float* Tb = g_T + ((long)b * CH + h * HD) * CH;
    const float* Kb = wk + (long)(h * HD) * CH;
    int lrow = tid >> 2;
    int lcol = (tid & 3) * 4;
    int tx = tid & 15, ty = tid >> 4;
    float acc[4][4];
    #pragma unroll
    for (int i = 0; i < 4; i++)
        #pragma unroll
        for (int j = 0; j < 4; j++) acc[i][j] = 0.f;

    for (int a0 = 0; a0 < CH; a0 += 16) {
        float4 tv = *(const float4*)(Tb + (long)lrow * CH + a0 + lcol);
        Ts[lcol + 0][lrow] = tv.x; Ts[lcol + 1][lrow] = tv.y;
        Ts[lcol + 2][lrow] = tv.z; Ts[lcol + 3][lrow] = tv.w;
        float4 kv4 = *(const float4*)(Kb + (long)lrow * CH + a0 + lcol);
        Ks[lcol + 0][lrow] = kv4.x; Ks[lcol + 1][lrow] = kv4.y;
        Ks[lcol + 2][lrow] = kv4.z; Ks[lcol + 3][lrow] = kv4.w;
        __syncthreads();
        #pragma unroll
        for (int kk = 0; kk < 16; kk++) {
            float ra[4], rb[4];
            *(float4*)&ra[0] = *(const float4*)&Ts[kk][ty * 4];
            *(float4*)&rb[0] = *(const float4*)&Ks[kk][tx * 4];
            #pragma unroll
            for (int i = 0; i < 4; i++)
                #pragma unroll
                for (int j = 0; j < 4; j++)
                    acc[i][j] += ra[i] * rb[j];
        }
        __syncthreads();
    }
    #pragma unroll
    for (int i = 0; i < 4; i++) {
        int gi = ty * 4 + i;
        #pragma unroll
        for (int j = 0; j < 4; j++) {
            int gj = tx * 4 + j;
            float e = acc[i][j] + qv[gi] * bkv[gj] + bqv[gi] * kvv[gj]
                      + 4096.f * bqv[gi] * bkv[gj];
            Es[gi][gj] = e * ATT_SCALE;
        }
    }
    __syncthreads();
    if (tid < 64) {
        int i = tid;
        float m = -1e30f;
        for (int j = 0; j < 64; j++) m = fmaxf(m, Es[i][j]);
        float sum = 0.f;
        for (int j = 0; j < 64; j++) {
            float ex = expf(Es[i][j] - m);
            Es[i][j] = ex;
            sum += ex;
        }
        float inv = 1.f / sum;
        float ab = 0.f;
        float* Arow = g_A + (((long)b * NH + h) * HD + i) * HD;
        for (int j = 0; j < 64; j++) {
            float a = Es[i][j] * inv;
            Arow[j] = a;
            ab += a * bvv[j];
        }
        g_abv[b * CH + h * HD + i] = ab;
    }
}

// ---------------- Pt = (A_bd * Wv)^T, fp16 hi/lo [c][r] ----------------
__global__ void __launch_bounds__(256) pk_kernel(const float* __restrict__ wv) {
    int h = blockIdx.x, b = blockIdx.y;
    __shared__ float Ash[64][64];
    __shared__ float Bv[64][64];
    int tid = threadIdx.x;
    const float* Ab = g_A + ((long)b * NH + h) * HD * HD;
    for (int r = tid; r < 64 * 16; r += 256) {
        int i = r >> 4, q = (r & 15) * 4;
        float4 v = *(const float4*)(Ab + i * 64 + q);
        Ash[q + 0][i] = v.x; Ash[q + 1][i] = v.y;
        Ash[q + 2][i] = v.z; Ash[q + 3][i] = v.w;
    }
    int tx = tid & 15, ty = tid >> 4;
    for (int cc = 0; cc < CH; cc += 64) {
        __syncthreads();
        for (int r = tid; r < 64 * 16; r += 256) {
            int j = r >> 4, q = (r & 15) * 4;
            *(float4*)&Bv[j][q] = *(const float4*)(wv + (long)(h * HD + j) * CH + cc + q);
        }
        __syncthreads();
        float acc[4][4];
        #pragma unroll
        for (int i = 0; i < 4; i++)
            #pragma unroll
            for (int j = 0; j < 4; j++) acc[i][j] = 0.f;
        #pragma unroll 8
        for (int j = 0; j < 64; j++) {
            float ra[4], rb[4];
            *(float4*)&ra[0] = *(const float4*)&Ash[j][ty * 4];
            *(float4*)&rb[0] = *(const float4*)&Bv[j][tx * 4];
            #pragma unroll
            for (int i = 0; i < 4; i++)
                #pragma unroll
                for (int u = 0; u < 4; u++)
                    acc[i][u] += ra[i] * rb[u];
        }
        #pragma unroll
        for (int u = 0; u < 4; u++) {
            int c = cc + tx * 4 + u;
            long base = ((long)b * CH + c) * CH + h * HD + ty * 4;
            float v0 = acc[0][u], v1 = acc[1][u], v2 = acc[2][u], v3 = acc[3][u];
            fp16 h0 = __float2half(v0), h1 = __float2half(v1);
            fp16 h2 = __float2half(v2), h3 = __float2half(v3);
            __half2 a0, a1, b0, b1;
            a0.x = h0; a0.y = h1; a1.x = h2; a1.y = h3;
            b0.x = __float2half(v0 - __half2float(h0));
            b0.y = __float2half(v1 - __half2float(h1));
            b1.x = __float2half(v2 - __half2float(h2));
            b1.y = __float2half(v3 - __half2float(h3));
            *(__half2*)(g_Pth + base)     = a0;
            *(__half2*)(g_Pth + base + 2) = a1;
            *(__half2*)(g_Ptl + base)     = b0;
            *(__half2*)(g_Ptl + base + 2) = b1;
        }
    }
}

// ---------------- c[b] = Wo * abv[b] + bo ----------------
__global__ void cvec_kernel(const float* __restrict__ wo, const float* __restrict__ bo) {
    int b = blockIdx.x;
    __shared__ float sv[CH];
    for (int i = threadIdx.x; i < CH; i += 256) sv[i] = g_abv[b * CH + i];
    __syncthreads();
    for (int o = threadIdx.x; o < CH; o += 256) {
        const float* wr = wo + (long)o * CH;
        float sum = bo[o];
        for (int c = 0; c < CH; c++) sum += wr[c] * sv[c];
        g_c[b * CH + o] = sum;
    }
}

// ---------------- launch ----------------
extern "C" void kernel_launch(void* const* d_in, const int* in_sizes, int n_in,
                              void* d_out, int out_size) {
    const float* x  = (const float*)d_in[0];
    const float* wq = (const float*)d_in[1];
    const float* bq = (const float*)d_in[2];
    const float* wk = (const float*)d_in[3];
    const float* bk = (const float*)d_in[4];
    const float* wv = (const float*)d_in[5];
    const float* bv = (const float*)d_in[6];
    const float* wo = (const float*)d_in[7];
    const float* bo = (const float*)d_in[8];
    float* y = (float*)d_out;

    float *pT, *pGP, *pc;
    fp16 *pXh, *pXl, *pXt, *pGh, *pGl, *pPth, *pPtl, *pMh;
    fp16 *pWqh, *pWql, *pWoh, *pWol;
    cudaGetSymbolAddress((void**)&pT,  g_T);
    cudaGetSymbolAddress((void**)&pGP, g_GP);
    cudaGetSymbolAddress((void**)&pc,  g_c);
    cudaGetSymbolAddress((void**)&pXh, g_Xh);
    cudaGetSymbolAddress((void**)&pXl, g_Xl);
    cudaGetSymbolAddress((void**)&pXt, g_Xt);
    cudaGetSymbolAddress((void**)&pGh, g_Gh);
    cudaGetSymbolAddress((void**)&pGl, g_Gl);
    cudaGetSymbolAddress((void**)&pPth, g_Pth);
    cudaGetSymbolAddress((void**)&pPtl, g_Ptl);
    cudaGetSymbolAddress((void**)&pMh, g_Mh);
    cudaGetSymbolAddress((void**)&pWqh, g_Wqh);
    cudaGetSymbolAddress((void**)&pWql, g_Wql);
    cudaGetSymbolAddress((void**)&pWoh, g_Woh);
    cudaGetSymbolAddress((void**)&pWol, g_Wol);

    cudaFuncSetAttribute((const void*)mma_gemm<0, true>,
                         cudaFuncAttributeMaxDynamicSharedMemorySize, MMA_SMEM);
    cudaFuncSetAttribute((const void*)mma_gemm<0, false>,
                         cudaFuncAttributeMaxDynamicSharedMemorySize, MMA_SMEM);
    cudaFuncSetAttribute((const void*)mma_gemm<1, false>,
                         cudaFuncAttributeMaxDynamicSharedMemorySize, MMA_SMEM);
    cudaFuncSetAttribute((const void*)mma_gemm_h1,
                         cudaFuncAttributeMaxDynamicSharedMemorySize, H1_SMEM);

    // 1. split x: fp16 h/l natural + fp16 transposed
    splitx_kernel<<<dim3(NPIX / 32, CH / 32, BATCH), dim3(32, 8)>>>(x);

    // 2. row sums + weight splits
    rowsum_kernel<<<dim3(CH, BATCH), 256>>>(x);
    splitw_kernel<<<(CH * CH) / 1024, 256>>>(wq, pWqh, pWql);
    splitw_kernel<<<(CH * CH) / 1024, 256>>>(wo, pWoh, pWol);

    // 3. Gram partials: 21 triangle tiles x split-K 2.  K = 4096
    mma_gemm<0, true><<<dim3(21, 2, BATCH), 256, MMA_SMEM>>>(
        pXh, pXl, pXh, pXl, pGP, nullptr,
        NPIX, NPIX / 2, CH, (long)CH * NPIX, (long)CH * NPIX, (long)CH * CH);

    // 4. reduce partials -> Gh/Gl (with mirror)
    gram_reduce<<<dim3(21, BATCH), 256>>>();

    // 5. qs/ks
    qsks_kernel<<<BATCH, 256>>>(wq, wk);

    // 6. T[b] = Wq * G[b]  (fp16 3-term).  K = 768
    mma_gemm<0, false><<<dim3(6, 6, BATCH), 256, MMA_SMEM>>>(
        pWqh, pWql, pGh, pGl, pT, nullptr,
        CH, CH, CH, 0L, (long)CH * CH, (long)CH * CH);

    // 7. attention
    attn_kernel<<<dim3(NH, BATCH), 256>>>(wk, bq, bk, bv);

    // 8. Pt fp16 h/l
    pk_kernel<<<dim3(NH, BATCH), 256>>>(wv);

    // 9. c[b] = Wo * abv + bo
    cvec_kernel<<<BATCH, 256>>>(wo, bo);

    // 10. M[b] = Wo * P[b]  (fp16 3-term, fp16 single out).  K = 768
    mma_gemm<1, false><<<dim3(6, 6, BATCH), 256, MMA_SMEM>>>(
        pWoh, pWol, pPth, pPtl, nullptr, pMh,
        CH, CH, CH, 0L, (long)CH * CH, (long)CH * CH);

    // 11. y[b] = M[b] * X[b] + c[b]  (fp16 single-term).  K = 768
    mma_gemm_h1<<<dim3(NPIX / 128, 6, BATCH), 256, H1_SMEM>>>(
        pMh, pXt, y, pc,
        CH, NPIX, (long)CH * CH, (long)NPIX * CH, (long)CH * NPIX);
}

// round 9
// speedup vs baseline: 2.3905x; 1.0238x over previous
#include <cuda_runtime.h>
#include <cuda_fp16.h>
#include <math.h>
#include <stdint.h>

#define BATCH 16
#define CH    768
#define NPIX  4096
#define NH    12
#define HD    64
#define ATT_SCALE 0.125f   // HD^-0.5

typedef __half fp16;

// ---------------- scratch (device globals; no runtime allocation) ----------------
__device__ float g_T [BATCH * CH * CH];       // T = Wq * G
__device__ float g_GP[2L * BATCH * CH * CH];  // Gram split-K partials
__device__ float g_A[BATCH * NH * HD * HD];
__device__ float g_s[BATCH * CH];
__device__ float g_qs[BATCH * CH];
__device__ float g_ks[BATCH * CH];
__device__ float g_abv[BATCH * CH];
__device__ float g_c[BATCH * CH];

__device__ __align__(16) fp16 g_Xh [BATCH * CH * NPIX];  // fp16 hi of X [b][c][n]
__device__ __align__(16) fp16 g_Xl [BATCH * CH * NPIX];  // fp16 lo
__device__ __align__(16) fp16 g_Xt [BATCH * NPIX * CH];  // fp16(X) transposed [b][n][c]
__device__ __align__(16) fp16 g_Gh [BATCH * CH * CH];
__device__ __align__(16) fp16 g_Gl [BATCH * CH * CH];
__device__ __align__(16) fp16 g_Pth[BATCH * CH * CH];    // (A_bd*Wv)^T hi [c][r]
__device__ __align__(16) fp16 g_Ptl[BATCH * CH * CH];
__device__ __align__(16) fp16 g_Mh [BATCH * CH * CH];    // fp16(M) single
__device__ __align__(16) fp16 g_Wqh[CH * CH];
__device__ __align__(16) fp16 g_Wql[CH * CH];
__device__ __align__(16) fp16 g_Woh[CH * CH];            // fp16(Wo) single

// ---------------- asm helpers (sm_80-compatible only) ----------------
__device__ __forceinline__ uint32_t smem_u32(const void* p) {
    uint32_t a;
    asm("{ .reg .u64 t; cvta.to.shared.u64 t, %1; cvt.u32.u64 %0, t; }" : "=r"(a) : "l"(p));
    return a;
}
__device__ __forceinline__ void ldsm4(uint32_t* r, uint32_t a) {
    asm volatile("ldmatrix.sync.aligned.m8n8.x4.shared.b16 {%0,%1,%2,%3}, [%4];"
                 : "=r"(r[0]), "=r"(r[1]), "=r"(r[2]), "=r"(r[3]) : "r"(a));
}
__device__ __forceinline__ void mma_f16(float* c, const uint32_t* a, const uint32_t* b) {
    asm volatile(
        "mma.sync.aligned.m16n8k16.row.col.f32.f16.f16.f32 "
        "{%0,%1,%2,%3}, {%4,%5,%6,%7}, {%8,%9}, {%0,%1,%2,%3};"
        : "+f"(c[0]), "+f"(c[1]), "+f"(c[2]), "+f"(c[3])
        : "r"(a[0]), "r"(a[1]), "r"(a[2]), "r"(a[3]), "r"(b[0]), "r"(b[1]));
}
#define CP_A16(dst, src) asm volatile( \
    "cp.async.cg.shared.global [%0], [%1], 16;" :: "r"(dst), "l"(src))
#define CP_COMMIT() asm volatile("cp.async.commit_group;" ::: "memory")
#define CP_WAIT0()  asm volatile("cp.async.wait_group 0;" ::: "memory")
#define CP_WAIT1()  asm volatile("cp.async.wait_group 1;" ::: "memory")
#define CP_WAIT2()  asm volatile("cp.async.wait_group 2;" ::: "memory")

// ---------------- smem geometry ----------------
#define ROWPITCH 80
#define ARR_BYTES 10240
#define STAGE_BYTES (4 * ARR_BYTES)          // 3-term: AH AL BH BL
#define MMA_SMEM (3 * STAGE_BYTES)           // 122880
#define T2_STAGE (3 * ARR_BYTES)             // 2-term: AH BH BL
#define T2_SMEM (3 * T2_STAGE)               // 92160
#define H1_STAGE (2 * ARR_BYTES)             // 1-term: A B
#define H1_SMEM (3 * H1_STAGE)               // 61440

// =================================================================
// 3-term fp16 GEMM:  C(128x128) = Ah*Bh^T + Ah*Bl^T + Al*Bh^T  (fp32 out)
// MIRROR: lower-triangle tile decode + split-K partial output.
// =================================================================
template<bool MIRROR>
__global__ void __launch_bounds__(256) mma_gemm(
    const fp16* __restrict__ Ahg, const fp16* __restrict__ Alg,
    const fp16* __restrict__ Bhg, const fp16* __restrict__ Blg,
    float* __restrict__ Cf,
    int Kdim, int Ksub, int ldc, long sA, long sB, long sC)
{
    extern __shared__ char smem[];
    uint32_t sbase = smem_u32(smem);
    int tid = threadIdx.x;
    int lane = tid & 31, wid = tid >> 5;
    int b = blockIdx.z;
    int m0, n0, kbase = 0;
    long outb;
    if (MIRROR) {
        int t = blockIdx.x, bi = 0;
        while ((bi + 1) * (bi + 2) / 2 <= t) bi++;
        int bj = t - bi * (bi + 1) / 2;
        m0 = bi * 128; n0 = bj * 128;
        kbase = blockIdx.y * Ksub;
        outb = ((long)blockIdx.y * BATCH + b) * sC;
    } else {
        m0 = blockIdx.y * 128; n0 = blockIdx.x * 128;
        outb = (long)b * sC;
    }
    int m_warp = (wid & 3) * 32, n_warp = (wid >> 2) * 64;

    const fp16* pAh = Ahg + b * sA + (long)m0 * Kdim + kbase;
    const fp16* pAl = Alg + b * sA + (long)m0 * Kdim + kbase;
    const fp16* pBh = Bhg + b * sB + (long)n0 * Kdim + kbase;
    const fp16* pBl = Blg + b * sB + (long)n0 * Kdim + kbase;

    uint32_t a_off = (uint32_t)((m_warp + (lane & 15)) * ROWPITCH + (lane >> 4) * 16);
    uint32_t b_off = (uint32_t)((n_warp + (lane & 7) + ((lane >> 4) & 1) * 8) * ROWPITCH
                                + ((lane >> 3) & 1) * 16);

    float acc[2][8][4];
    #pragma unroll
    for (int mt = 0; mt < 2; mt++)
        #pragma unroll
        for (int nt = 0; nt < 8; nt++)
            #pragma unroll
            for (int q = 0; q < 4; q++) acc[mt][nt][q] = 0.f;

    int nch = Ksub >> 5;

    auto load_stage = [&](int stage, int k0) {
        uint32_t st = sbase + stage * STAGE_BYTES;
        #pragma unroll
        for (int it = 0; it < 2; it++) {
            int q = tid + it * 256;
            int r = q >> 2, c = q & 3;
            uint32_t off = r * ROWPITCH + c * 16;
            long gofs = ((long)r * Kdim + k0 + c * 8);
            CP_A16(st + 0 * ARR_BYTES + off, (const char*)(pAh + gofs));
            CP_A16(st + 1 * ARR_BYTES + off, (const char*)(pAl + gofs));
            CP_A16(st + 2 * ARR_BYTES + off, (const char*)(pBh + gofs));
            CP_A16(st + 3 * ARR_BYTES + off, (const char*)(pBl + gofs));
        }
        CP_COMMIT();
    };

    load_stage(0, 0);
    load_stage(1, 32);

    for (int ic = 0; ic < nch; ic++) {
        if (ic + 2 < nch) { load_stage((ic + 2) % 3, (ic + 2) * 32); CP_WAIT2(); }
        else if (ic + 1 < nch) { CP_WAIT1(); }
        else { CP_WAIT0(); }
        __syncthreads();

        uint32_t st = sbase + (ic % 3) * STAGE_BYTES;
        #pragma unroll
        for (int kk = 0; kk < 2; kk++) {
            uint32_t ah[2][4], al[2][4];
            ldsm4(ah[0], st + 0 * ARR_BYTES + a_off + kk * 32);
            ldsm4(ah[1], st + 0 * ARR_BYTES + a_off + 16 * ROWPITCH + kk * 32);
            ldsm4(al[0], st + 1 * ARR_BYTES + a_off + kk * 32);
            ldsm4(al[1], st + 1 * ARR_BYTES + a_off + 16 * ROWPITCH + kk * 32);
            #pragma unroll
            for (int ntp = 0; ntp < 4; ntp++) {
                uint32_t bh[4], bl[4];
                ldsm4(bh, st + 2 * ARR_BYTES + b_off + ntp * 16 * ROWPITCH + kk * 32);
                ldsm4(bl, st + 3 * ARR_BYTES + b_off + ntp * 16 * ROWPITCH + kk * 32);
                #pragma unroll
                for (int mt = 0; mt < 2; mt++) {
                    mma_f16(acc[mt][2 * ntp],     ah[mt], bh);
                    mma_f16(acc[mt][2 * ntp],     ah[mt], bl);
                    mma_f16(acc[mt][2 * ntp],     al[mt], bh);
                    mma_f16(acc[mt][2 * ntp + 1], ah[mt], bh + 2);
                    mma_f16(acc[mt][2 * ntp + 1], ah[mt], bl + 2);
                    mma_f16(acc[mt][2 * ntp + 1], al[mt], bh + 2);
                }
            }
        }
        __syncthreads();
    }

    #pragma unroll
    for (int mt = 0; mt < 2; mt++) {
        #pragma unroll
        for (int hh = 0; hh < 2; hh++) {
            int rg = m0 + m_warp + mt * 16 + (lane >> 2) + hh * 8;
            long rowoff = outb + (long)rg * ldc;
            #pragma unroll
            for (int nt = 0; nt < 8; nt++) {
                int cg = n0 + n_warp + nt * 8 + (lane & 3) * 2;
                *(float2*)(Cf + rowoff + cg) =
                    make_float2(acc[mt][nt][hh * 2 + 0], acc[mt][nt][hh * 2 + 1]);
            }
        }
    }
}

// =================================================================
// 2-term fp16 GEMM:  C = Ah*(Bh+Bl)^T, fp16 out (for M = Wo * P)
// A single fp16 (no batch), B hi/lo batched.
// =================================================================
__global__ void __launch_bounds__(256) mma_gemm2(
    const fp16* __restrict__ Ag,
    const fp16* __restrict__ Bhg, const fp16* __restrict__ Blg,
    fp16* __restrict__ Ch,
    int Kdim, int ldc, long sB, long sC)
{
    extern __shared__ char smem[];
    uint32_t sbase = smem_u32(smem);
    int tid = threadIdx.x;
    int lane = tid & 31, wid = tid >> 5;
    int b = blockIdx.z;
    int m0 = blockIdx.y * 128, n0 = blockIdx.x * 128;
    int m_warp = (wid & 3) * 32, n_warp = (wid >> 2) * 64;

    const fp16* pA  = Ag  + (long)m0 * Kdim;
    const fp16* pBh = Bhg + b * sB + (long)n0 * Kdim;
    const fp16* pBl = Blg + b * sB + (long)n0 * Kdim;

    uint32_t a_off = (uint32_t)((m_warp + (lane & 15)) * ROWPITCH + (lane >> 4) * 16);
    uint32_t b_off = (uint32_t)((n_warp + (lane & 7) + ((lane >> 4) & 1) * 8) * ROWPITCH
                                + ((lane >> 3) & 1) * 16);

    float acc[2][8][4];
    #pragma unroll
    for (int mt = 0; mt < 2; mt++)
        #pragma unroll
        for (int nt = 0; nt < 8; nt++)
            #pragma unroll
            for (int q = 0; q < 4; q++) acc[mt][nt][q] = 0.f;

    int nch = Kdim >> 5;

    auto load_stage = [&](int stage, int k0) {
        uint32_t st = sbase + stage * T2_STAGE;
        #pragma unroll
        for (int it = 0; it < 2; it++) {
            int q = tid + it * 256;
            int r = q >> 2, c = q & 3;
            uint32_t off = r * ROWPITCH + c * 16;
            long gofs = ((long)r * Kdim + k0 + c * 8);
            CP_A16(st + 0 * ARR_BYTES + off, (const char*)(pA  + gofs));
            CP_A16(st + 1 * ARR_BYTES + off, (const char*)(pBh + gofs));
            CP_A16(st + 2 * ARR_BYTES + off, (const char*)(pBl + gofs));
        }
        CP_COMMIT();
    };

    load_stage(0, 0);
    load_stage(1, 32);

    for (int ic = 0; ic < nch; ic++) {
        if (ic + 2 < nch) { load_stage((ic + 2) % 3, (ic + 2) * 32); CP_WAIT2(); }
        else if (ic + 1 < nch) { CP_WAIT1(); }
        else { CP_WAIT0(); }
        __syncthreads();

        uint32_t st = sbase + (ic % 3) * T2_STAGE;
        #pragma unroll
        for (int kk = 0; kk < 2; kk++) {
            uint32_t a[2][4];
            ldsm4(a[0], st + a_off + kk * 32);
            ldsm4(a[1], st + a_off + 16 * ROWPITCH + kk * 32);
            #pragma unroll
            for (int ntp = 0; ntp < 4; ntp++) {
                uint32_t bh[4], bl[4];
                ldsm4(bh, st + 1 * ARR_BYTES + b_off + ntp * 16 * ROWPITCH + kk * 32);
                ldsm4(bl, st + 2 * ARR_BYTES + b_off + ntp * 16 * ROWPITCH + kk * 32);
                #pragma unroll
                for (int mt = 0; mt < 2; mt++) {
                    mma_f16(acc[mt][2 * ntp],     a[mt], bh);
                    mma_f16(acc[mt][2 * ntp],     a[mt], bl);
                    mma_f16(acc[mt][2 * ntp + 1], a[mt], bh + 2);
                    mma_f16(acc[mt][2 * ntp + 1], a[mt], bl + 2);
                }
            }
        }
        __syncthreads();
    }

    #pragma unroll
    for (int mt = 0; mt < 2; mt++) {
        #pragma unroll
        for (int hh = 0; hh < 2; hh++) {
            int rg = m0 + m_warp + mt * 16 + (lane >> 2) + hh * 8;
            long rowoff = (long)b * sC + (long)rg * ldc;
            #pragma unroll
            for (int nt = 0; nt < 8; nt++) {
                int cg = n0 + n_warp + nt * 8 + (lane & 3) * 2;
                __half2 hv;
                hv.x = __float2half(acc[mt][nt][hh * 2 + 0]);
                hv.y = __float2half(acc[mt][nt][hh * 2 + 1]);
                *(__half2*)(Ch + rowoff + cg) = hv;
            }
        }
    }
}

// ---------------- Gram reduce: sum split-K partials -> fp16 h/l + mirror ----------------
__global__ void gram_reduce() {
    int t = blockIdx.x, b = blockIdx.y;
    int bi = 0;
    while ((bi + 1) * (bi + 2) / 2 <= t) bi++;
    int bj = t - bi * (bi + 1) / 2;
    long mb = (long)b * CH * CH;
    const float* P0 = g_GP + mb;
    const float* P1 = g_GP + (long)BATCH * CH * CH + mb;
    bool mir = (bi != bj);
    for (int e = threadIdx.x; e < 16384; e += 256) {
        int r = bi * 128 + (e >> 7);
        int c = bj * 128 + (e & 127);
        long o = (long)r * CH + c;
        float v = P0[o] + P1[o];
        fp16 h = __float2half(v);
        fp16 l = __float2half(v - __half2float(h));
        g_Gh[mb + o] = h;
        g_Gl[mb + o] = l;
        if (mir) {
            long ot = (long)c * CH + r;
            g_Gh[mb + ot] = h;
            g_Gl[mb + ot] = l;
        }
    }
}

// =================================================================
// 1-term fp16 GEMM (final):  C = A * B^T + bias[r], fp32 out, 2 CTAs/SM
// =================================================================
__global__ void __launch_bounds__(256, 2) mma_gemm_h1(
    const fp16* __restrict__ Ag, const fp16* __restrict__ Bg,
    float* __restrict__ Cf, const float* __restrict__ biasg,
    int Kdim, int ldc, long sA, long sB, long sC)
{
    extern __shared__ char smem[];
    uint32_t sbase = smem_u32(smem);
    int tid = threadIdx.x;
    int lane = tid & 31, wid = tid >> 5;
    int b = blockIdx.z;
    int m0 = blockIdx.y * 128, n0 = blockIdx.x * 128;
    int m_warp = (wid & 3) * 32, n_warp = (wid >> 2) * 64;

    const fp16* pA = Ag + b * sA + (long)m0 * Kdim;
    const fp16* pB = Bg + b * sB + (long)n0 * Kdim;

    uint32_t a_off = (uint32_t)((m_warp + (lane & 15)) * ROWPITCH + (lane >> 4) * 16);
    uint32_t b_off = (uint32_t)((n_warp + (lane & 7) + ((lane >> 4) & 1) * 8) * ROWPITCH
                                + ((lane >> 3) & 1) * 16);

    float acc[2][8][4];
    #pragma unroll
    for (int mt = 0; mt < 2; mt++)
        #pragma unroll
        for (int nt = 0; nt < 8; nt++)
            #pragma unroll
            for (int q = 0; q < 4; q++) acc[mt][nt][q] = 0.f;

    int nch = Kdim >> 5;

    auto load_stage = [&](int stage, int k0) {
        uint32_t st = sbase + stage * H1_STAGE;
        #pragma unroll
        for (int it = 0; it < 4; it++) {
            int q = tid + it * 256;
            int r = q >> 2, c = q & 3;
            int arr = r >> 7, rr = r & 127;
            uint32_t dst = st + arr * ARR_BYTES + rr * ROWPITCH + c * 16;
            const fp16* src = (arr ? pB : pA) + (long)rr * Kdim + k0 + c * 8;
            CP_A16(dst, (const char*)src);
        }
        CP_COMMIT();
    };

    load_stage(0, 0);
    load_stage(1, 32);

    for (int ic = 0; ic < nch; ic++) {
        if (ic + 2 < nch) { load_stage((ic + 2) % 3, (ic + 2) * 32); CP_WAIT2(); }
        else if (ic + 1 < nch) { CP_WAIT1(); }
        else { CP_WAIT0(); }
        __syncthreads();

        uint32_t st = sbase + (ic % 3) * H1_STAGE;
        #pragma unroll
        for (int kk = 0; kk < 2; kk++) {
            uint32_t a[2][4];
            ldsm4(a[0], st + a_off + kk * 32);
            ldsm4(a[1], st + a_off + 16 * ROWPITCH + kk * 32);
            #pragma unroll
            for (int ntp = 0; ntp < 4; ntp++) {
                uint32_t bf[4];
                ldsm4(bf, st + ARR_BYTES + b_off + ntp * 16 * ROWPITCH + kk * 32);
                #pragma unroll
                for (int mt = 0; mt < 2; mt++) {
                    mma_f16(acc[mt][2 * ntp],     a[mt], bf);
                    mma_f16(acc[mt][2 * ntp + 1], a[mt], bf + 2);
                }
            }
        }
        __syncthreads();
    }

    #pragma unroll
    for (int mt = 0; mt < 2; mt++) {
        #pragma unroll
        for (int hh = 0; hh < 2; hh++) {
            int rg = m0 + m_warp + mt * 16 + (lane >> 2) + hh * 8;
            float bias = biasg[b * CH + rg];
            long rowoff = b * sC + (long)rg * ldc;
            #pragma unroll
            for (int nt = 0; nt < 8; nt++) {
                int cg = n0 + n_warp + nt * 8 + (lane & 3) * 2;
                *(float2*)(Cf + rowoff + cg) =
                    make_float2(acc[mt][nt][hh * 2 + 0] + bias,
                                acc[mt][nt][hh * 2 + 1] + bias);
            }
        }
    }
}

// ---------------- x -> fp16 h/l (natural) + fp16 single (transposed) ----------------
__global__ void splitx_kernel(const float* __restrict__ x) {
    __shared__ float xt[32][33];
    int b = blockIdx.z;
    int n0 = blockIdx.x * 32, c0 = blockIdx.y * 32;
    int tx = threadIdx.x, ty = threadIdx.y;
    const float* xb = x + (long)b * CH * NPIX;
    #pragma unroll
    for (int k = 0; k < 4; k++) {
        int c = c0 + ty + k * 8;
        float v = xb[(long)c * NPIX + n0 + tx];
        xt[ty + k * 8][tx] = v;
        fp16 h = __float2half(v);
        fp16 l = __float2half(v - __half2float(h));
        long idx = ((long)b * CH + c) * NPIX + n0 + tx;
        g_Xh[idx] = h;
        g_Xl[idx] = l;
    }
    __syncthreads();
    #pragma unroll
    for (int k = 0; k < 4; k++) {
        int n = n0 + ty + k * 8;
        long idx = ((long)b * NPIX + n) * CH + c0 + tx;
        g_Xt[idx] = __float2half(xt[tx][ty + k * 8]);
    }
}

// ---------------- elementwise split fp32 -> fp16 h/l ----------------
__global__ void splitw_kernel(const float* __restrict__ src,
                              fp16* __restrict__ oh, fp16* __restrict__ ol) {
    long i = ((long)blockIdx.x * 256 + threadIdx.x) * 4;
    float4 v = *(const float4*)(src + i);
    fp16 h0 = __float2half(v.x), h1 = __float2half(v.y);
    fp16 h2 = __float2half(v.z), h3 = __float2half(v.w);
    oh[i + 0] = h0; ol[i + 0] = __float2half(v.x - __half2float(h0));
    oh[i + 1] = h1; ol[i + 1] = __float2half(v.y - __half2float(h1));
    oh[i + 2] = h2; ol[i + 2] = __float2half(v.z - __half2float(h2));
    oh[i + 3] = h3; ol[i + 3] = __float2half(v.w - __half2float(h3));
}

// ---------------- fp32 -> fp16 single convert ----------------
__global__ void cvt_kernel(const float* __restrict__ src, fp16* __restrict__ dst) {
    long i = ((long)blockIdx.x * 256 + threadIdx.x) * 4;
    float4 v = *(const float4*)(src + i);
    __half2 a, b;
    a.x = __float2half(v.x); a.y = __float2half(v.y);
    b.x = __float2half(v.z); b.y = __float2half(v.w);
    *(__half2*)(dst + i)     = a;
    *(__half2*)(dst + i + 2) = b;
}

// ---------------- row sums ----------------
__global__ void rowsum_kernel(const float* __restrict__ x) {
    int c = blockIdx.x, b = blockIdx.y;
    const float* row = x + ((long)b * CH + c) * NPIX;
    float s = 0.f;
    for (int n = threadIdx.x * 4; n < NPIX; n += 256 * 4) {
        float4 v = *(const float4*)(row + n);
        s += v.x + v.y + v.z + v.w;
    }
    __shared__ float red[256];
    red[threadIdx.x] = s;
    __syncthreads();
    for (int off = 128; off > 0; off >>= 1) {
        if (threadIdx.x < off) red[threadIdx.x] += red[threadIdx.x + off];
        __syncthreads();
    }
    if (threadIdx.x == 0) g_s[b * CH + c] = red[0];
}

// ---------------- qs = Wq*s, ks = Wk*s ----------------
__global__ void qsks_kernel(const float* __restrict__ wq, const float* __restrict__ wk) {
    int b = blockIdx.x;
    __shared__ float sv[CH];
    for (int i = threadIdx.x; i < CH; i += 256) sv[i] = g_s[b * CH + i];
    __syncthreads();
    for (int o = threadIdx.x; o < CH; o += 256) {
        const float* wr = wq + (long)o * CH;
        const float* kr = wk + (long)o * CH;
        float aq = 0.f, ak = 0.f;
        for (int c = 0; c < CH; c++) { aq += wr[c] * sv[c]; ak += kr[c] * sv[c]; }
        g_qs[b * CH + o] = aq;
        g_ks[b * CH + o] = ak;
    }
}

// ---------------- energy blocks + softmax + abv ----------------
__global__ void __launch_bounds__(256) attn_kernel(
    const float* __restrict__ wk, const float* __restrict__ bq,
    const float* __restrict__ bk, const float* __restrict__ bv)
{
    int h = blockIdx.x, b = blockIdx.y;
    __shared__ float Ts[16][64];
    __shared__ float Ks[16][64];
    __shared__ float Es[64][65];
    __shared__ float qv[64], kvv[64], bqv[64], bkv[64], bvv[64];
    int tid = threadIdx.x;
    if (tid < 64) {
        qv[tid]  = g_qs[b * CH + h * HD + tid];
        kvv[tid] = g_ks[b * CH + h * HD + tid];
        bqv[tid] = bq[h * HD + tid];
        bkv[tid] = bk[h * HD + tid];
        bvv[tid] = bv[h * HD + tid];
    }
    const float* Tb = g_T + ((long)b * CH + h * HD) * CH;
    const float* Kb = wk + (long)(h * HD) * CH;
    int lrow = tid >> 2;
    int lcol = (tid & 3) * 4;
    int tx = tid & 15, ty = tid >> 4;
    float acc[4][4];
    #pragma unroll
    for (int i = 0; i < 4; i++)
        #pragma unroll
        for (int j = 0; j < 4; j++) acc[i][j] = 0.f;

    for (int a0 = 0; a0 < CH; a0 += 16) {
        float4 tv = *(const float4*)(Tb + (long)lrow * CH + a0 + lcol);
        Ts[lcol + 0][lrow] = tv.x; Ts[lcol + 1][lrow] = tv.y;
        Ts[lcol + 2][lrow] = tv.z; Ts[lcol + 3][lrow] = tv.w;
        float4 kv4 = *(const float4*)(Kb + (long)lrow * CH + a0 + lcol);
        Ks[lcol + 0][lrow] = kv4.x; Ks[lcol + 1][lrow] = kv4.y;
        Ks[lcol + 2][lrow] = kv4.z; Ks[lcol + 3][lrow] = kv4.w;
        __syncthreads();
        #pragma unroll
        for (int kk = 0; kk < 16; kk++) {
            float ra[4], rb[4];
            *(float4*)&ra[0] = *(const float4*)&Ts[kk][ty * 4];
            *(float4*)&rb[0] = *(const float4*)&Ks[kk][tx * 4];
            #pragma unroll
            for (int i = 0; i < 4; i++)
                #pragma unroll
                for (int j = 0; j < 4; j++)
                    acc[i][j] += ra[i] * rb[j];
        }
        __syncthreads();
    }
    #pragma unroll
    for (int i = 0; i < 4; i++) {
        int gi = ty * 4 + i;
        #pragma unroll
        for (int j = 0; j < 4; j++) {
            int gj = tx * 4 + j;
            float e = acc[i][j] + qv[gi] * bkv[gj] + bqv[gi] * kvv[gj]
                      + 4096.f * bqv[gi] * bkv[gj];
            Es[gi][gj] = e * ATT_SCALE;
        }
    }
    __syncthreads();
    if (tid < 64) {
        int i = tid;
        float m = -1e30f;
        for (int j = 0; j < 64; j++) m = fmaxf(m, Es[i][j]);
        float sum = 0.f;
        for (int j = 0; j < 64; j++) {
            float ex = expf(Es[i][j] - m);
            Es[i][j] = ex;
            sum += ex;
        }
        float inv = 1.f / sum;
        float ab = 0.f;
        float* Arow = g_A + (((long)b * NH + h) * HD + i) * HD;
        for (int j = 0; j < 64; j++) {
            float a = Es[i][j] * inv;
            Arow[j] = a;
            ab += a * bvv[j];
        }
        g_abv[b * CH + h * HD + i] = ab;
    }
}

// ---------------- Pt = (A_bd * Wv)^T, fp16 hi/lo [c][r] ----------------
__global__ void __launch_bounds__(256) pk_kernel(const float* __restrict__ wv) {
    int h = blockIdx.x, b = blockIdx.y;
    __shared__ float Ash[64][64];
    __shared__ float Bv[64][64];
    int tid = threadIdx.x;
    const float* Ab = g_A + ((long)b * NH + h) * HD * HD;
    for (int r = tid; r < 64 * 16; r += 256) {
        int i = r >> 4, q = (r & 15) * 4;
        float4 v = *(const float4*)(Ab + i * 64 + q);
        Ash[q + 0][i] = v.x; Ash[q + 1][i] = v.y;
        Ash[q + 2][i] = v.z; Ash[q + 3][i] = v.w;
    }
    int tx = tid & 15, ty = tid >> 4;
    for (int cc = 0; cc < CH; cc += 64) {
        __syncthreads();
        for (int r = tid; r < 64 * 16; r += 256) {
            int j = r >> 4, q = (r & 15) * 4;
            *(float4*)&Bv[j][q] = *(const float4*)(wv + (long)(h * HD + j) * CH + cc + q);
        }
        __syncthreads();
        float acc[4][4];
        #pragma unroll
        for (int i = 0; i < 4; i++)
            #pragma unroll
            for (int j = 0; j < 4; j++) acc[i][j] = 0.f;
        #pragma unroll 8
        for (int j = 0; j < 64; j++) {
            float ra[4], rb[4];
            *(float4*)&ra[0] = *(const float4*)&Ash[j][ty * 4];
            *(float4*)&rb[0] = *(const float4*)&Bv[j][tx * 4];
            #pragma unroll
            for (int i = 0; i < 4; i++)
                #pragma unroll
                for (int u = 0; u < 4; u++)
                    acc[i][u] += ra[i] * rb[u];
        }
        #pragma unroll
        for (int u = 0; u < 4; u++) {
            int c = cc + tx * 4 + u;
            long base = ((long)b * CH + c) * CH + h * HD + ty * 4;
            float v0 = acc[0][u], v1 = acc[1][u], v2 = acc[2][u], v3 = acc[3][u];
            fp16 h0 = __float2half(v0), h1 = __float2half(v1);
            fp16 h2 = __float2half(v2), h3 = __float2half(v3);
            __half2 a0, a1, b0, b1;
            a0.x = h0; a0.y = h1; a1.x = h2; a1.y = h3;
            b0.x = __float2half(v0 - __half2float(h0));
            b0.y = __float2half(v1 - __half2float(h1));
            b1.x = __float2half(v2 - __half2float(h2));
            b1.y = __float2half(v3 - __half2float(h3));
            *(__half2*)(g_Pth + base)     = a0;
            *(__half2*)(g_Pth + base + 2) = a1;
            *(__half2*)(g_Ptl + base)     = b0;
            *(__half2*)(g_Ptl + base + 2) = b1;
        }
    }
}

// ---------------- c[b] = Wo * abv[b] + bo ----------------
__global__ void cvec_kernel(const float* __restrict__ wo, const float* __restrict__ bo) {
    int b = blockIdx.x;
    __shared__ float sv[CH];
    for (int i = threadIdx.x; i < CH; i += 256) sv[i] = g_abv[b * CH + i];
    __syncthreads();
    for (int o = threadIdx.x; o < CH; o += 256) {
        const float* wr = wo + (long)o * CH;
        float sum = bo[o];
        for (int c = 0; c < CH; c++) sum += wr[c] * sv[c];
        g_c[b * CH + o] = sum;
    }
}

// ---------------- launch ----------------
extern "C" void kernel_launch(void* const* d_in, const int* in_sizes, int n_in,
                              void* d_out, int out_size) {
    const float* x  = (const float*)d_in[0];
    const float* wq = (const float*)d_in[1];
    const float* bq = (const float*)d_in[2];
    const float* wk = (const float*)d_in[3];
    const float* bk = (const float*)d_in[4];
    const float* wv = (const float*)d_in[5];
    const float* bv = (const float*)d_in[6];
    const float* wo = (const float*)d_in[7];
    const float* bo = (const float*)d_in[8];
    float* y = (float*)d_out;

    float *pT, *pGP, *pc;
    fp16 *pXh, *pXl, *pXt, *pGh, *pGl, *pPth, *pPtl, *pMh;
    fp16 *pWqh, *pWql, *pWoh;
    cudaGetSymbolAddress((void**)&pT,  g_T);
    cudaGetSymbolAddress((void**)&pGP, g_GP);
    cudaGetSymbolAddress((void**)&pc,  g_c);
    cudaGetSymbolAddress((void**)&pXh, g_Xh);
    cudaGetSymbolAddress((void**)&pXl, g_Xl);
    cudaGetSymbolAddress((void**)&pXt, g_Xt);
    cudaGetSymbolAddress((void**)&pGh, g_Gh);
    cudaGetSymbolAddress((void**)&pGl, g_Gl);
    cudaGetSymbolAddress((void**)&pPth, g_Pth);
    cudaGetSymbolAddress((void**)&pPtl, g_Ptl);
    cudaGetSymbolAddress((void**)&pMh, g_Mh);
    cudaGetSymbolAddress((void**)&pWqh, g_Wqh);
    cudaGetSymbolAddress((void**)&pWql, g_Wql);
    cudaGetSymbolAddress((void**)&pWoh, g_Woh);

    cudaFuncSetAttribute((const void*)mma_gemm<true>,
                         cudaFuncAttributeMaxDynamicSharedMemorySize, MMA_SMEM);
    cudaFuncSetAttribute((const void*)mma_gemm<false>,
                         cudaFuncAttributeMaxDynamicSharedMemorySize, MMA_SMEM);
    cudaFuncSetAttribute((const void*)mma_gemm2,
                         cudaFuncAttributeMaxDynamicSharedMemorySize, T2_SMEM);
    cudaFuncSetAttribute((const void*)mma_gemm_h1,
                         cudaFuncAttributeMaxDynamicSharedMemorySize, H1_SMEM);

    // 1-3. prep (positions 1-3)
    splitx_kernel<<<dim3(NPIX / 32, CH / 32, BATCH), dim3(32, 8)>>>(x);
    splitw_kernel<<<(CH * CH) / 1024, 256>>>(wq, pWqh, pWql);
    cvt_kernel<<<(CH * CH) / 1024, 256>>>(wo, pWoh);

    // 4. Gram partials (launch #4 -> ncu capture target).  K = 4096
    mma_gemm<true><<<dim3(21, 2, BATCH), 256, MMA_SMEM>>>(
        pXh, pXl, pXh, pXl, pGP,
        NPIX, NPIX / 2, CH, (long)CH * NPIX, (long)CH * NPIX, (long)CH * CH);

    // 5-6. row sums + reduce partials
    rowsum_kernel<<<dim3(CH, BATCH), 256>>>(x);
    gram_reduce<<<dim3(21, BATCH), 256>>>();

    // 7. qs/ks
    qsks_kernel<<<BATCH, 256>>>(wq, wk);

    // 8. T[b] = Wq * G[b]  (fp16 3-term).  K = 768
    mma_gemm<false><<<dim3(6, 6, BATCH), 256, MMA_SMEM>>>(
        pWqh, pWql, pGh, pGl, pT,
        CH, CH, CH, 0L, (long)CH * CH, (long)CH * CH);

    // 9. attention
    attn_kernel<<<dim3(NH, BATCH), 256>>>(wk, bq, bk, bv);

    // 10. Pt fp16 h/l
    pk_kernel<<<dim3(NH, BATCH), 256>>>(wv);

    // 11. c[b] = Wo * abv + bo
    cvec_kernel<<<BATCH, 256>>>(wo, bo);

    // 12. M[b] = Wo * P[b]  (fp16 2-term, fp16 out).  K = 768
    mma_gemm2<<<dim3(6, 6, BATCH), 256, T2_SMEM>>>(
        pWoh, pPth, pPtl, pMh,
        CH, CH, (long)CH * CH, (long)CH * CH);

    // 13. y[b] = M[b] * X[b] + c[b]  (fp16 1-term).  K = 768
    mma_gemm_h1<<<dim3(NPIX / 128, 6, BATCH), 256, H1_SMEM>>>(
        pMh, pXt, y, pc,
        CH, NPIX, (long)CH * CH, (long)NPIX * CH, (long)CH * NPIX);
}

// round 10
// speedup vs baseline: 2.5172x; 1.0530x over previous
#include <cuda_runtime.h>
#include <cuda_fp16.h>
#include <math.h>
#include <stdint.h>

#define BATCH 16
#define CH    768
#define NPIX  4096
#define NH    12
#define HD    64
#define ATT_SCALE 0.125f   // HD^-0.5

typedef __half fp16;

// ---------------- scratch (device globals; no runtime allocation) ----------------
__device__ float g_T [BATCH * CH * CH];       // T = Wq * G
__device__ float g_GP[2L * BATCH * CH * CH];  // Gram split-K partials
__device__ float g_A[BATCH * NH * HD * HD];
__device__ float g_s[BATCH * CH];
__device__ float g_qs[BATCH * CH];
__device__ float g_ks[BATCH * CH];
__device__ float g_abv[BATCH * CH];
__device__ float g_c[BATCH * CH];

__device__ __align__(16) fp16 g_Xh [BATCH * CH * NPIX];  // fp16 hi of X [b][c][n]
__device__ __align__(16) fp16 g_Xl [BATCH * CH * NPIX];  // fp16 lo
__device__ __align__(16) fp16 g_Xt [BATCH * NPIX * CH];  // fp16(X) transposed [b][n][c]
__device__ __align__(16) fp16 g_Gh [BATCH * CH * CH];
__device__ __align__(16) fp16 g_Gl [BATCH * CH * CH];
__device__ __align__(16) fp16 g_Pth[BATCH * CH * CH];    // (A_bd*Wv)^T hi [c][r]
__device__ __align__(16) fp16 g_Ptl[BATCH * CH * CH];
__device__ __align__(16) fp16 g_Mh [BATCH * CH * CH];    // fp16(M) single
__device__ __align__(16) fp16 g_Wqh[CH * CH];
__device__ __align__(16) fp16 g_Wql[CH * CH];
__device__ __align__(16) fp16 g_Woh[CH * CH];            // fp16(Wo) single

// ---------------- asm helpers (sm_80-compatible only) ----------------
__device__ __forceinline__ uint32_t smem_u32(const void* p) {
    uint32_t a;
    asm("{ .reg .u64 t; cvta.to.shared.u64 t, %1; cvt.u32.u64 %0, t; }" : "=r"(a) : "l"(p));
    return a;
}
__device__ __forceinline__ void ldsm4(uint32_t* r, uint32_t a) {
    asm volatile("ldmatrix.sync.aligned.m8n8.x4.shared.b16 {%0,%1,%2,%3}, [%4];"
                 : "=r"(r[0]), "=r"(r[1]), "=r"(r[2]), "=r"(r[3]) : "r"(a));
}
__device__ __forceinline__ void mma_f16(float* c, const uint32_t* a, const uint32_t* b) {
    asm volatile(
        "mma.sync.aligned.m16n8k16.row.col.f32.f16.f16.f32 "
        "{%0,%1,%2,%3}, {%4,%5,%6,%7}, {%8,%9}, {%0,%1,%2,%3};"
        : "+f"(c[0]), "+f"(c[1]), "+f"(c[2]), "+f"(c[3])
        : "r"(a[0]), "r"(a[1]), "r"(a[2]), "r"(a[3]), "r"(b[0]), "r"(b[1]));
}
#define CP_A16(dst, src) asm volatile( \
    "cp.async.cg.shared.global [%0], [%1], 16;" :: "r"(dst), "l"(src))
#define CP_COMMIT() asm volatile("cp.async.commit_group;" ::: "memory")
#define CP_WAIT0()  asm volatile("cp.async.wait_group 0;" ::: "memory")
#define CP_WAIT1()  asm volatile("cp.async.wait_group 1;" ::: "memory")
#define CP_WAIT2()  asm volatile("cp.async.wait_group 2;" ::: "memory")

// ---------------- smem geometry ----------------
#define ROWPITCH 80
#define ARR_BYTES 10240
#define STAGE_BYTES (4 * ARR_BYTES)          // 3-term: AH AL BH BL
#define MMA_SMEM (2 * STAGE_BYTES)           // 81920  -> 2 CTAs/SM
#define T2_STAGE (3 * ARR_BYTES)             // 2-term: AH BH BL
#define T2_SMEM (2 * T2_STAGE)               // 61440  -> 2 CTAs/SM
#define H1_STAGE (2 * ARR_BYTES)             // 1-term: A B
#define H1_SMEM (3 * H1_STAGE)               // 61440  -> 2 CTAs/SM

// =================================================================
// 3-term fp16 GEMM:  C(128x128) = Ah*Bh^T + Ah*Bl^T + Al*Bh^T  (fp32 out)
// 2-stage pipeline, 2 CTAs/SM.
// MIRROR: lower-triangle tile decode + split-K partial output.
// =================================================================
template<bool MIRROR>
__global__ void __launch_bounds__(256, 2) mma_gemm(
    const fp16* __restrict__ Ahg, const fp16* __restrict__ Alg,
    const fp16* __restrict__ Bhg, const fp16* __restrict__ Blg,
    float* __restrict__ Cf,
    int Kdim, int Ksub, int ldc, long sA, long sB, long sC)
{
    extern __shared__ char smem[];
    uint32_t sbase = smem_u32(smem);
    int tid = threadIdx.x;
    int lane = tid & 31, wid = tid >> 5;
    int b = blockIdx.z;
    int m0, n0, kbase = 0;
    long outb;
    if (MIRROR) {
        int t = blockIdx.x, bi = 0;
        while ((bi + 1) * (bi + 2) / 2 <= t) bi++;
        int bj = t - bi * (bi + 1) / 2;
        m0 = bi * 128; n0 = bj * 128;
        kbase = blockIdx.y * Ksub;
        outb = ((long)blockIdx.y * BATCH + b) * sC;
    } else {
        m0 = blockIdx.y * 128; n0 = blockIdx.x * 128;
        outb = (long)b * sC;
    }
    int m_warp = (wid & 3) * 32, n_warp = (wid >> 2) * 64;

    const fp16* pAh = Ahg + b * sA + (long)m0 * Kdim + kbase;
    const fp16* pAl = Alg + b * sA + (long)m0 * Kdim + kbase;
    const fp16* pBh = Bhg + b * sB + (long)n0 * Kdim + kbase;
    const fp16* pBl = Blg + b * sB + (long)n0 * Kdim + kbase;

    uint32_t a_off = (uint32_t)((m_warp + (lane & 15)) * ROWPITCH + (lane >> 4) * 16);
    uint32_t b_off = (uint32_t)((n_warp + (lane & 7) + ((lane >> 4) & 1) * 8) * ROWPITCH
                                + ((lane >> 3) & 1) * 16);

    float acc[2][8][4];
    #pragma unroll
    for (int mt = 0; mt < 2; mt++)
        #pragma unroll
        for (int nt = 0; nt < 8; nt++)
            #pragma unroll
            for (int q = 0; q < 4; q++) acc[mt][nt][q] = 0.f;

    int nch = Ksub >> 5;

    auto load_stage = [&](int stage, int k0) {
        uint32_t st = sbase + stage * STAGE_BYTES;
        #pragma unroll
        for (int it = 0; it < 2; it++) {
            int q = tid + it * 256;
            int r = q >> 2, c = q & 3;
            uint32_t off = r * ROWPITCH + c * 16;
            long gofs = ((long)r * Kdim + k0 + c * 8);
            CP_A16(st + 0 * ARR_BYTES + off, (const char*)(pAh + gofs));
            CP_A16(st + 1 * ARR_BYTES + off, (const char*)(pAl + gofs));
            CP_A16(st + 2 * ARR_BYTES + off, (const char*)(pBh + gofs));
            CP_A16(st + 3 * ARR_BYTES + off, (const char*)(pBl + gofs));
        }
        CP_COMMIT();
    };

    load_stage(0, 0);

    for (int ic = 0; ic < nch; ic++) {
        int p = ic & 1;
        if (ic + 1 < nch) { load_stage(p ^ 1, (ic + 1) * 32); CP_WAIT1(); }
        else              { CP_WAIT0(); }
        __syncthreads();

        uint32_t st = sbase + p * STAGE_BYTES;
        #pragma unroll
        for (int kk = 0; kk < 2; kk++) {
            uint32_t ah[2][4], al[2][4];
            ldsm4(ah[0], st + 0 * ARR_BYTES + a_off + kk * 32);
            ldsm4(ah[1], st + 0 * ARR_BYTES + a_off + 16 * ROWPITCH + kk * 32);
            ldsm4(al[0], st + 1 * ARR_BYTES + a_off + kk * 32);
            ldsm4(al[1], st + 1 * ARR_BYTES + a_off + 16 * ROWPITCH + kk * 32);
            #pragma unroll
            for (int ntp = 0; ntp < 4; ntp++) {
                uint32_t bh[4], bl[4];
                ldsm4(bh, st + 2 * ARR_BYTES + b_off + ntp * 16 * ROWPITCH + kk * 32);
                ldsm4(bl, st + 3 * ARR_BYTES + b_off + ntp * 16 * ROWPITCH + kk * 32);
                #pragma unroll
                for (int mt = 0; mt < 2; mt++) {
                    mma_f16(acc[mt][2 * ntp],     ah[mt], bh);
                    mma_f16(acc[mt][2 * ntp],     ah[mt], bl);
                    mma_f16(acc[mt][2 * ntp],     al[mt], bh);
                    mma_f16(acc[mt][2 * ntp + 1], ah[mt], bh + 2);
                    mma_f16(acc[mt][2 * ntp + 1], ah[mt], bl + 2);
                    mma_f16(acc[mt][2 * ntp + 1], al[mt], bh + 2);
                }
            }
        }
        __syncthreads();
    }

    #pragma unroll
    for (int mt = 0; mt < 2; mt++) {
        #pragma unroll
        for (int hh = 0; hh < 2; hh++) {
            int rg = m0 + m_warp + mt * 16 + (lane >> 2) + hh * 8;
            long rowoff = outb + (long)rg * ldc;
            #pragma unroll
            for (int nt = 0; nt < 8; nt++) {
                int cg = n0 + n_warp + nt * 8 + (lane & 3) * 2;
                *(float2*)(Cf + rowoff + cg) =
                    make_float2(acc[mt][nt][hh * 2 + 0], acc[mt][nt][hh * 2 + 1]);
            }
        }
    }
}

// =================================================================
// 2-term fp16 GEMM:  C = Ah*(Bh+Bl)^T, fp16 out (for M = Wo * P)
// 2-stage, 2 CTAs/SM. A single fp16 (no batch), B hi/lo batched.
// =================================================================
__global__ void __launch_bounds__(256, 2) mma_gemm2(
    const fp16* __restrict__ Ag,
    const fp16* __restrict__ Bhg, const fp16* __restrict__ Blg,
    fp16* __restrict__ Ch,
    int Kdim, int ldc, long sB, long sC)
{
    extern __shared__ char smem[];
    uint32_t sbase = smem_u32(smem);
    int tid = threadIdx.x;
    int lane = tid & 31, wid = tid >> 5;
    int b = blockIdx.z;
    int m0 = blockIdx.y * 128, n0 = blockIdx.x * 128;
    int m_warp = (wid & 3) * 32, n_warp = (wid >> 2) * 64;

    const fp16* pA  = Ag  + (long)m0 * Kdim;
    const fp16* pBh = Bhg + b * sB + (long)n0 * Kdim;
    const fp16* pBl = Blg + b * sB + (long)n0 * Kdim;

    uint32_t a_off = (uint32_t)((m_warp + (lane & 15)) * ROWPITCH + (lane >> 4) * 16);
    uint32_t b_off = (uint32_t)((n_warp + (lane & 7) + ((lane >> 4) & 1) * 8) * ROWPITCH
                                + ((lane >> 3) & 1) * 16);

    float acc[2][8][4];
    #pragma unroll
    for (int mt = 0; mt < 2; mt++)
        #pragma unroll
        for (int nt = 0; nt < 8; nt++)
            #pragma unroll
            for (int q = 0; q < 4; q++) acc[mt][nt][q] = 0.f;

    int nch = Kdim >> 5;

    auto load_stage = [&](int stage, int k0) {
        uint32_t st = sbase + stage * T2_STAGE;
        #pragma unroll
        for (int it = 0; it < 2; it++) {
            int q = tid + it * 256;
            int r = q >> 2, c = q & 3;
            uint32_t off = r * ROWPITCH + c * 16;
            long gofs = ((long)r * Kdim + k0 + c * 8);
            CP_A16(st + 0 * ARR_BYTES + off, (const char*)(pA  + gofs));
            CP_A16(st + 1 * ARR_BYTES + off, (const char*)(pBh + gofs));
            CP_A16(st + 2 * ARR_BYTES + off, (const char*)(pBl + gofs));
        }
        CP_COMMIT();
    };

    load_stage(0, 0);

    for (int ic = 0; ic < nch; ic++) {
        int p = ic & 1;
        if (ic + 1 < nch) { load_stage(p ^ 1, (ic + 1) * 32); CP_WAIT1(); }
        else              { CP_WAIT0(); }
        __syncthreads();

        uint32_t st = sbase + p * T2_STAGE;
        #pragma unroll
        for (int kk = 0; kk < 2; kk++) {
            uint32_t a[2][4];
            ldsm4(a[0], st + a_off + kk * 32);
            ldsm4(a[1], st + a_off + 16 * ROWPITCH + kk * 32);
            #pragma unroll
            for (int ntp = 0; ntp < 4; ntp++) {
                uint32_t bh[4], bl[4];
                ldsm4(bh, st + 1 * ARR_BYTES + b_off + ntp * 16 * ROWPITCH + kk * 32);
                ldsm4(bl, st + 2 * ARR_BYTES + b_off + ntp * 16 * ROWPITCH + kk * 32);
                #pragma unroll
                for (int mt = 0; mt < 2; mt++) {
                    mma_f16(acc[mt][2 * ntp],     a[mt], bh);
                    mma_f16(acc[mt][2 * ntp],     a[mt], bl);
                    mma_f16(acc[mt][2 * ntp + 1], a[mt], bh + 2);
                    mma_f16(acc[mt][2 * ntp + 1], a[mt], bl + 2);
                }
            }
        }
        __syncthreads();
    }

    #pragma unroll
    for (int mt = 0; mt < 2; mt++) {
        #pragma unroll
        for (int hh = 0; hh < 2; hh++) {
            int rg = m0 + m_warp + mt * 16 + (lane >> 2) + hh * 8;
            long rowoff = (long)b * sC + (long)rg * ldc;
            #pragma unroll
            for (int nt = 0; nt < 8; nt++) {
                int cg = n0 + n_warp + nt * 8 + (lane & 3) * 2;
                __half2 hv;
                hv.x = __float2half(acc[mt][nt][hh * 2 + 0]);
                hv.y = __float2half(acc[mt][nt][hh * 2 + 1]);
                *(__half2*)(Ch + rowoff + cg) = hv;
            }
        }
    }
}

// ---------------- Gram reduce: sum split-K partials -> fp16 h/l + mirror ----------------
__global__ void gram_reduce() {
    int t = blockIdx.x, b = blockIdx.y;
    int bi = 0;
    while ((bi + 1) * (bi + 2) / 2 <= t) bi++;
    int bj = t - bi * (bi + 1) / 2;
    long mb = (long)b * CH * CH;
    const float* P0 = g_GP + mb;
    const float* P1 = g_GP + (long)BATCH * CH * CH + mb;
    bool mir = (bi != bj);
    for (int e = threadIdx.x; e < 16384; e += 256) {
        int r = bi * 128 + (e >> 7);
        int c = bj * 128 + (e & 127);
        long o = (long)r * CH + c;
        float v = P0[o] + P1[o];
        fp16 h = __float2half(v);
        fp16 l = __float2half(v - __half2float(h));
        g_Gh[mb + o] = h;
        g_Gl[mb + o] = l;
        if (mir) {
            long ot = (long)c * CH + r;
            g_Gh[mb + ot] = h;
            g_Gl[mb + ot] = l;
        }
    }
}

// =================================================================
// 1-term fp16 GEMM (final):  C = A * B^T + bias[r], fp32 out, 2 CTAs/SM
// =================================================================
__global__ void __launch_bounds__(256, 2) mma_gemm_h1(
    const fp16* __restrict__ Ag, const fp16* __restrict__ Bg,
    float* __restrict__ Cf, const float* __restrict__ biasg,
    int Kdim, int ldc, long sA, long sB, long sC)
{
    extern __shared__ char smem[];
    uint32_t sbase = smem_u32(smem);
    int tid = threadIdx.x;
    int lane = tid & 31, wid = tid >> 5;
    int b = blockIdx.z;
    int m0 = blockIdx.y * 128, n0 = blockIdx.x * 128;
    int m_warp = (wid & 3) * 32, n_warp = (wid >> 2) * 64;

    const fp16* pA = Ag + b * sA + (long)m0 * Kdim;
    const fp16* pB = Bg + b * sB + (long)n0 * Kdim;

    uint32_t a_off = (uint32_t)((m_warp + (lane & 15)) * ROWPITCH + (lane >> 4) * 16);
    uint32_t b_off = (uint32_t)((n_warp + (lane & 7) + ((lane >> 4) & 1) * 8) * ROWPITCH
                                + ((lane >> 3) & 1) * 16);

    float acc[2][8][4];
    #pragma unroll
    for (int mt = 0; mt < 2; mt++)
        #pragma unroll
        for (int nt = 0; nt < 8; nt++)
            #pragma unroll
            for (int q = 0; q < 4; q++) acc[mt][nt][q] = 0.f;

    int nch = Kdim >> 5;

    auto load_stage = [&](int stage, int k0) {
        uint32_t st = sbase + stage * H1_STAGE;
        #pragma unroll
        for (int it = 0; it < 4; it++) {
            int q = tid + it * 256;
            int r = q >> 2, c = q & 3;
            int arr = r >> 7, rr = r & 127;
            uint32_t dst = st + arr * ARR_BYTES + rr * ROWPITCH + c * 16;
            const fp16* src = (arr ? pB : pA) + (long)rr * Kdim + k0 + c * 8;
            CP_A16(dst, (const char*)src);
        }
        CP_COMMIT();
    };

    load_stage(0, 0);
    load_stage(1, 32);

    for (int ic = 0; ic < nch; ic++) {
        if (ic + 2 < nch) { load_stage((ic + 2) % 3, (ic + 2) * 32); CP_WAIT2(); }
        else if (ic + 1 < nch) { CP_WAIT1(); }
        else { CP_WAIT0(); }
        __syncthreads();

        uint32_t st = sbase + (ic % 3) * H1_STAGE;
        #pragma unroll
        for (int kk = 0; kk < 2; kk++) {
            uint32_t a[2][4];
            ldsm4(a[0], st + a_off + kk * 32);
            ldsm4(a[1], st + a_off + 16 * ROWPITCH + kk * 32);
            #pragma unroll
            for (int ntp = 0; ntp < 4; ntp++) {
                uint32_t bf[4];
                ldsm4(bf, st + ARR_BYTES + b_off + ntp * 16 * ROWPITCH + kk * 32);
                #pragma unroll
                for (int mt = 0; mt < 2; mt++) {
                    mma_f16(acc[mt][2 * ntp],     a[mt], bf);
                    mma_f16(acc[mt][2 * ntp + 1], a[mt], bf + 2);
                }
            }
        }
        __syncthreads();
    }

    #pragma unroll
    for (int mt = 0; mt < 2; mt++) {
        #pragma unroll
        for (int hh = 0; hh < 2; hh++) {
            int rg = m0 + m_warp + mt * 16 + (lane >> 2) + hh * 8;
            float bias = biasg[b * CH + rg];
            long rowoff = b * sC + (long)rg * ldc;
            #pragma unroll
            for (int nt = 0; nt < 8; nt++) {
                int cg = n0 + n_warp + nt * 8 + (lane & 3) * 2;
                *(float2*)(Cf + rowoff + cg) =
                    make_float2(acc[mt][nt][hh * 2 + 0] + bias,
                                acc[mt][nt][hh * 2 + 1] + bias);
            }
        }
    }
}

// ---------------- x -> fp16 h/l (natural) + fp16 single (transposed) ----------------
__global__ void splitx_kernel(const float* __restrict__ x) {
    __shared__ float xt[32][33];
    int b = blockIdx.z;
    int n0 = blockIdx.x * 32, c0 = blockIdx.y * 32;
    int tx = threadIdx.x, ty = threadIdx.y;
    const float* xb = x + (long)b * CH * NPIX;
    #pragma unroll
    for (int k = 0; k < 4; k++) {
        int c = c0 + ty + k * 8;
        float v = xb[(long)c * NPIX + n0 + tx];
        xt[ty + k * 8][tx] = v;
        fp16 h = __float2half(v);
        fp16 l = __float2half(v - __half2float(h));
        long idx = ((long)b * CH + c) * NPIX + n0 + tx;
        g_Xh[idx] = h;
        g_Xl[idx] = l;
    }
    __syncthreads();
    #pragma unroll
    for (int k = 0; k < 4; k++) {
        int n = n0 + ty + k * 8;
        long idx = ((long)b * NPIX + n) * CH + c0 + tx;
        g_Xt[idx] = __float2half(xt[tx][ty + k * 8]);
    }
}

// ---------------- elementwise split fp32 -> fp16 h/l ----------------
__global__ void splitw_kernel(const float* __restrict__ src,
                              fp16* __restrict__ oh, fp16* __restrict__ ol) {
    long i = ((long)blockIdx.x * 256 + threadIdx.x) * 4;
    float4 v = *(const float4*)(src + i);
    fp16 h0 = __float2half(v.x), h1 = __float2half(v.y);
    fp16 h2 = __float2half(v.z), h3 = __float2half(v.w);
    oh[i + 0] = h0; ol[i + 0] = __float2half(v.x - __half2float(h0));
    oh[i + 1] = h1; ol[i + 1] = __float2half(v.y - __half2float(h1));
    oh[i + 2] = h2; ol[i + 2] = __float2half(v.z - __half2float(h2));
    oh[i + 3] = h3; ol[i + 3] = __float2half(v.w - __half2float(h3));
}

// ---------------- fp32 -> fp16 single convert ----------------
__global__ void cvt_kernel(const float* __restrict__ src, fp16* __restrict__ dst) {
    long i = ((long)blockIdx.x * 256 + threadIdx.x) * 4;
    float4 v = *(const float4*)(src + i);
    __half2 a, b;
    a.x = __float2half(v.x); a.y = __float2half(v.y);
    b.x = __float2half(v.z); b.y = __float2half(v.w);
    *(__half2*)(dst + i)     = a;
    *(__half2*)(dst + i + 2) = b;
}

// ---------------- row sums ----------------
__global__ void rowsum_kernel(const float* __restrict__ x) {
    int c = blockIdx.x, b = blockIdx.y;
    const float* row = x + ((long)b * CH + c) * NPIX;
    float s = 0.f;
    for (int n = threadIdx.x * 4; n < NPIX; n += 256 * 4) {
        float4 v = *(const float4*)(row + n);
        s += v.x + v.y + v.z + v.w;
    }
    __shared__ float red[256];
    red[threadIdx.x] = s;
    __syncthreads();
    for (int off = 128; off > 0; off >>= 1) {
        if (threadIdx.x < off) red[threadIdx.x] += red[threadIdx.x + off];
        __syncthreads();
    }
    if (threadIdx.x == 0) g_s[b * CH + c] = red[0];
}

// ---------------- qs = Wq*s, ks = Wk*s ----------------
__global__ void qsks_kernel(const float* __restrict__ wq, const float* __restrict__ wk) {
    int b = blockIdx.x;
    __shared__ float sv[CH];
    for (int i = threadIdx.x; i < CH; i += 256) sv[i] = g_s[b * CH + i];
    __syncthreads();
    for (int o = threadIdx.x; o < CH; o += 256) {
        const float* wr = wq + (long)o * CH;
        const float* kr = wk + (long)o * CH;
        float aq = 0.f, ak = 0.f;
        for (int c = 0; c < CH; c++) { aq += wr[c] * sv[c]; ak += kr[c] * sv[c]; }
        g_qs[b * CH + o] = aq;
        g_ks[b * CH + o] = ak;
    }
}

// ---------------- energy blocks + softmax + abv ----------------
__global__ void __launch_bounds__(256) attn_kernel(
    const float* __restrict__ wk, const float* __restrict__ bq,
    const float* __restrict__ bk, const float* __restrict__ bv)
{
    int h = blockIdx.x, b = blockIdx.y;
    __shared__ float Ts[16][64];
    __shared__ float Ks[16][64];
    __shared__ float Es[64][65];
    __shared__ float qv[64], kvv[64], bqv[64], bkv[64], bvv[64];
    int tid = threadIdx.x;
    if (tid < 64) {
        qv[tid]  = g_qs[b * CH + h * HD + tid];
        kvv[tid] = g_ks[b * CH + h * HD + tid];
        bqv[tid] = bq[h * HD + tid];
        bkv[tid] = bk[h * HD + tid];
        bvv[tid] = bv[h * HD + tid];
    }
    const float* Tb = g_T + ((long)b * CH + h * HD) * CH;
    const float* Kb = wk + (long)(h * HD) * CH;
    int lrow = tid >> 2;
    int lcol = (tid & 3) * 4;
    int tx = tid & 15, ty = tid >> 4;
    float acc[4][4];
    #pragma unroll
    for (int i = 0; i < 4; i++)
        #pragma unroll
        for (int j = 0; j < 4; j++) acc[i][j] = 0.f;

    for (int a0 = 0; a0 < CH; a0 += 16) {
        float4 tv = *(const float4*)(Tb + (long)lrow * CH + a0 + lcol);
        Ts[lcol + 0][lrow] = tv.x; Ts[lcol + 1][lrow] = tv.y;
        Ts[lcol + 2][lrow] = tv.z; Ts[lcol + 3][lrow] = tv.w;
        float4 kv4 = *(const float4*)(Kb + (long)lrow * CH + a0 + lcol);
        Ks[lcol + 0][lrow] = kv4.x; Ks[lcol + 1][lrow] = kv4.y;
        Ks[lcol + 2][lrow] = kv4.z; Ks[lcol + 3][lrow] = kv4.w;
        __syncthreads();
        #pragma unroll
        for (int kk = 0; kk < 16; kk++) {
            float ra[4], rb[4];
            *(float4*)&ra[0] = *(const float4*)&Ts[kk][ty * 4];
            *(float4*)&rb[0] = *(const float4*)&Ks[kk][tx * 4];
            #pragma unroll
            for (int i = 0; i < 4; i++)
                #pragma unroll
                for (int j = 0; j < 4; j++)
                    acc[i][j] += ra[i] * rb[j];
        }
        __syncthreads();
    }
    #pragma unroll
    for (int i = 0; i < 4; i++) {
        int gi = ty * 4 + i;
        #pragma unroll
        for (int j = 0; j < 4; j++) {
            int gj = tx * 4 + j;
            float e = acc[i][j] + qv[gi] * bkv[gj] + bqv[gi] * kvv[gj]
                      + 4096.f * bqv[gi] * bkv[gj];
            Es[gi][gj] = e * ATT_SCALE;
        }
    }
    __syncthreads();
    if (tid < 64) {
        int i = tid;
        float m = -1e30f;
        for (int j = 0; j < 64; j++) m = fmaxf(m, Es[i][j]);
        float sum = 0.f;
        for (int j = 0; j < 64; j++) {
            float ex = expf(Es[i][j] - m);
            Es[i][j] = ex;
            sum += ex;
        }
        float inv = 1.f / sum;
        float ab = 0.f;
        float* Arow = g_A + (((long)b * NH + h) * HD + i) * HD;
        for (int j = 0; j < 64; j++) {
            float a = Es[i][j] * inv;
            Arow[j] = a;
            ab += a * bvv[j];
        }
        g_abv[b * CH + h * HD + i] = ab;
    }
}

// ---------------- Pt = (A_bd * Wv)^T, fp16 hi/lo [c][r] ----------------
__global__ void __launch_bounds__(256) pk_kernel(const float* __restrict__ wv) {
    int h = blockIdx.x, b = blockIdx.y;
    __shared__ float Ash[64][64];
    __shared__ float Bv[64][64];
    int tid = threadIdx.x;
    const float* Ab = g_A + ((long)b * NH + h) * HD * HD;
    for (int r = tid; r < 64 * 16; r += 256) {
        int i = r >> 4, q = (r & 15) * 4;
        float4 v = *(const float4*)(Ab + i * 64 + q);
        Ash[q + 0][i] = v.x; Ash[q + 1][i] = v.y;
        Ash[q + 2][i] = v.z; Ash[q + 3][i] = v.w;
    }
    int tx = tid & 15, ty = tid >> 4;
    for (int cc = 0; cc < CH; cc += 64) {
        __syncthreads();
        for (int r = tid; r < 64 * 16; r += 256) {
            int j = r >> 4, q = (r & 15) * 4;
            *(float4*)&Bv[j][q] = *(const float4*)(wv + (long)(h * HD + j) * CH + cc + q);
        }
        __syncthreads();
        float acc[4][4];
        #pragma unroll
        for (int i = 0; i < 4; i++)
            #pragma unroll
            for (int j = 0; j < 4; j++) acc[i][j] = 0.f;
        #pragma unroll 8
        for (int j = 0; j < 64; j++) {
            float ra[4], rb[4];
            *(float4*)&ra[0] = *(const float4*)&Ash[j][ty * 4];
            *(float4*)&rb[0] = *(const float4*)&Bv[j][tx * 4];
            #pragma unroll
            for (int i = 0; i < 4; i++)
                #pragma unroll
                for (int u = 0; u < 4; u++)
                    acc[i][u] += ra[i] * rb[u];
        }
        #pragma unroll
        for (int u = 0; u < 4; u++) {
            int c = cc + tx * 4 + u;
            long base = ((long)b * CH + c) * CH + h * HD + ty * 4;
            float v0 = acc[0][u], v1 = acc[1][u], v2 = acc[2][u], v3 = acc[3][u];
            fp16 h0 = __float2half(v0), h1 = __float2half(v1);
            fp16 h2 = __float2half(v2), h3 = __float2half(v3);
            __half2 a0, a1, b0, b1;
            a0.x = h0; a0.y = h1; a1.x = h2; a1.y = h3;
            b0.x = __float2half(v0 - __half2float(h0));
            b0.y = __float2half(v1 - __half2float(h1));
            b1.x = __float2half(v2 - __half2float(h2));
            b1.y = __float2half(v3 - __half2float(h3));
            *(__half2*)(g_Pth + base)     = a0;
            *(__half2*)(g_Pth + base + 2) = a1;
            *(__half2*)(g_Ptl + base)     = b0;
            *(__half2*)(g_Ptl + base + 2) = b1;
        }
    }
}

// ---------------- c[b] = Wo * abv[b] + bo ----------------
__global__ void cvec_kernel(const float* __restrict__ wo, const float* __restrict__ bo) {
    int b = blockIdx.x;
    __shared__ float sv[CH];
    for (int i = threadIdx.x; i < CH; i += 256) sv[i] = g_abv[b * CH + i];
    __syncthreads();
    for (int o = threadIdx.x; o < CH; o += 256) {
        const float* wr = wo + (long)o * CH;
        float sum = bo[o];
        for (int c = 0; c < CH; c++) sum += wr[c] * sv[c];
        g_c[b * CH + o] = sum;
    }
}

// ---------------- launch ----------------
extern "C" void kernel_launch(void* const* d_in, const int* in_sizes, int n_in,
                              void* d_out, int out_size) {
    const float* x  = (const float*)d_in[0];
    const float* wq = (const float*)d_in[1];
    const float* bq = (const float*)d_in[2];
    const float* wk = (const float*)d_in[3];
    const float* bk = (const float*)d_in[4];
    const float* wv = (const float*)d_in[5];
    const float* bv = (const float*)d_in[6];
    const float* wo = (const float*)d_in[7];
    const float* bo = (const float*)d_in[8];
    float* y = (float*)d_out;

    float *pT, *pGP, *pc;
    fp16 *pXh, *pXl, *pXt, *pGh, *pGl, *pPth, *pPtl, *pMh;
    fp16 *pWqh, *pWql, *pWoh;
    cudaGetSymbolAddress((void**)&pT,  g_T);
    cudaGetSymbolAddress((void**)&pGP, g_GP);
    cudaGetSymbolAddress((void**)&pc,  g_c);
    cudaGetSymbolAddress((void**)&pXh, g_Xh);
    cudaGetSymbolAddress((void**)&pXl, g_Xl);
    cudaGetSymbolAddress((void**)&pXt, g_Xt);
    cudaGetSymbolAddress((void**)&pGh, g_Gh);
    cudaGetSymbolAddress((void**)&pGl, g_Gl);
    cudaGetSymbolAddress((void**)&pPth, g_Pth);
    cudaGetSymbolAddress((void**)&pPtl, g_Ptl);
    cudaGetSymbolAddress((void**)&pMh, g_Mh);
    cudaGetSymbolAddress((void**)&pWqh, g_Wqh);
    cudaGetSymbolAddress((void**)&pWql, g_Wql);
    cudaGetSymbolAddress((void**)&pWoh, g_Woh);

    cudaFuncSetAttribute((const void*)mma_gemm<true>,
                         cudaFuncAttributeMaxDynamicSharedMemorySize, MMA_SMEM);
    cudaFuncSetAttribute((const void*)mma_gemm<false>,
                         cudaFuncAttributeMaxDynamicSharedMemorySize, MMA_SMEM);
    cudaFuncSetAttribute((const void*)mma_gemm2,
                         cudaFuncAttributeMaxDynamicSharedMemorySize, T2_SMEM);
    cudaFuncSetAttribute((const void*)mma_gemm_h1,
                         cudaFuncAttributeMaxDynamicSharedMemorySize, H1_SMEM);

    // 1-3. prep (positions 1-3)
    splitx_kernel<<<dim3(NPIX / 32, CH / 32, BATCH), dim3(32, 8)>>>(x);
    splitw_kernel<<<(CH * CH) / 1024, 256>>>(wq, pWqh, pWql);
    cvt_kernel<<<(CH * CH) / 1024, 256>>>(wo, pWoh);

    // 4. Gram partials (launch #4 -> ncu capture target).  K = 4096
    mma_gemm<true><<<dim3(21, 2, BATCH), 256, MMA_SMEM>>>(
        pXh, pXl, pXh, pXl, pGP,
        NPIX, NPIX / 2, CH, (long)CH * NPIX, (long)CH * NPIX, (long)CH * CH);

    // 5-6. row sums + reduce partials
    rowsum_kernel<<<dim3(CH, BATCH), 256>>>(x);
    gram_reduce<<<dim3(21, BATCH), 256>>>();

    // 7. qs/ks
    qsks_kernel<<<BATCH, 256>>>(wq, wk);

    // 8. T[b] = Wq * G[b]  (fp16 3-term).  K = 768
    mma_gemm<false><<<dim3(6, 6, BATCH), 256, MMA_SMEM>>>(
        pWqh, pWql, pGh, pGl, pT,
        CH, CH, CH, 0L, (long)CH * CH, (long)CH * CH);

    // 9. attention
    attn_kernel<<<dim3(NH, BATCH), 256>>>(wk, bq, bk, bv);

    // 10. Pt fp16 h/l
    pk_kernel<<<dim3(NH, BATCH), 256>>>(wv);

    // 11. c[b] = Wo * abv + bo
    cvec_kernel<<<BATCH, 256>>>(wo, bo);

    // 12. M[b] = Wo * P[b]  (fp16 2-term, fp16 out).  K = 768
    mma_gemm2<<<dim3(6, 6, BATCH), 256, T2_SMEM>>>(
        pWoh, pPth, pPtl, pMh,
        CH, CH, (long)CH * CH, (long)CH * CH);

    // 13. y[b] = M[b] * X[b] + c[b]  (fp16 1-term).  K = 768
    mma_gemm_h1<<<dim3(NPIX / 128, 6, BATCH), 256, H1_SMEM>>>(
        pMh, pXt, y, pc,
        CH, NPIX, (long)CH * CH, (long)NPIX * CH, (long)CH * NPIX);
}

// round 11
// speedup vs baseline: 3.8956x; 1.5476x over previous
#include <cuda_runtime.h>
#include <cuda_fp16.h>
#include <math.h>
#include <stdint.h>

#define BATCH 16
#define CH    768
#define NPIX  4096
#define NH    12
#define HD    64
#define ATT_SCALE 0.125f   // HD^-0.5

typedef __half fp16;

// ---------------- scratch (device globals; no runtime allocation) ----------------
__device__ float g_T [BATCH * CH * CH];       // T = Wq * G
__device__ float g_GP[4L * BATCH * CH * CH];  // Gram split-K partials (x4)
__device__ float g_A[BATCH * NH * HD * HD];
__device__ float g_s[BATCH * CH];
__device__ float g_qs[BATCH * CH];
__device__ float g_ks[BATCH * CH];
__device__ float g_abv[BATCH * CH];
__device__ float g_c[BATCH * CH];

__device__ __align__(16) fp16 g_Xh [BATCH * CH * NPIX];  // fp16 hi of X [b][c][n]
__device__ __align__(16) fp16 g_Xl [BATCH * CH * NPIX];  // fp16 lo
__device__ __align__(16) fp16 g_Xt [BATCH * NPIX * CH];  // fp16(X) transposed [b][n][c]
__device__ __align__(16) fp16 g_Gh [BATCH * CH * CH];
__device__ __align__(16) fp16 g_Gl [BATCH * CH * CH];
__device__ __align__(16) fp16 g_Pth[BATCH * CH * CH];    // (A_bd*Wv)^T hi [c][r]
__device__ __align__(16) fp16 g_Ptl[BATCH * CH * CH];
__device__ __align__(16) fp16 g_Mh [BATCH * CH * CH];    // fp16(M) single
__device__ __align__(16) fp16 g_Wqh[CH * CH];
__device__ __align__(16) fp16 g_Wql[CH * CH];
__device__ __align__(16) fp16 g_Woh[CH * CH];            // fp16(Wo) single

// ---------------- asm helpers (sm_80-compatible only) ----------------
__device__ __forceinline__ uint32_t smem_u32(const void* p) {
    uint32_t a;
    asm("{ .reg .u64 t; cvta.to.shared.u64 t, %1; cvt.u32.u64 %0, t; }" : "=r"(a) : "l"(p));
    return a;
}
__device__ __forceinline__ void ldsm4(uint32_t* r, uint32_t a) {
    asm volatile("ldmatrix.sync.aligned.m8n8.x4.shared.b16 {%0,%1,%2,%3}, [%4];"
                 : "=r"(r[0]), "=r"(r[1]), "=r"(r[2]), "=r"(r[3]) : "r"(a));
}
__device__ __forceinline__ void mma_f16(float* c, const uint32_t* a, const uint32_t* b) {
    asm volatile(
        "mma.sync.aligned.m16n8k16.row.col.f32.f16.f16.f32 "
        "{%0,%1,%2,%3}, {%4,%5,%6,%7}, {%8,%9}, {%0,%1,%2,%3};"
        : "+f"(c[0]), "+f"(c[1]), "+f"(c[2]), "+f"(c[3])
        : "r"(a[0]), "r"(a[1]), "r"(a[2]), "r"(a[3]), "r"(b[0]), "r"(b[1]));
}
#define CP_A16(dst, src) asm volatile( \
    "cp.async.cg.shared.global [%0], [%1], 16;" :: "r"(dst), "l"(src))
#define CP_COMMIT() asm volatile("cp.async.commit_group;" ::: "memory")
#define CP_WAIT0()  asm volatile("cp.async.wait_group 0;" ::: "memory")
#define CP_WAIT1()  asm volatile("cp.async.wait_group 1;" ::: "memory")
#define CP_WAIT2()  asm volatile("cp.async.wait_group 2;" ::: "memory")

// ---------------- smem geometry ----------------
#define ROWPITCH 80
#define ARR_BYTES 10240
#define STAGE_BYTES (4 * ARR_BYTES)          // 3-term: AH AL BH BL
#define MMA_SMEM (2 * STAGE_BYTES)           // 81920  -> 2 CTAs/SM
#define T2_STAGE (3 * ARR_BYTES)             // 2-term: AH BH BL
#define T2_SMEM (2 * T2_STAGE)               // 61440  -> 2 CTAs/SM
#define H1_STAGE (2 * ARR_BYTES)             // 1-term: A B
#define H1_SMEM (3 * H1_STAGE)               // 61440  -> 2 CTAs/SM

// =================================================================
// 3-term fp16 GEMM:  C(128x128) = Ah*Bh^T + Ah*Bl^T + Al*Bh^T  (fp32 out)
// 2-stage pipeline, 2 CTAs/SM.
// MIRROR: lower-triangle tile decode + split-K partial output.
// =================================================================
template<bool MIRROR>
__global__ void __launch_bounds__(256, 2) mma_gemm(
    const fp16* __restrict__ Ahg, const fp16* __restrict__ Alg,
    const fp16* __restrict__ Bhg, const fp16* __restrict__ Blg,
    float* __restrict__ Cf,
    int Kdim, int Ksub, int ldc, long sA, long sB, long sC)
{
    extern __shared__ char smem[];
    uint32_t sbase = smem_u32(smem);
    int tid = threadIdx.x;
    int lane = tid & 31, wid = tid >> 5;
    int b = blockIdx.z;
    int m0, n0, kbase = 0;
    long outb;
    if (MIRROR) {
        int t = blockIdx.x, bi = 0;
        while ((bi + 1) * (bi + 2) / 2 <= t) bi++;
        int bj = t - bi * (bi + 1) / 2;
        m0 = bi * 128; n0 = bj * 128;
        kbase = blockIdx.y * Ksub;
        outb = ((long)blockIdx.y * BATCH + b) * sC;
    } else {
        m0 = blockIdx.y * 128; n0 = blockIdx.x * 128;
        outb = (long)b * sC;
    }
    int m_warp = (wid & 3) * 32, n_warp = (wid >> 2) * 64;

    const fp16* pAh = Ahg + b * sA + (long)m0 * Kdim + kbase;
    const fp16* pAl = Alg + b * sA + (long)m0 * Kdim + kbase;
    const fp16* pBh = Bhg + b * sB + (long)n0 * Kdim + kbase;
    const fp16* pBl = Blg + b * sB + (long)n0 * Kdim + kbase;

    uint32_t a_off = (uint32_t)((m_warp + (lane & 15)) * ROWPITCH + (lane >> 4) * 16);
    uint32_t b_off = (uint32_t)((n_warp + (lane & 7) + ((lane >> 4) & 1) * 8) * ROWPITCH
                                + ((lane >> 3) & 1) * 16);

    float acc[2][8][4];
    #pragma unroll
    for (int mt = 0; mt < 2; mt++)
        #pragma unroll
        for (int nt = 0; nt < 8; nt++)
            #pragma unroll
            for (int q = 0; q < 4; q++) acc[mt][nt][q] = 0.f;

    int nch = Ksub >> 5;

    auto load_stage = [&](int stage, int k0) {
        uint32_t st = sbase + stage * STAGE_BYTES;
        #pragma unroll
        for (int it = 0; it < 2; it++) {
            int q = tid + it * 256;
            int r = q >> 2, c = q & 3;
            uint32_t off = r * ROWPITCH + c * 16;
            long gofs = ((long)r * Kdim + k0 + c * 8);
            CP_A16(st + 0 * ARR_BYTES + off, (const char*)(pAh + gofs));
            CP_A16(st + 1 * ARR_BYTES + off, (const char*)(pAl + gofs));
            CP_A16(st + 2 * ARR_BYTES + off, (const char*)(pBh + gofs));
            CP_A16(st + 3 * ARR_BYTES + off, (const char*)(pBl + gofs));
        }
        CP_COMMIT();
    };

    load_stage(0, 0);

    for (int ic = 0; ic < nch; ic++) {
        int p = ic & 1;
        if (ic + 1 < nch) { load_stage(p ^ 1, (ic + 1) * 32); CP_WAIT1(); }
        else              { CP_WAIT0(); }
        __syncthreads();

        uint32_t st = sbase + p * STAGE_BYTES;
        #pragma unroll
        for (int kk = 0; kk < 2; kk++) {
            uint32_t ah[2][4], al[2][4];
            ldsm4(ah[0], st + 0 * ARR_BYTES + a_off + kk * 32);
            ldsm4(ah[1], st + 0 * ARR_BYTES + a_off + 16 * ROWPITCH + kk * 32);
            ldsm4(al[0], st + 1 * ARR_BYTES + a_off + kk * 32);
            ldsm4(al[1], st + 1 * ARR_BYTES + a_off + 16 * ROWPITCH + kk * 32);
            #pragma unroll
            for (int ntp = 0; ntp < 4; ntp++) {
                uint32_t bh[4], bl[4];
                ldsm4(bh, st + 2 * ARR_BYTES + b_off + ntp * 16 * ROWPITCH + kk * 32);
                ldsm4(bl, st + 3 * ARR_BYTES + b_off + ntp * 16 * ROWPITCH + kk * 32);
                #pragma unroll
                for (int mt = 0; mt < 2; mt++) {
                    mma_f16(acc[mt][2 * ntp],     ah[mt], bh);
                    mma_f16(acc[mt][2 * ntp],     ah[mt], bl);
                    mma_f16(acc[mt][2 * ntp],     al[mt], bh);
                    mma_f16(acc[mt][2 * ntp + 1], ah[mt], bh + 2);
                    mma_f16(acc[mt][2 * ntp + 1], ah[mt], bl + 2);
                    mma_f16(acc[mt][2 * ntp + 1], al[mt], bh + 2);
                }
            }
        }
        __syncthreads();
    }

    #pragma unroll
    for (int mt = 0; mt < 2; mt++) {
        #pragma unroll
        for (int hh = 0; hh < 2; hh++) {
            int rg = m0 + m_warp + mt * 16 + (lane >> 2) + hh * 8;
            long rowoff = outb + (long)rg * ldc;
            #pragma unroll
            for (int nt = 0; nt < 8; nt++) {
                int cg = n0 + n_warp + nt * 8 + (lane & 3) * 2;
                *(float2*)(Cf + rowoff + cg) =
                    make_float2(acc[mt][nt][hh * 2 + 0], acc[mt][nt][hh * 2 + 1]);
            }
        }
    }
}

// =================================================================
// 2-term fp16 GEMM:  C = Ah*(Bh+Bl)^T, fp16 out (for M = Wo * P)
// =================================================================
__global__ void __launch_bounds__(256, 2) mma_gemm2(
    const fp16* __restrict__ Ag,
    const fp16* __restrict__ Bhg, const fp16* __restrict__ Blg,
    fp16* __restrict__ Ch,
    int Kdim, int ldc, long sB, long sC)
{
    extern __shared__ char smem[];
    uint32_t sbase = smem_u32(smem);
    int tid = threadIdx.x;
    int lane = tid & 31, wid = tid >> 5;
    int b = blockIdx.z;
    int m0 = blockIdx.y * 128, n0 = blockIdx.x * 128;
    int m_warp = (wid & 3) * 32, n_warp = (wid >> 2) * 64;

    const fp16* pA  = Ag  + (long)m0 * Kdim;
    const fp16* pBh = Bhg + b * sB + (long)n0 * Kdim;
    const fp16* pBl = Blg + b * sB + (long)n0 * Kdim;

    uint32_t a_off = (uint32_t)((m_warp + (lane & 15)) * ROWPITCH + (lane >> 4) * 16);
    uint32_t b_off = (uint32_t)((n_warp + (lane & 7) + ((lane >> 4) & 1) * 8) * ROWPITCH
                                + ((lane >> 3) & 1) * 16);

    float acc[2][8][4];
    #pragma unroll
    for (int mt = 0; mt < 2; mt++)
        #pragma unroll
        for (int nt = 0; nt < 8; nt++)
            #pragma unroll
            for (int q = 0; q < 4; q++) acc[mt][nt][q] = 0.f;

    int nch = Kdim >> 5;

    auto load_stage = [&](int stage, int k0) {
        uint32_t st = sbase + stage * T2_STAGE;
        #pragma unroll
        for (int it = 0; it < 2; it++) {
            int q = tid + it * 256;
            int r = q >> 2, c = q & 3;
            uint32_t off = r * ROWPITCH + c * 16;
            long gofs = ((long)r * Kdim + k0 + c * 8);
            CP_A16(st + 0 * ARR_BYTES + off, (const char*)(pA  + gofs));
            CP_A16(st + 1 * ARR_BYTES + off, (const char*)(pBh + gofs));
            CP_A16(st + 2 * ARR_BYTES + off, (const char*)(pBl + gofs));
        }
        CP_COMMIT();
    };

    load_stage(0, 0);

    for (int ic = 0; ic < nch; ic++) {
        int p = ic & 1;
        if (ic + 1 < nch) { load_stage(p ^ 1, (ic + 1) * 32); CP_WAIT1(); }
        else              { CP_WAIT0(); }
        __syncthreads();

        uint32_t st = sbase + p * T2_STAGE;
        #pragma unroll
        for (int kk = 0; kk < 2; kk++) {
            uint32_t a[2][4];
            ldsm4(a[0], st + a_off + kk * 32);
            ldsm4(a[1], st + a_off + 16 * ROWPITCH + kk * 32);
            #pragma unroll
            for (int ntp = 0; ntp < 4; ntp++) {
                uint32_t bh[4], bl[4];
                ldsm4(bh, st + 1 * ARR_BYTES + b_off + ntp * 16 * ROWPITCH + kk * 32);
                ldsm4(bl, st + 2 * ARR_BYTES + b_off + ntp * 16 * ROWPITCH + kk * 32);
                #pragma unroll
                for (int mt = 0; mt < 2; mt++) {
                    mma_f16(acc[mt][2 * ntp],     a[mt], bh);
                    mma_f16(acc[mt][2 * ntp],     a[mt], bl);
                    mma_f16(acc[mt][2 * ntp + 1], a[mt], bh + 2);
                    mma_f16(acc[mt][2 * ntp + 1], a[mt], bl + 2);
                }
            }
        }
        __syncthreads();
    }

    #pragma unroll
    for (int mt = 0; mt < 2; mt++) {
        #pragma unroll
        for (int hh = 0; hh < 2; hh++) {
            int rg = m0 + m_warp + mt * 16 + (lane >> 2) + hh * 8;
            long rowoff = (long)b * sC + (long)rg * ldc;
            #pragma unroll
            for (int nt = 0; nt < 8; nt++) {
                int cg = n0 + n_warp + nt * 8 + (lane & 3) * 2;
                __half2 hv;
                hv.x = __float2half(acc[mt][nt][hh * 2 + 0]);
                hv.y = __float2half(acc[mt][nt][hh * 2 + 1]);
                *(__half2*)(Ch + rowoff + cg) = hv;
            }
        }
    }
}

// ---------------- Gram reduce: sum 4 split-K partials -> fp16 h/l + mirror ----------------
__global__ void gram_reduce() {
    int t = blockIdx.x, b = blockIdx.y;
    int bi = 0;
    while ((bi + 1) * (bi + 2) / 2 <= t) bi++;
    int bj = t - bi * (bi + 1) / 2;
    long mb = (long)b * CH * CH;
    long PS = (long)BATCH * CH * CH;
    bool mir = (bi != bj);
    for (int e = threadIdx.x; e < 16384; e += 256) {
        int r = bi * 128 + (e >> 7);
        int c = bj * 128 + (e & 127);
        long o = (long)r * CH + c;
        float v = g_GP[mb + o] + g_GP[PS + mb + o]
                + g_GP[2 * PS + mb + o] + g_GP[3 * PS + mb + o];
        fp16 h = __float2half(v);
        fp16 l = __float2half(v - __half2float(h));
        g_Gh[mb + o] = h;
        g_Gl[mb + o] = l;
        if (mir) {
            long ot = (long)c * CH + r;
            g_Gh[mb + ot] = h;
            g_Gl[mb + ot] = l;
        }
    }
}

// =================================================================
// 1-term fp16 GEMM (final):  C = A * B^T + bias[r], fp32 out, 2 CTAs/SM
// =================================================================
__global__ void __launch_bounds__(256, 2) mma_gemm_h1(
    const fp16* __restrict__ Ag, const fp16* __restrict__ Bg,
    float* __restrict__ Cf, const float* __restrict__ biasg,
    int Kdim, int ldc, long sA, long sB, long sC)
{
    extern __shared__ char smem[];
    uint32_t sbase = smem_u32(smem);
    int tid = threadIdx.x;
    int lane = tid & 31, wid = tid >> 5;
    int b = blockIdx.z;
    int m0 = blockIdx.y * 128, n0 = blockIdx.x * 128;
    int m_warp = (wid & 3) * 32, n_warp = (wid >> 2) * 64;

    const fp16* pA = Ag + b * sA + (long)m0 * Kdim;
    const fp16* pB = Bg + b * sB + (long)n0 * Kdim;

    uint32_t a_off = (uint32_t)((m_warp + (lane & 15)) * ROWPITCH + (lane >> 4) * 16);
    uint32_t b_off = (uint32_t)((n_warp + (lane & 7) + ((lane >> 4) & 1) * 8) * ROWPITCH
                                + ((lane >> 3) & 1) * 16);

    float acc[2][8][4];
    #pragma unroll
    for (int mt = 0; mt < 2; mt++)
        #pragma unroll
        for (int nt = 0; nt < 8; nt++)
            #pragma unroll
            for (int q = 0; q < 4; q++) acc[mt][nt][q] = 0.f;

    int nch = Kdim >> 5;

    auto load_stage = [&](int stage, int k0) {
        uint32_t st = sbase + stage * H1_STAGE;
        #pragma unroll
        for (int it = 0; it < 4; it++) {
            int q = tid + it * 256;
            int r = q >> 2, c = q & 3;
            int arr = r >> 7, rr = r & 127;
            uint32_t dst = st + arr * ARR_BYTES + rr * ROWPITCH + c * 16;
            const fp16* src = (arr ? pB : pA) + (long)rr * Kdim + k0 + c * 8;
            CP_A16(dst, (const char*)src);
        }
        CP_COMMIT();
    };

    load_stage(0, 0);
    load_stage(1, 32);

    for (int ic = 0; ic < nch; ic++) {
        if (ic + 2 < nch) { load_stage((ic + 2) % 3, (ic + 2) * 32); CP_WAIT2(); }
        else if (ic + 1 < nch) { CP_WAIT1(); }
        else { CP_WAIT0(); }
        __syncthreads();

        uint32_t st = sbase + (ic % 3) * H1_STAGE;
        #pragma unroll
        for (int kk = 0; kk < 2; kk++) {
            uint32_t a[2][4];
            ldsm4(a[0], st + a_off + kk * 32);
            ldsm4(a[1], st + a_off + 16 * ROWPITCH + kk * 32);
            #pragma unroll
            for (int ntp = 0; ntp < 4; ntp++) {
                uint32_t bf[4];
                ldsm4(bf, st + ARR_BYTES + b_off + ntp * 16 * ROWPITCH + kk * 32);
                #pragma unroll
                for (int mt = 0; mt < 2; mt++) {
                    mma_f16(acc[mt][2 * ntp],     a[mt], bf);
                    mma_f16(acc[mt][2 * ntp + 1], a[mt], bf + 2);
                }
            }
        }
        __syncthreads();
    }

    #pragma unroll
    for (int mt = 0; mt < 2; mt++) {
        #pragma unroll
        for (int hh = 0; hh < 2; hh++) {
            int rg = m0 + m_warp + mt * 16 + (lane >> 2) + hh * 8;
            float bias = biasg[b * CH + rg];
            long rowoff = b * sC + (long)rg * ldc;
            #pragma unroll
            for (int nt = 0; nt < 8; nt++) {
                int cg = n0 + n_warp + nt * 8 + (lane & 3) * 2;
                *(float2*)(Cf + rowoff + cg) =
                    make_float2(acc[mt][nt][hh * 2 + 0] + bias,
                                acc[mt][nt][hh * 2 + 1] + bias);
            }
        }
    }
}

// ---------------- zero g_s ----------------
__global__ void zs_kernel() {
    int i = blockIdx.x * 256 + threadIdx.x;
    if (i < BATCH * CH) g_s[i] = 0.f;
}

// ---------------- x -> fp16 h/l + fp16 transposed + fused row sums ----------------
__global__ void splitx_kernel(const float* __restrict__ x) {
    __shared__ float xt[32][33];
    int b = blockIdx.z;
    int n0 = blockIdx.x * 32, c0 = blockIdx.y * 32;
    int tx = threadIdx.x, ty = threadIdx.y;
    const float* xb = x + (long)b * CH * NPIX;
    float vsum[4];
    #pragma unroll
    for (int k = 0; k < 4; k++) {
        int c = c0 + ty + k * 8;
        float v = xb[(long)c * NPIX + n0 + tx];
        xt[ty + k * 8][tx] = v;
        vsum[k] = v;
        fp16 h = __float2half(v);
        fp16 l = __float2half(v - __half2float(h));
        long idx = ((long)b * CH + c) * NPIX + n0 + tx;
        g_Xh[idx] = h;
        g_Xl[idx] = l;
    }
    // fused row-sum: warp-reduce each row's 32 n-values, atomicAdd into g_s
    #pragma unroll
    for (int k = 0; k < 4; k++) {
        float s = vsum[k];
        #pragma unroll
        for (int off = 16; off > 0; off >>= 1)
            s += __shfl_down_sync(0xFFFFFFFFu, s, off);
        if (tx == 0) atomicAdd(&g_s[b * CH + c0 + ty + k * 8], s);
    }
    __syncthreads();
    #pragma unroll
    for (int k = 0; k < 4; k++) {
        int n = n0 + ty + k * 8;
        long idx = ((long)b * NPIX + n) * CH + c0 + tx;
        g_Xt[idx] = __float2half(xt[tx][ty + k * 8]);
    }
}

// ---------------- elementwise split fp32 -> fp16 h/l ----------------
__global__ void splitw_kernel(const float* __restrict__ src,
                              fp16* __restrict__ oh, fp16* __restrict__ ol) {
    long i = ((long)blockIdx.x * 256 + threadIdx.x) * 4;
    float4 v = *(const float4*)(src + i);
    fp16 h0 = __float2half(v.x), h1 = __float2half(v.y);
    fp16 h2 = __float2half(v.z), h3 = __float2half(v.w);
    oh[i + 0] = h0; ol[i + 0] = __float2half(v.x - __half2float(h0));
    oh[i + 1] = h1; ol[i + 1] = __float2half(v.y - __half2float(h1));
    oh[i + 2] = h2; ol[i + 2] = __float2half(v.z - __half2float(h2));
    oh[i + 3] = h3; ol[i + 3] = __float2half(v.w - __half2float(h3));
}

// ---------------- fp32 -> fp16 single convert ----------------
__global__ void cvt_kernel(const float* __restrict__ src, fp16* __restrict__ dst) {
    long i = ((long)blockIdx.x * 256 + threadIdx.x) * 4;
    float4 v = *(const float4*)(src + i);
    __half2 a, b;
    a.x = __float2half(v.x); a.y = __float2half(v.y);
    b.x = __float2half(v.z); b.y = __float2half(v.w);
    *(__half2*)(dst + i)     = a;
    *(__half2*)(dst + i + 2) = b;
}

// ---------------- qs = Wq*s, ks = Wk*s  (grid CH blocks; warp -> 2 batches) ----------------
__global__ void __launch_bounds__(256) qsks_kernel(
    const float* __restrict__ wq, const float* __restrict__ wk)
{
    int o = blockIdx.x;
    int lane = threadIdx.x & 31, w = threadIdx.x >> 5;
    const float* wr = wq + (long)o * CH;
    const float* kr = wk + (long)o * CH;
    int b0 = w, b1 = w + 8;
    float aq0 = 0.f, ak0 = 0.f, aq1 = 0.f, ak1 = 0.f;
    for (int c = lane; c < CH; c += 32) {
        float wv = wr[c], kv = kr[c];
        float s0 = g_s[b0 * CH + c], s1 = g_s[b1 * CH + c];
        aq0 += wv * s0; ak0 += kv * s0;
        aq1 += wv * s1; ak1 += kv * s1;
    }
    #pragma unroll
    for (int off = 16; off > 0; off >>= 1) {
        aq0 += __shfl_down_sync(0xFFFFFFFFu, aq0, off);
        ak0 += __shfl_down_sync(0xFFFFFFFFu, ak0, off);
        aq1 += __shfl_down_sync(0xFFFFFFFFu, aq1, off);
        ak1 += __shfl_down_sync(0xFFFFFFFFu, ak1, off);
    }
    if (lane == 0) {
        g_qs[b0 * CH + o] = aq0; g_ks[b0 * CH + o] = ak0;
        g_qs[b1 * CH + o] = aq1; g_ks[b1 * CH + o] = ak1;
    }
}

// ---------------- c = Wo*abv + bo  (grid CH blocks; warp -> 2 batches) ----------------
__global__ void __launch_bounds__(256) cvec_kernel(
    const float* __restrict__ wo, const float* __restrict__ bo)
{
    int o = blockIdx.x;
    int lane = threadIdx.x & 31, w = threadIdx.x >> 5;
    const float* wr = wo + (long)o * CH;
    int b0 = w, b1 = w + 8;
    float a0 = 0.f, a1 = 0.f;
    for (int c = lane; c < CH; c += 32) {
        float wv = wr[c];
        a0 += wv * g_abv[b0 * CH + c];
        a1 += wv * g_abv[b1 * CH + c];
    }
    #pragma unroll
    for (int off = 16; off > 0; off >>= 1) {
        a0 += __shfl_down_sync(0xFFFFFFFFu, a0, off);
        a1 += __shfl_down_sync(0xFFFFFFFFu, a1, off);
    }
    if (lane == 0) {
        float bov = bo[o];
        g_c[b0 * CH + o] = a0 + bov;
        g_c[b1 * CH + o] = a1 + bov;
    }
}

// ---------------- energy blocks + softmax + abv ----------------
__global__ void __launch_bounds__(256) attn_kernel(
    const float* __restrict__ wk, const float* __restrict__ bq,
    const float* __restrict__ bk, const float* __restrict__ bv)
{
    int h = blockIdx.x, b = blockIdx.y;
    __shared__ float Ts[16][64];
    __shared__ float Ks[16][64];
    __shared__ float Es[64][65];
    __shared__ float qv[64], kvv[64], bqv[64], bkv[64], bvv[64];
    int tid = threadIdx.x;
    if (tid < 64) {
        qv[tid]  = g_qs[b * CH + h * HD + tid];
        kvv[tid] = g_ks[b * CH + h * HD + tid];
        bqv[tid] = bq[h * HD + tid];
        bkv[tid] = bk[h * HD + tid];
        bvv[tid] = bv[h * HD + tid];
    }
    const float* Tb = g_T + ((long)b * CH + h * HD) * CH;
    const float* Kb = wk + (long)(h * HD) * CH;
    int lrow = tid >> 2;
    int lcol = (tid & 3) * 4;
    int tx = tid & 15, ty = tid >> 4;
    float acc[4][4];
    #pragma unroll
    for (int i = 0; i < 4; i++)
        #pragma unroll
        for (int j = 0; j < 4; j++) acc[i][j] = 0.f;

    for (int a0 = 0; a0 < CH; a0 += 16) {
        float4 tv = *(const float4*)(Tb + (long)lrow * CH + a0 + lcol);
        Ts[lcol + 0][lrow] = tv.x; Ts[lcol + 1][lrow] = tv.y;
        Ts[lcol + 2][lrow] = tv.z; Ts[lcol + 3][lrow] = tv.w;
        float4 kv4 = *(const float4*)(Kb + (long)lrow * CH + a0 + lcol);
        Ks[lcol + 0][lrow] = kv4.x; Ks[lcol + 1][lrow] = kv4.y;
        Ks[lcol + 2][lrow] = kv4.z; Ks[lcol + 3][lrow] = kv4.w;
        __syncthreads();
        #pragma unroll
        for (int kk = 0; kk < 16; kk++) {
            float ra[4], rb[4];
            *(float4*)&ra[0] = *(const float4*)&Ts[kk][ty * 4];
            *(float4*)&rb[0] = *(const float4*)&Ks[kk][tx * 4];
            #pragma unroll
            for (int i = 0; i < 4; i++)
                #pragma unroll
                for (int j = 0; j < 4; j++)
                    acc[i][j] += ra[i] * rb[j];
        }
        __syncthreads();
    }
    #pragma unroll
    for (int i = 0; i < 4; i++) {
        int gi = ty * 4 + i;
        #pragma unroll
        for (int j = 0; j < 4; j++) {
            int gj = tx * 4 + j;
            float e = acc[i][j] + qv[gi] * bkv[gj] + bqv[gi] * kvv[gj]
                      + 4096.f * bqv[gi] * bkv[gj];
            Es[gi][gj] = e * ATT_SCALE;
        }
    }
    __syncthreads();
    if (tid < 64) {
        int i = tid;
        float m = -1e30f;
        for (int j = 0; j < 64; j++) m = fmaxf(m, Es[i][j]);
        float sum = 0.f;
        for (int j = 0; j < 64; j++) {
            float ex = expf(Es[i][j] - m);
            Es[i][j] = ex;
            sum += ex;
        }
        float inv = 1.f / sum;
        float ab = 0.f;
        float* Arow = g_A + (((long)b * NH + h) * HD + i) * HD;
        for (int j = 0; j < 64; j++) {
            float a = Es[i][j] * inv;
            Arow[j] = a;
            ab += a * bvv[j];
        }
        g_abv[b * CH + h * HD + i] = ab;
    }
}

// ---------------- Pt = (A_bd * Wv)^T, fp16 hi/lo [c][r]; 3-way cc split ----------------
__global__ void __launch_bounds__(256) pk_kernel(const float* __restrict__ wv) {
    int hx = blockIdx.x;
    int h = hx / 3, seg = hx % 3;
    int b = blockIdx.y;
    __shared__ float Ash[64][64];
    __shared__ float Bv[64][64];
    int tid = threadIdx.x;
    const float* Ab = g_A + ((long)b * NH + h) * HD * HD;
    for (int r = tid; r < 64 * 16; r += 256) {
        int i = r >> 4, q = (r & 15) * 4;
        float4 v = *(const float4*)(Ab + i * 64 + q);
        Ash[q + 0][i] = v.x; Ash[q + 1][i] = v.y;
        Ash[q + 2][i] = v.z; Ash[q + 3][i] = v.w;
    }
    int tx = tid & 15, ty = tid >> 4;
    int cc0 = seg * 256;
    for (int cc = cc0; cc < cc0 + 256; cc += 64) {
        __syncthreads();
        for (int r = tid; r < 64 * 16; r += 256) {
            int j = r >> 4, q = (r & 15) * 4;
            *(float4*)&Bv[j][q] = *(const float4*)(wv + (long)(h * HD + j) * CH + cc + q);
        }
        __syncthreads();
        float acc[4][4];
        #pragma unroll
        for (int i = 0; i < 4; i++)
            #pragma unroll
            for (int j = 0; j < 4; j++) acc[i][j] = 0.f;
        #pragma unroll 8
        for (int j = 0; j < 64; j++) {
            float ra[4], rb[4];
            *(float4*)&ra[0] = *(const float4*)&Ash[j][ty * 4];
            *(float4*)&rb[0] = *(const float4*)&Bv[j][tx * 4];
            #pragma unroll
            for (int i = 0; i < 4; i++)
                #pragma unroll
                for (int u = 0; u < 4; u++)
                    acc[i][u] += ra[i] * rb[u];
        }
        #pragma unroll
        for (int u = 0; u < 4; u++) {
            int c = cc + tx * 4 + u;
            long base = ((long)b * CH + c) * CH + h * HD + ty * 4;
            float v0 = acc[0][u], v1 = acc[1][u], v2 = acc[2][u], v3 = acc[3][u];
            fp16 h0 = __float2half(v0), h1 = __float2half(v1);
            fp16 h2 = __float2half(v2), h3 = __float2half(v3);
            __half2 a0, a1, b0, b1;
            a0.x = h0; a0.y = h1; a1.x = h2; a1.y = h3;
            b0.x = __float2half(v0 - __half2float(h0));
            b0.y = __float2half(v1 - __half2float(h1));
            b1.x = __float2half(v2 - __half2float(h2));
            b1.y = __float2half(v3 - __half2float(h3));
            *(__half2*)(g_Pth + base)     = a0;
            *(__half2*)(g_Pth + base + 2) = a1;
            *(__half2*)(g_Ptl + base)     = b0;
            *(__half2*)(g_Ptl + base + 2) = b1;
        }
    }
}

// ---------------- launch ----------------
extern "C" void kernel_launch(void* const* d_in, const int* in_sizes, int n_in,
                              void* d_out, int out_size) {
    const float* x  = (const float*)d_in[0];
    const float* wq = (const float*)d_in[1];
    const float* bq = (const float*)d_in[2];
    const float* wk = (const float*)d_in[3];
    const float* bk = (const float*)d_in[4];
    const float* wv = (const float*)d_in[5];
    const float* bv = (const float*)d_in[6];
    const float* wo = (const float*)d_in[7];
    const float* bo = (const float*)d_in[8];
    float* y = (float*)d_out;

    float *pT, *pGP, *pc;
    fp16 *pXh, *pXl, *pXt, *pGh, *pGl, *pPth, *pPtl, *pMh;
    fp16 *pWqh, *pWql, *pWoh;
    cudaGetSymbolAddress((void**)&pT,  g_T);
    cudaGetSymbolAddress((void**)&pGP, g_GP);
    cudaGetSymbolAddress((void**)&pc,  g_c);
    cudaGetSymbolAddress((void**)&pXh, g_Xh);
    cudaGetSymbolAddress((void**)&pXl, g_Xl);
    cudaGetSymbolAddress((void**)&pXt, g_Xt);
    cudaGetSymbolAddress((void**)&pGh, g_Gh);
    cudaGetSymbolAddress((void**)&pGl, g_Gl);
    cudaGetSymbolAddress((void**)&pPth, g_Pth);
    cudaGetSymbolAddress((void**)&pPtl, g_Ptl);
    cudaGetSymbolAddress((void**)&pMh, g_Mh);
    cudaGetSymbolAddress((void**)&pWqh, g_Wqh);
    cudaGetSymbolAddress((void**)&pWql, g_Wql);
    cudaGetSymbolAddress((void**)&pWoh, g_Woh);

    cudaFuncSetAttribute((const void*)mma_gemm<true>,
                         cudaFuncAttributeMaxDynamicSharedMemorySize, MMA_SMEM);
    cudaFuncSetAttribute((const void*)mma_gemm<false>,
                         cudaFuncAttributeMaxDynamicSharedMemorySize, MMA_SMEM);
    cudaFuncSetAttribute((const void*)mma_gemm2,
                         cudaFuncAttributeMaxDynamicSharedMemorySize, T2_SMEM);
    cudaFuncSetAttribute((const void*)mma_gemm_h1,
                         cudaFuncAttributeMaxDynamicSharedMemorySize, H1_SMEM);

    // 1-3. prep
    zs_kernel<<<48, 256>>>();
    splitx_kernel<<<dim3(NPIX / 32, CH / 32, BATCH), dim3(32, 8)>>>(x);
    splitw_kernel<<<(CH * CH) / 1024, 256>>>(wq, pWqh, pWql);

    // 4. Gram partials (launch #4 -> ncu target): 21 tiles x split-K 4.  K = 4096
    mma_gemm<true><<<dim3(21, 4, BATCH), 256, MMA_SMEM>>>(
        pXh, pXl, pXh, pXl, pGP,
        NPIX, NPIX / 4, CH, (long)CH * NPIX, (long)CH * NPIX, (long)CH * CH);

    // 5-7. cvt wo + reduce + qs/ks
    cvt_kernel<<<(CH * CH) / 1024, 256>>>(wo, pWoh);
    gram_reduce<<<dim3(21, BATCH), 256>>>();
    qsks_kernel<<<CH, 256>>>(wq, wk);

    // 8. T[b] = Wq * G[b]  (fp16 3-term).  K = 768
    mma_gemm<false><<<dim3(6, 6, BATCH), 256, MMA_SMEM>>>(
        pWqh, pWql, pGh, pGl, pT,
        CH, CH, CH, 0L, (long)CH * CH, (long)CH * CH);

    // 9. attention
    attn_kernel<<<dim3(NH, BATCH), 256>>>(wk, bq, bk, bv);

    // 10. Pt fp16 h/l (3-way cc split)
    pk_kernel<<<dim3(NH * 3, BATCH), 256>>>(wv);

    // 11. c[b] = Wo * abv + bo
    cvec_kernel<<<CH, 256>>>(wo, bo);

    // 12. M[b] = Wo * P[b]  (fp16 2-term, fp16 out).  K = 768
    mma_gemm2<<<dim3(6, 6, BATCH), 256, T2_SMEM>>>(
        pWoh, pPth, pPtl, pMh,
        CH, CH, (long)CH * CH, (long)CH * CH);

    // 13. y[b] = M[b] * X[b] + c[b]  (fp16 1-term).  K = 768
    mma_gemm_h1<<<dim3(NPIX / 128, 6, BATCH), 256, H1_SMEM>>>(
        pMh, pXt, y, pc,
        CH, NPIX, (long)CH * CH, (long)NPIX * CH, (long)CH * NPIX);
}